// round 5
// baseline (speedup 1.0000x reference)
#include <cuda_runtime.h>
#include <cstddef>

#define DIMM    768
#define MTOK    4096      // B*N
#define NSEQ    1024
#define NHEADS  12
#define DHEAD   64
#define FFI     2048
#define BHTOT   48        // B*HEADS

// ---------------- scratch (static device globals; no allocation) -------------
__device__ float g_h [MTOK * DIMM];          // LN output
__device__ float g_q [MTOK * DIMM];          // q = h @ wq
__device__ float g_kv[MTOK * 2 * DIMM];      // kv = x @ wkv
__device__ float g_qt[BHTOT * NSEQ * DHEAD]; // Q in (b,h,n,d)
__device__ float g_kt[BHTOT * NSEQ * DHEAD]; // K in (b,h,n,d)
__device__ float g_vt[BHTOT * NSEQ * DHEAD]; // V in (b,h,n,d)
__device__ float g_o [MTOK * DIMM];          // attention output (b,n,inner)
__device__ float g_u [MTOK * 2 * FFI];       // wff1 output
__device__ float g_g [MTOK * FFI];           // gated

// ------------------------------- LayerNorm -----------------------------------
// one block per row (768 = 3*256)
__global__ void __launch_bounds__(256) ln_kernel(
    const float* __restrict__ x, const float* __restrict__ gamma,
    const float* __restrict__ beta, float* __restrict__ out)
{
    int row = blockIdx.x;
    int tid = threadIdx.x;
    const float* xr = x + (size_t)row * DIMM;
    float v0 = xr[tid], v1 = xr[tid + 256], v2 = xr[tid + 512];
    float s  = v0 + v1 + v2;
    float sq = v0 * v0 + v1 * v1 + v2 * v2;
#pragma unroll
    for (int o = 16; o > 0; o >>= 1) {
        s  += __shfl_xor_sync(0xffffffffu, s, o);
        sq += __shfl_xor_sync(0xffffffffu, sq, o);
    }
    __shared__ float red[16];
    int w = tid >> 5;
    if ((tid & 31) == 0) { red[w] = s; red[w + 8] = sq; }
    __syncthreads();
    float ts = 0.f, tq = 0.f;
#pragma unroll
    for (int i = 0; i < 8; i++) { ts += red[i]; tq += red[i + 8]; }
    float mu  = ts * (1.0f / 768.0f);
    float var = tq * (1.0f / 768.0f) - mu * mu;
    float inv = rsqrtf(var + 1e-5f);
    float* orow = out + (size_t)row * DIMM;
    float b0 = beta ? beta[tid]       : 0.f;
    float b1 = beta ? beta[tid + 256] : 0.f;
    float b2 = beta ? beta[tid + 512] : 0.f;
    orow[tid]       = (v0 - mu) * inv * gamma[tid]       + b0;
    orow[tid + 256] = (v1 - mu) * inv * gamma[tid + 256] + b1;
    orow[tid + 512] = (v2 - mu) * inv * gamma[tid + 512] + b2;
}

// ------------------------------- SGEMM ---------------------------------------
// C[M,N] = A[M,K] @ B[K,N] (+ res). 128x128 block tile, BK=16, 256 threads,
// 8x8 per thread. Requires M%128==0, N%128==0, K%16==0 (all shapes satisfy).
#define BM 128
#define BN 128
#define BKK 16
__global__ void __launch_bounds__(256) sgemm_kernel(
    const float* __restrict__ A, const float* __restrict__ B,
    const float* __restrict__ res, float* __restrict__ C,
    int M, int N, int K)
{
    __shared__ __align__(16) float As[BKK][BM];
    __shared__ __align__(16) float Bs[BKK][BN];
    int tid = threadIdx.x;
    int bm = blockIdx.y * BM;
    int bn = blockIdx.x * BN;
    int tx = tid & 15;
    int ty = tid >> 4;

    float acc[8][8];
#pragma unroll
    for (int i = 0; i < 8; i++)
#pragma unroll
        for (int j = 0; j < 8; j++) acc[i][j] = 0.f;

    const float* Ab = A + (size_t)bm * K;
    const float* Bb = B + bn;

    for (int k0 = 0; k0 < K; k0 += BKK) {
#pragma unroll
        for (int i = 0; i < 2; i++) {
            int id = tid + i * 256;        // 512 float4 loads cover 128x16
            int ar = id >> 2;              // 0..127
            int ac = (id & 3) << 2;        // 0,4,8,12
            float4 v = *reinterpret_cast<const float4*>(Ab + (size_t)ar * K + k0 + ac);
            As[ac + 0][ar] = v.x; As[ac + 1][ar] = v.y;
            As[ac + 2][ar] = v.z; As[ac + 3][ar] = v.w;
        }
#pragma unroll
        for (int i = 0; i < 2; i++) {
            int id = tid + i * 256;
            int br = id >> 5;              // 0..15
            int bc = (id & 31) << 2;       // 0..124
            *reinterpret_cast<float4*>(&Bs[br][bc]) =
                *reinterpret_cast<const float4*>(Bb + (size_t)(k0 + br) * N + bc);
        }
        __syncthreads();
#pragma unroll
        for (int k = 0; k < BKK; k++) {
            float a[8], b[8];
            *reinterpret_cast<float4*>(a)     = *reinterpret_cast<float4*>(&As[k][ty * 8]);
            *reinterpret_cast<float4*>(a + 4) = *reinterpret_cast<float4*>(&As[k][ty * 8 + 4]);
            *reinterpret_cast<float4*>(b)     = *reinterpret_cast<float4*>(&Bs[k][tx * 8]);
            *reinterpret_cast<float4*>(b + 4) = *reinterpret_cast<float4*>(&Bs[k][tx * 8 + 4]);
#pragma unroll
            for (int i = 0; i < 8; i++)
#pragma unroll
                for (int j = 0; j < 8; j++)
                    acc[i][j] = fmaf(a[i], b[j], acc[i][j]);
        }
        __syncthreads();
    }
#pragma unroll
    for (int i = 0; i < 8; i++) {
        size_t row = (size_t)(bm + ty * 8 + i);
#pragma unroll
        for (int j = 0; j < 8; j += 4) {
            size_t idx = row * N + bn + tx * 8 + j;
            float4 o;
            o.x = acc[i][j]; o.y = acc[i][j + 1]; o.z = acc[i][j + 2]; o.w = acc[i][j + 3];
            if (res) {
                float4 r = *reinterpret_cast<const float4*>(res + idx);
                o.x += r.x; o.y += r.y; o.z += r.z; o.w += r.w;
            }
            *reinterpret_cast<float4*>(C + idx) = o;
        }
    }
}

// --------------------- RoPE + l2norm + scale + transpose ---------------------
// block = one (token-row, head); 64 threads = dh lanes.
// src row layout: [..., h*64+d] with row stride srcStride.
// dst: (b, h, n, d)
__global__ void __launch_bounds__(64) rope_norm_kernel(
    const float* __restrict__ src, int srcStride,
    const float* __restrict__ scale, float* __restrict__ dst)
{
    int row = blockIdx.x;            // b*1024 + n
    int h   = blockIdx.y;
    int d   = threadIdx.x;
    int n   = row & 1023;
    int b   = row >> 10;
    float v = src[(size_t)row * srcStride + h * DHEAD + d];

    // 2D rope: pair j = d/2; freq index t = j/2; j even -> x (n%32), odd -> y (n/32)
    int j = d >> 1;
    int t = j >> 1;
    float p = (j & 1) ? (float)(n >> 5) : (float)(n & 31);
    float freq = exp2f(-0.830482024f * (float)t);   // 10000^(-t/16)
    float ang = p * freq;
    float c = cosf(ang), s = sinf(ang);
    float other = __shfl_xor_sync(0xffffffffu, v, 1);
    float out = (d & 1) ? (other * s + v * c) : (v * c - other * s);

    // l2 norm over the 64-wide head dim (2 warps)
    float ss = out * out;
#pragma unroll
    for (int o = 16; o > 0; o >>= 1) ss += __shfl_xor_sync(0xffffffffu, ss, o);
    __shared__ float wsum[2];
    if ((d & 31) == 0) wsum[d >> 5] = ss;
    __syncthreads();
    float tot = wsum[0] + wsum[1];
    float inv = 1.0f / fmaxf(sqrtf(tot), 1e-12f);
    out = out * inv * scale[d];
    dst[(((size_t)(b * NHEADS + h)) * NSEQ + n) * DHEAD + d] = out;
}

// ---------------------------- V transpose ------------------------------------
__global__ void __launch_bounds__(256) vtrans_kernel(
    const float* __restrict__ kv, float* __restrict__ V)
{
    int idx = blockIdx.x * 256 + threadIdx.x;  // 0 .. 4096*768-1
    int row = idx / DIMM;
    int c   = idx - row * DIMM;
    int n = row & 1023, b = row >> 10;
    int h = c >> 6, d = c & 63;
    V[(((size_t)(b * NHEADS + h)) * NSEQ + n) * DHEAD + d] =
        kv[(size_t)row * (2 * DIMM) + DIMM + c];
}

// ------------------------- Flash attention ------------------------------------
// one block = (bh, 64 queries); 128 threads (ty=tid>>3 rows x4, tx=tid&7 cols x8)
__global__ void __launch_bounds__(128) attn_kernel(
    const float* __restrict__ Q, const float* __restrict__ K,
    const float* __restrict__ V, float* __restrict__ O)
{
    __shared__ __align__(16) float Qt[64][64];   // [d][q]  (pre-scaled by 8)
    __shared__ __align__(16) float Kt[64][64];   // [d][k]; reused as P[k][q]
    __shared__ __align__(16) float Vs[64][64];   // [k][d]

    int tid = threadIdx.x;
    int bh  = blockIdx.y;
    int q0  = blockIdx.x * 64;
    const float* Qg = Q + ((size_t)bh * NSEQ + q0) * DHEAD;
    const float* Kg = K + (size_t)bh * NSEQ * DHEAD;
    const float* Vg = V + (size_t)bh * NSEQ * DHEAD;
    int ty = tid >> 3;
    int tx = tid & 7;

    // load Q tile transposed & scaled
#pragma unroll
    for (int i = 0; i < 8; i++) {
        int id = tid + i * 128;
        int r  = id & 63;
        int c4 = (id >> 6) << 2;
        float4 v = *reinterpret_cast<const float4*>(Qg + r * 64 + c4);
        Qt[c4 + 0][r] = v.x * 8.0f;
        Qt[c4 + 1][r] = v.y * 8.0f;
        Qt[c4 + 2][r] = v.z * 8.0f;
        Qt[c4 + 3][r] = v.w * 8.0f;
    }
    float m[4], l[4], o[4][8];
#pragma unroll
    for (int i = 0; i < 4; i++) {
        m[i] = -1e30f; l[i] = 0.f;
#pragma unroll
        for (int j = 0; j < 8; j++) o[i][j] = 0.f;
    }
    __syncthreads();

    for (int kt = 0; kt < 16; kt++) {
        const float* Kgt = Kg + kt * 64 * 64;
        const float* Vgt = Vg + kt * 64 * 64;
#pragma unroll
        for (int i = 0; i < 8; i++) {
            int id = tid + i * 128;
            int r  = id & 63;
            int c4 = (id >> 6) << 2;
            float4 kk = *reinterpret_cast<const float4*>(Kgt + r * 64 + c4);
            Kt[c4 + 0][r] = kk.x; Kt[c4 + 1][r] = kk.y;
            Kt[c4 + 2][r] = kk.z; Kt[c4 + 3][r] = kk.w;
            int r2 = id >> 4;
            int d4 = (id & 15) << 2;
            *reinterpret_cast<float4*>(&Vs[r2][d4]) =
                *reinterpret_cast<const float4*>(Vgt + r2 * 64 + d4);
        }
        __syncthreads();

        // S = (8*Q) K^T
        float s[4][8];
#pragma unroll
        for (int i = 0; i < 4; i++)
#pragma unroll
            for (int j = 0; j < 8; j++) s[i][j] = 0.f;
#pragma unroll 4
        for (int d = 0; d < 64; d++) {
            float qv[4];
#pragma unroll
            for (int i = 0; i < 4; i++) qv[i] = Qt[d][ty * 4 + i];
            float kv[8];
            *reinterpret_cast<float4*>(kv)     = *reinterpret_cast<float4*>(&Kt[d][tx * 8]);
            *reinterpret_cast<float4*>(kv + 4) = *reinterpret_cast<float4*>(&Kt[d][tx * 8 + 4]);
#pragma unroll
            for (int i = 0; i < 4; i++)
#pragma unroll
                for (int j = 0; j < 8; j++)
                    s[i][j] = fmaf(qv[i], kv[j], s[i][j]);
        }

        // online softmax (registers; rows shared by tx-group of 8 lanes)
#pragma unroll
        for (int i = 0; i < 4; i++) {
            float mx = s[i][0];
#pragma unroll
            for (int j = 1; j < 8; j++) mx = fmaxf(mx, s[i][j]);
            mx = fmaxf(mx, __shfl_xor_sync(0xffffffffu, mx, 1));
            mx = fmaxf(mx, __shfl_xor_sync(0xffffffffu, mx, 2));
            mx = fmaxf(mx, __shfl_xor_sync(0xffffffffu, mx, 4));
            float mnew = fmaxf(m[i], mx);
            float corr = __expf(m[i] - mnew);
            float rs = 0.f;
#pragma unroll
            for (int j = 0; j < 8; j++) {
                float pv = __expf(s[i][j] - mnew);
                s[i][j] = pv; rs += pv;
            }
            rs += __shfl_xor_sync(0xffffffffu, rs, 1);
            rs += __shfl_xor_sync(0xffffffffu, rs, 2);
            rs += __shfl_xor_sync(0xffffffffu, rs, 4);
            l[i] = l[i] * corr + rs;
            m[i] = mnew;
#pragma unroll
            for (int j = 0; j < 8; j++) o[i][j] *= corr;
        }
        __syncthreads();                 // done reading Kt as K
        // write P transposed into Kt: P[k][q]
#pragma unroll
        for (int i = 0; i < 4; i++)
#pragma unroll
            for (int j = 0; j < 8; j++)
                Kt[tx * 8 + j][ty * 4 + i] = s[i][j];
        __syncthreads();

        // O += P V
#pragma unroll 4
        for (int kc = 0; kc < 64; kc++) {
            float p[4];
#pragma unroll
            for (int i = 0; i < 4; i++) p[i] = Kt[kc][ty * 4 + i];
            float vv[8];
            *reinterpret_cast<float4*>(vv)     = *reinterpret_cast<float4*>(&Vs[kc][tx * 8]);
            *reinterpret_cast<float4*>(vv + 4) = *reinterpret_cast<float4*>(&Vs[kc][tx * 8 + 4]);
#pragma unroll
            for (int i = 0; i < 4; i++)
#pragma unroll
                for (int j = 0; j < 8; j++)
                    o[i][j] = fmaf(p[i], vv[j], o[i][j]);
        }
        __syncthreads();
    }

    // epilogue: normalize and write into (b, n, h*64+d) row layout
    int b = bh / NHEADS, hh = bh % NHEADS;
#pragma unroll
    for (int i = 0; i < 4; i++) {
        float invl = 1.0f / l[i];
        int n = q0 + ty * 4 + i;
        float* orow = O + ((size_t)(b * NSEQ + n)) * DIMM + hh * DHEAD + tx * 8;
#pragma unroll
        for (int j = 0; j < 8; j++) orow[j] = o[i][j] * invl;
    }
}

// ------------------------------ GELU gate -------------------------------------
__global__ void __launch_bounds__(256) gate_kernel(
    const float* __restrict__ u, float* __restrict__ g)
{
    int idx = blockIdx.x * 256 + threadIdx.x;  // 0 .. 4096*2048-1
    int row = idx / FFI;
    int c   = idx - row * FFI;
    float a  = u[(size_t)row * (2 * FFI) + c];
    float xg = u[(size_t)row * (2 * FFI) + FFI + c];
    float gl = 0.5f * xg * (1.0f + erff(xg * 0.7071067811865475f));
    g[idx] = a * gl;
}

// ------------------------------ launch ----------------------------------------
extern "C" void kernel_launch(void* const* d_in, const int* in_sizes, int n_in,
                              void* d_out, int out_size)
{
    (void)in_sizes; (void)n_in; (void)out_size;
    const float* x          = (const float*)d_in[0];
    const float* attn_gamma = (const float*)d_in[1];
    const float* wq         = (const float*)d_in[2];
    const float* wkv        = (const float*)d_in[3];
    const float* q_scale    = (const float*)d_in[4];
    const float* k_scale    = (const float*)d_in[5];
    const float* wo         = (const float*)d_in[6];
    const float* ff_gamma   = (const float*)d_in[7];
    const float* ff_beta    = (const float*)d_in[8];
    const float* wff1       = (const float*)d_in[9];
    const float* wff2       = (const float*)d_in[10];
    float* xo = (float*)d_out;

    float *h, *q, *kv, *qt, *kt, *vt, *o, *u, *g;
    cudaGetSymbolAddress((void**)&h,  g_h);
    cudaGetSymbolAddress((void**)&q,  g_q);
    cudaGetSymbolAddress((void**)&kv, g_kv);
    cudaGetSymbolAddress((void**)&qt, g_qt);
    cudaGetSymbolAddress((void**)&kt, g_kt);
    cudaGetSymbolAddress((void**)&vt, g_vt);
    cudaGetSymbolAddress((void**)&o,  g_o);
    cudaGetSymbolAddress((void**)&u,  g_u);
    cudaGetSymbolAddress((void**)&g,  g_g);

    cudaMemcpyAsync(xo, x, (size_t)MTOK * DIMM * sizeof(float),
                    cudaMemcpyDeviceToDevice);

    for (int i = 0; i < 4; i++) {
        // attention block
        ln_kernel<<<MTOK, 256>>>(xo, attn_gamma + (size_t)i * DIMM, nullptr, h);
        sgemm_kernel<<<dim3(DIMM / BN, MTOK / BM), 256>>>(
            h, wq + (size_t)i * DIMM * DIMM, nullptr, q, MTOK, DIMM, DIMM);
        sgemm_kernel<<<dim3(2 * DIMM / BN, MTOK / BM), 256>>>(
            xo, wkv + (size_t)i * DIMM * 2 * DIMM, nullptr, kv, MTOK, 2 * DIMM, DIMM);
        rope_norm_kernel<<<dim3(MTOK, NHEADS), 64>>>(q, DIMM, q_scale + (size_t)i * DHEAD, qt);
        rope_norm_kernel<<<dim3(MTOK, NHEADS), 64>>>(kv, 2 * DIMM, k_scale + (size_t)i * DHEAD, kt);
        vtrans_kernel<<<(MTOK * DIMM) / 256, 256>>>(kv, vt);
        attn_kernel<<<dim3(NSEQ / 64, BHTOT), 128>>>(qt, kt, vt, o);
        sgemm_kernel<<<dim3(DIMM / BN, MTOK / BM), 256>>>(
            o, wo + (size_t)i * DIMM * DIMM, xo, xo, MTOK, DIMM, DIMM);

        // feed-forward block
        ln_kernel<<<MTOK, 256>>>(xo, ff_gamma + (size_t)i * DIMM,
                                 ff_beta + (size_t)i * DIMM, h);
        sgemm_kernel<<<dim3(2 * FFI / BN, MTOK / BM), 256>>>(
            h, wff1 + (size_t)i * DIMM * 2 * FFI, nullptr, u, MTOK, 2 * FFI, DIMM);
        gate_kernel<<<(MTOK * FFI) / 256, 256>>>(u, g);
        sgemm_kernel<<<dim3(DIMM / BN, MTOK / BM), 256>>>(
            g, wff2 + (size_t)i * FFI * DIMM, xo, xo, MTOK, DIMM, FFI);
    }
}

// round 7
// speedup vs baseline: 1.6020x; 1.6020x over previous
#include <cuda_runtime.h>
#include <cuda_bf16.h>
#include <cstdint>
#include <cstddef>

#define DIMM    768
#define MTOK    4096
#define NSEQ    1024
#define NHEADS  12
#define DHEAD   64
#define FFI     2048
#define BHTOT   48

// ---------------- scratch (static device globals; no allocation) -------------
__device__ float g_q [MTOK * DIMM];
__device__ float g_kv[MTOK * 2 * DIMM];
__device__ float g_u [MTOK * 2 * FFI];
__device__ float g_o [MTOK * DIMM];
__device__ float g_qt[BHTOT * NSEQ * DHEAD];
__device__ float g_kt[BHTOT * NSEQ * DHEAD];
__device__ float g_vt[BHTOT * NSEQ * DHEAD];
__device__ __align__(16) __nv_bfloat16 g_ah [MTOK * FFI];
__device__ __align__(16) __nv_bfloat16 g_al [MTOK * FFI];
__device__ __align__(16) __nv_bfloat16 g_wth[4096 * 768];
__device__ __align__(16) __nv_bfloat16 g_wtl[4096 * 768];

// =========================== PTX helpers (sm_80-safe) =========================
__device__ __forceinline__ uint32_t smem_to_u32(const void* p) {
    uint32_t a;
    asm("{ .reg .u64 t; cvta.to.shared.u64 t, %1; cvt.u32.u64 %0, t; }"
        : "=r"(a) : "l"(p));
    return a;
}
#define CPASYNC(d, s) \
    asm volatile("cp.async.cg.shared.global [%0], [%1], 16;" :: "r"(d), "l"(s))
#define CPCOMMIT() asm volatile("cp.async.commit_group;" ::: "memory")
#define CPWAIT1()  asm volatile("cp.async.wait_group 1;" ::: "memory")
#define CPWAIT0()  asm volatile("cp.async.wait_group 0;" ::: "memory")
#define LDSM4(r, addr) \
    asm volatile("ldmatrix.sync.aligned.m8n8.x4.shared.b16 {%0,%1,%2,%3}, [%4];" \
        : "=r"((r)[0]), "=r"((r)[1]), "=r"((r)[2]), "=r"((r)[3]) : "r"(addr))
#define MMA_BF16(d, a, b0, b1) \
    asm volatile("mma.sync.aligned.m16n8k16.row.col.f32.bf16.bf16.f32 " \
        "{%0,%1,%2,%3}, {%4,%5,%6,%7}, {%8,%9}, {%0,%1,%2,%3};" \
        : "+f"((d)[0]), "+f"((d)[1]), "+f"((d)[2]), "+f"((d)[3]) \
        : "r"((a)[0]), "r"((a)[1]), "r"((a)[2]), "r"((a)[3]), "r"(b0), "r"(b1))

__device__ __forceinline__ void bsplit(float v, __nv_bfloat16& h, __nv_bfloat16& l) {
    h = __float2bfloat16(v);
    l = __float2bfloat16(v - __bfloat162float(h));
}

// ------------------------- LayerNorm -> split bf16 ---------------------------
__global__ void __launch_bounds__(256) ln_kernel(
    const float* __restrict__ x, const float* __restrict__ gamma,
    const float* __restrict__ beta,
    __nv_bfloat16* __restrict__ oh, __nv_bfloat16* __restrict__ ol)
{
    int row = blockIdx.x, tid = threadIdx.x;
    const float* xr = x + (size_t)row * DIMM;
    float v0 = xr[tid], v1 = xr[tid + 256], v2 = xr[tid + 512];
    float s = v0 + v1 + v2, sq = v0 * v0 + v1 * v1 + v2 * v2;
#pragma unroll
    for (int o = 16; o > 0; o >>= 1) {
        s  += __shfl_xor_sync(0xffffffffu, s, o);
        sq += __shfl_xor_sync(0xffffffffu, sq, o);
    }
    __shared__ float red[16];
    if ((tid & 31) == 0) { red[tid >> 5] = s; red[(tid >> 5) + 8] = sq; }
    __syncthreads();
    float ts = 0.f, tq = 0.f;
#pragma unroll
    for (int i = 0; i < 8; i++) { ts += red[i]; tq += red[i + 8]; }
    float mu  = ts * (1.0f / 768.0f);
    float var = tq * (1.0f / 768.0f) - mu * mu;
    float inv = rsqrtf(var + 1e-5f);
    size_t base = (size_t)row * DIMM;
#pragma unroll
    for (int i = 0; i < 3; i++) {
        int c = tid + i * 256;
        float vv = (i == 0 ? v0 : (i == 1 ? v1 : v2));
        float b = beta ? beta[c] : 0.f;
        float y = (vv - mu) * inv * gamma[c] + b;
        __nv_bfloat16 h, l; bsplit(y, h, l);
        oh[base + c] = h; ol[base + c] = l;
    }
}

// ---------------- weight transpose + split: W[K,N] -> Wt[N,K] hi/lo ----------
__global__ void __launch_bounds__(256) wtrans_kernel(
    const float* __restrict__ W, __nv_bfloat16* __restrict__ th,
    __nv_bfloat16* __restrict__ tl, int Kd, int Nd)
{
    __shared__ float t[32][33];
    int tx = threadIdx.x & 31, ty = threadIdx.x >> 5;
    int n0 = blockIdx.x * 32, k0 = blockIdx.y * 32;
#pragma unroll
    for (int i = 0; i < 4; i++)
        t[ty + i * 8][tx] = W[(size_t)(k0 + ty + i * 8) * Nd + n0 + tx];
    __syncthreads();
#pragma unroll
    for (int i = 0; i < 4; i++) {
        int n = n0 + ty + i * 8;
        float v = t[tx][ty + i * 8];
        __nv_bfloat16 h, l; bsplit(v, h, l);
        th[(size_t)n * Kd + k0 + tx] = h;
        tl[(size_t)n * Kd + k0 + tx] = l;
    }
}

// --------------------------- fp32 -> split bf16 ------------------------------
__global__ void __launch_bounds__(256) split_kernel(
    const float* __restrict__ x, __nv_bfloat16* __restrict__ oh,
    __nv_bfloat16* __restrict__ ol)
{
    int i = blockIdx.x * 256 + threadIdx.x;
    __nv_bfloat16 h, l; bsplit(x[i], h, l);
    oh[i] = h; ol[i] = l;
}

// -------------------------- GELU gate -> split bf16 --------------------------
__global__ void __launch_bounds__(256) gate_kernel(
    const float* __restrict__ u, __nv_bfloat16* __restrict__ oh,
    __nv_bfloat16* __restrict__ ol)
{
    int idx = blockIdx.x * 256 + threadIdx.x;
    int row = idx >> 11, c = idx & 2047;
    float a  = u[(size_t)row * (2 * FFI) + c];
    float xg = u[(size_t)row * (2 * FFI) + FFI + c];
    float ge = 0.5f * xg * (1.0f + erff(xg * 0.7071067811865475f));
    __nv_bfloat16 h, l; bsplit(a * ge, h, l);
    oh[idx] = h; ol[idx] = l;
}

// --------------------- RoPE + l2norm + scale + transpose ---------------------
__global__ void __launch_bounds__(64) rope_norm_kernel(
    const float* __restrict__ src, int srcStride,
    const float* __restrict__ scale, float* __restrict__ dst)
{
    int row = blockIdx.x, h = blockIdx.y, d = threadIdx.x;
    int n = row & 1023, b = row >> 10;
    float v = src[(size_t)row * srcStride + h * DHEAD + d];
    int j = d >> 1, t = j >> 1;
    float p = (j & 1) ? (float)(n >> 5) : (float)(n & 31);
    float ang = p * exp2f(-0.830482024f * (float)t);
    float c = cosf(ang), s = sinf(ang);
    float other = __shfl_xor_sync(0xffffffffu, v, 1);
    float out = (d & 1) ? (other * s + v * c) : (v * c - other * s);
    float ss = out * out;
#pragma unroll
    for (int o = 16; o > 0; o >>= 1) ss += __shfl_xor_sync(0xffffffffu, ss, o);
    __shared__ float ws[2];
    if ((d & 31) == 0) ws[d >> 5] = ss;
    __syncthreads();
    float inv = 1.0f / fmaxf(sqrtf(ws[0] + ws[1]), 1e-12f);
    dst[(((size_t)(b * NHEADS + h)) * NSEQ + n) * DHEAD + d] = out * inv * scale[d];
}

__global__ void __launch_bounds__(256) vtrans_kernel(
    const float* __restrict__ kv, float* __restrict__ V)
{
    int idx = blockIdx.x * 256 + threadIdx.x;
    int row = idx / DIMM, c = idx - row * DIMM;
    int n = row & 1023, b = row >> 10, h = c >> 6, d = c & 63;
    V[(((size_t)(b * NHEADS + h)) * NSEQ + n) * DHEAD + d] =
        kv[(size_t)row * (2 * DIMM) + DIMM + c];
}

// --------------------------- Flash attention (fp32) --------------------------
__global__ void __launch_bounds__(128) attn_kernel(
    const float* __restrict__ Q, const float* __restrict__ K,
    const float* __restrict__ V, float* __restrict__ O)
{
    __shared__ __align__(16) float Qt[64][64];
    __shared__ __align__(16) float Kt[64][64];
    __shared__ __align__(16) float Vs[64][64];
    int tid = threadIdx.x, bh = blockIdx.y, q0 = blockIdx.x * 64;
    const float* Qg = Q + ((size_t)bh * NSEQ + q0) * DHEAD;
    const float* Kg = K + (size_t)bh * NSEQ * DHEAD;
    const float* Vg = V + (size_t)bh * NSEQ * DHEAD;
    int ty = tid >> 3, tx = tid & 7;
#pragma unroll
    for (int i = 0; i < 8; i++) {
        int id = tid + i * 128, r = id & 63, c4 = (id >> 6) << 2;
        float4 v = *reinterpret_cast<const float4*>(Qg + r * 64 + c4);
        Qt[c4 + 0][r] = v.x * 8.0f; Qt[c4 + 1][r] = v.y * 8.0f;
        Qt[c4 + 2][r] = v.z * 8.0f; Qt[c4 + 3][r] = v.w * 8.0f;
    }
    float m[4], l[4], o[4][8];
#pragma unroll
    for (int i = 0; i < 4; i++) {
        m[i] = -1e30f; l[i] = 0.f;
#pragma unroll
        for (int j = 0; j < 8; j++) o[i][j] = 0.f;
    }
    __syncthreads();
    for (int kt = 0; kt < 16; kt++) {
        const float* Kgt = Kg + kt * 4096;
        const float* Vgt = Vg + kt * 4096;
#pragma unroll
        for (int i = 0; i < 8; i++) {
            int id = tid + i * 128, r = id & 63, c4 = (id >> 6) << 2;
            float4 kk = *reinterpret_cast<const float4*>(Kgt + r * 64 + c4);
            Kt[c4 + 0][r] = kk.x; Kt[c4 + 1][r] = kk.y;
            Kt[c4 + 2][r] = kk.z; Kt[c4 + 3][r] = kk.w;
            int r2 = id >> 4, d4 = (id & 15) << 2;
            *reinterpret_cast<float4*>(&Vs[r2][d4]) =
                *reinterpret_cast<const float4*>(Vgt + r2 * 64 + d4);
        }
        __syncthreads();
        float s[4][8];
#pragma unroll
        for (int i = 0; i < 4; i++)
#pragma unroll
            for (int j = 0; j < 8; j++) s[i][j] = 0.f;
#pragma unroll 4
        for (int d = 0; d < 64; d++) {
            float qv[4];
#pragma unroll
            for (int i = 0; i < 4; i++) qv[i] = Qt[d][ty * 4 + i];
            float kv[8];
            *reinterpret_cast<float4*>(kv)     = *reinterpret_cast<float4*>(&Kt[d][tx * 8]);
            *reinterpret_cast<float4*>(kv + 4) = *reinterpret_cast<float4*>(&Kt[d][tx * 8 + 4]);
#pragma unroll
            for (int i = 0; i < 4; i++)
#pragma unroll
                for (int j = 0; j < 8; j++) s[i][j] = fmaf(qv[i], kv[j], s[i][j]);
        }
#pragma unroll
        for (int i = 0; i < 4; i++) {
            float mx = s[i][0];
#pragma unroll
            for (int j = 1; j < 8; j++) mx = fmaxf(mx, s[i][j]);
            mx = fmaxf(mx, __shfl_xor_sync(0xffffffffu, mx, 1));
            mx = fmaxf(mx, __shfl_xor_sync(0xffffffffu, mx, 2));
            mx = fmaxf(mx, __shfl_xor_sync(0xffffffffu, mx, 4));
            float mnew = fmaxf(m[i], mx);
            float corr = __expf(m[i] - mnew);
            float rs = 0.f;
#pragma unroll
            for (int j = 0; j < 8; j++) {
                float pv = __expf(s[i][j] - mnew);
                s[i][j] = pv; rs += pv;
            }
            rs += __shfl_xor_sync(0xffffffffu, rs, 1);
            rs += __shfl_xor_sync(0xffffffffu, rs, 2);
            rs += __shfl_xor_sync(0xffffffffu, rs, 4);
            l[i] = l[i] * corr + rs; m[i] = mnew;
#pragma unroll
            for (int j = 0; j < 8; j++) o[i][j] *= corr;
        }
        __syncthreads();
#pragma unroll
        for (int i = 0; i < 4; i++)
#pragma unroll
            for (int j = 0; j < 8; j++) Kt[tx * 8 + j][ty * 4 + i] = s[i][j];
        __syncthreads();
#pragma unroll 4
        for (int kc = 0; kc < 64; kc++) {
            float p[4];
#pragma unroll
            for (int i = 0; i < 4; i++) p[i] = Kt[kc][ty * 4 + i];
            float vv[8];
            *reinterpret_cast<float4*>(vv)     = *reinterpret_cast<float4*>(&Vs[kc][tx * 8]);
            *reinterpret_cast<float4*>(vv + 4) = *reinterpret_cast<float4*>(&Vs[kc][tx * 8 + 4]);
#pragma unroll
            for (int i = 0; i < 4; i++)
#pragma unroll
                for (int j = 0; j < 8; j++) o[i][j] = fmaf(p[i], vv[j], o[i][j]);
        }
        __syncthreads();
    }
    int b = bh / NHEADS, hh = bh % NHEADS;
#pragma unroll
    for (int i = 0; i < 4; i++) {
        float invl = 1.0f / l[i];
        int n = q0 + ty * 4 + i;
        float* orow = O + ((size_t)(b * NSEQ + n)) * DIMM + hh * DHEAD + tx * 8;
#pragma unroll
        for (int j = 0; j < 8; j++) orow[j] = o[i][j] * invl;
    }
}

// =========== HMMA (mma.sync bf16) GEMM: C = A@B^T (+res), split-3 =============
// A hi/lo [M,K] bf16; B hi/lo [N,K] bf16 (pre-transposed). CTA tile 128x128,
// BK=32, 8 warps (2x4), warp tile 64x32. Smem rows padded to 40 bf16 (80B,
// conflict-free for ldmatrix). Double-buffered cp.async.
#define SROW   40
#define SMAT   (128 * SROW)            // elems per matrix per stage
#define SMATB  (SMAT * 2)              // bytes
#define SSTAGE (4 * SMATB)             // bytes per stage (Ah,Al,Bh,Bl)
#define GSMEM  (2 * SSTAGE)            // 81920 bytes

__global__ void __launch_bounds__(256) gemm_mma(
    const __nv_bfloat16* __restrict__ Ah, const __nv_bfloat16* __restrict__ Al,
    const __nv_bfloat16* __restrict__ Bh, const __nv_bfloat16* __restrict__ Bl,
    const float* __restrict__ res, float* __restrict__ C, int N, int K)
{
    extern __shared__ __align__(16) __nv_bfloat16 sm[];
    const int tid = threadIdx.x, lane = tid & 31, w = tid >> 5;
    const int wr = w & 1, wc = w >> 1;
    const int bm = blockIdx.y * 128, bn = blockIdx.x * 128;
    const int NK = K >> 5;
    const uint32_t sbase = smem_to_u32(sm);

    // per-thread load slots: 2 chunks of 16B per matrix per stage
    const int c0 = tid, c1 = tid + 256;            // chunk ids in [0,512)
    const int r0 = c0 >> 2, q0 = (c0 & 3) * 8;
    const int r1 = c1 >> 2, q1 = (c1 & 3) * 8;
    const uint32_t d0 = (uint32_t)(r0 * SROW + q0) * 2;
    const uint32_t d1 = (uint32_t)(r1 * SROW + q1) * 2;

    const __nv_bfloat16* gAh = Ah + (size_t)bm * K;
    const __nv_bfloat16* gAl = Al + (size_t)bm * K;
    const __nv_bfloat16* gBh = Bh + (size_t)bn * K;
    const __nv_bfloat16* gBl = Bl + (size_t)bn * K;

    float acc[4][4][4];
#pragma unroll
    for (int a = 0; a < 4; a++)
#pragma unroll
        for (int b = 0; b < 4; b++)
#pragma unroll
            for (int c = 0; c < 4; c++) acc[a][b][c] = 0.f;

    // issue loads for stage st (buffer index) from K-chunk kc
    auto issue = [&](int st, int kc) {
        uint32_t sb = sbase + st * SSTAGE;
        int ko = kc * 32;
        CPASYNC(sb + 0 * SMATB + d0, gAh + (size_t)r0 * K + ko + q0);
        CPASYNC(sb + 0 * SMATB + d1, gAh + (size_t)r1 * K + ko + q1);
        CPASYNC(sb + 1 * SMATB + d0, gAl + (size_t)r0 * K + ko + q0);
        CPASYNC(sb + 1 * SMATB + d1, gAl + (size_t)r1 * K + ko + q1);
        CPASYNC(sb + 2 * SMATB + d0, gBh + (size_t)r0 * K + ko + q0);
        CPASYNC(sb + 2 * SMATB + d1, gBh + (size_t)r1 * K + ko + q1);
        CPASYNC(sb + 3 * SMATB + d0, gBl + (size_t)r0 * K + ko + q0);
        CPASYNC(sb + 3 * SMATB + d1, gBl + (size_t)r1 * K + ko + q1);
    };

    issue(0, 0);
    CPCOMMIT();

    const int lj = lane >> 3, lr = lane & 7;   // ldmatrix: matrix idx, row

    for (int kc = 0; kc < NK; kc++) {
        bool more = (kc + 1 < NK);
        if (more) { issue((kc + 1) & 1, kc + 1); CPCOMMIT(); }
        if (more) CPWAIT1(); else CPWAIT0();
        __syncthreads();

        uint32_t sb = sbase + (kc & 1) * SSTAGE;
        uint32_t aH = sb, aL = sb + SMATB, bH = sb + 2 * SMATB, bL = sb + 3 * SMATB;

#pragma unroll
        for (int ks = 0; ks < 2; ks++) {
            uint32_t ahf[4][4], alf[4][4], bhf[2][4], blf[2][4];
#pragma unroll
            for (int mi = 0; mi < 4; mi++) {
                int mrow = wr * 64 + mi * 16 + (lj & 1) * 8 + lr;
                int kcol = ks * 16 + (lj >> 1) * 8;
                uint32_t off = (uint32_t)(mrow * SROW + kcol) * 2;
                LDSM4(ahf[mi], aH + off);
                LDSM4(alf[mi], aL + off);
            }
#pragma unroll
            for (int bt = 0; bt < 2; bt++) {
                int nrow = wc * 32 + bt * 16 + (lj >> 1) * 8 + lr;
                int kcol = ks * 16 + (lj & 1) * 8;
                uint32_t off = (uint32_t)(nrow * SROW + kcol) * 2;
                LDSM4(bhf[bt], bH + off);
                LDSM4(blf[bt], bL + off);
            }
#pragma unroll
            for (int mi = 0; mi < 4; mi++)
#pragma unroll
                for (int bt = 0; bt < 2; bt++)
#pragma unroll
                    for (int hf = 0; hf < 2; hf++) {
                        int nt = bt * 2 + hf;
                        MMA_BF16(acc[mi][nt], ahf[mi], bhf[bt][hf * 2], bhf[bt][hf * 2 + 1]);
                        MMA_BF16(acc[mi][nt], ahf[mi], blf[bt][hf * 2], blf[bt][hf * 2 + 1]);
                        MMA_BF16(acc[mi][nt], alf[mi], bhf[bt][hf * 2], bhf[bt][hf * 2 + 1]);
                    }
        }
        __syncthreads();
    }

    // epilogue: fragment-direct stores with optional residual add
#pragma unroll
    for (int mi = 0; mi < 4; mi++) {
        int row0 = bm + wr * 64 + mi * 16 + (lane >> 2);
#pragma unroll
        for (int nt = 0; nt < 4; nt++) {
            int col = bn + wc * 32 + nt * 8 + (lane & 3) * 2;
            size_t i0 = (size_t)row0 * N + col;
            size_t i1 = (size_t)(row0 + 8) * N + col;
            float2 v0 = make_float2(acc[mi][nt][0], acc[mi][nt][1]);
            float2 v1 = make_float2(acc[mi][nt][2], acc[mi][nt][3]);
            if (res) {
                float2 a0 = *reinterpret_cast<const float2*>(res + i0);
                float2 a1 = *reinterpret_cast<const float2*>(res + i1);
                v0.x += a0.x; v0.y += a0.y; v1.x += a1.x; v1.y += a1.y;
            }
            *reinterpret_cast<float2*>(C + i0) = v0;
            *reinterpret_cast<float2*>(C + i1) = v1;
        }
    }
}

// ------------------------------ launch ----------------------------------------
extern "C" void kernel_launch(void* const* d_in, const int* in_sizes, int n_in,
                              void* d_out, int out_size)
{
    (void)in_sizes; (void)n_in; (void)out_size;
    const float* x          = (const float*)d_in[0];
    const float* attn_gamma = (const float*)d_in[1];
    const float* wq         = (const float*)d_in[2];
    const float* wkv        = (const float*)d_in[3];
    const float* q_scale    = (const float*)d_in[4];
    const float* k_scale    = (const float*)d_in[5];
    const float* wo         = (const float*)d_in[6];
    const float* ff_gamma   = (const float*)d_in[7];
    const float* ff_beta    = (const float*)d_in[8];
    const float* wff1       = (const float*)d_in[9];
    const float* wff2       = (const float*)d_in[10];
    float* xo = (float*)d_out;

    float *q, *kv, *u, *o, *qt, *kt, *vt;
    __nv_bfloat16 *ah, *al, *wth, *wtl;
    cudaGetSymbolAddress((void**)&q,   g_q);
    cudaGetSymbolAddress((void**)&kv,  g_kv);
    cudaGetSymbolAddress((void**)&u,   g_u);
    cudaGetSymbolAddress((void**)&o,   g_o);
    cudaGetSymbolAddress((void**)&qt,  g_qt);
    cudaGetSymbolAddress((void**)&kt,  g_kt);
    cudaGetSymbolAddress((void**)&vt,  g_vt);
    cudaGetSymbolAddress((void**)&ah,  g_ah);
    cudaGetSymbolAddress((void**)&al,  g_al);
    cudaGetSymbolAddress((void**)&wth, g_wth);
    cudaGetSymbolAddress((void**)&wtl, g_wtl);

    cudaFuncSetAttribute(gemm_mma, cudaFuncAttributeMaxDynamicSharedMemorySize, GSMEM);

    cudaMemcpyAsync(xo, x, (size_t)MTOK * DIMM * sizeof(float),
                    cudaMemcpyDeviceToDevice);

    for (int i = 0; i < 4; i++) {
        // --- attention block ---
        ln_kernel<<<MTOK, 256>>>(xo, attn_gamma + (size_t)i * DIMM, nullptr, ah, al);
        wtrans_kernel<<<dim3(24, 24), 256>>>(wq + (size_t)i * 768 * 768, wth, wtl, 768, 768);
        gemm_mma<<<dim3(6, 32), 256, GSMEM>>>(ah, al, wth, wtl, nullptr, q, 768, 768);
        split_kernel<<<(MTOK * DIMM) / 256, 256>>>(xo, ah, al);
        wtrans_kernel<<<dim3(48, 24), 256>>>(wkv + (size_t)i * 768 * 1536, wth, wtl, 768, 1536);
        gemm_mma<<<dim3(12, 32), 256, GSMEM>>>(ah, al, wth, wtl, nullptr, kv, 1536, 768);
        rope_norm_kernel<<<dim3(MTOK, NHEADS), 64>>>(q, DIMM, q_scale + (size_t)i * DHEAD, qt);
        rope_norm_kernel<<<dim3(MTOK, NHEADS), 64>>>(kv, 2 * DIMM, k_scale + (size_t)i * DHEAD, kt);
        vtrans_kernel<<<(MTOK * DIMM) / 256, 256>>>(kv, vt);
        attn_kernel<<<dim3(NSEQ / 64, BHTOT), 128>>>(qt, kt, vt, o);
        split_kernel<<<(MTOK * DIMM) / 256, 256>>>(o, ah, al);
        wtrans_kernel<<<dim3(24, 24), 256>>>(wo + (size_t)i * 768 * 768, wth, wtl, 768, 768);
        gemm_mma<<<dim3(6, 32), 256, GSMEM>>>(ah, al, wth, wtl, xo, xo, 768, 768);
        // --- feed-forward block ---
        ln_kernel<<<MTOK, 256>>>(xo, ff_gamma + (size_t)i * DIMM,
                                 ff_beta + (size_t)i * DIMM, ah, al);
        wtrans_kernel<<<dim3(128, 24), 256>>>(wff1 + (size_t)i * 768 * 4096, wth, wtl, 768, 4096);
        gemm_mma<<<dim3(32, 32), 256, GSMEM>>>(ah, al, wth, wtl, nullptr, u, 4096, 768);
        gate_kernel<<<(MTOK * FFI) / 256, 256>>>(u, ah, al);
        wtrans_kernel<<<dim3(24, 64), 256>>>(wff2 + (size_t)i * 2048 * 768, wth, wtl, 2048, 768);
        gemm_mma<<<dim3(6, 32), 256, GSMEM>>>(ah, al, wth, wtl, xo, xo, 768, 2048);
    }
}

// round 9
// speedup vs baseline: 2.3367x; 1.4585x over previous
#include <cuda_runtime.h>
#include <cuda_bf16.h>
#include <cstdint>
#include <cstddef>

#define DIMM    768
#define MTOK    4096
#define NSEQ    1024
#define NHEADS  12
#define DHEAD   64
#define FFI     2048
#define BHTOT   48

// ---------------- scratch (static device globals; no allocation) -------------
__device__ float g_q [MTOK * DIMM];
__device__ float g_kv[MTOK * 2 * DIMM];
__device__ float g_u [MTOK * 2 * FFI];
__device__ __align__(16) __nv_bfloat16 g_ah [MTOK * FFI];
__device__ __align__(16) __nv_bfloat16 g_al [MTOK * FFI];
__device__ __align__(16) __nv_bfloat16 g_wth[4096 * 768];
__device__ __align__(16) __nv_bfloat16 g_wtl[4096 * 768];
__device__ __align__(16) __nv_bfloat16 g_qh [BHTOT * NSEQ * DHEAD];
__device__ __align__(16) __nv_bfloat16 g_ql [BHTOT * NSEQ * DHEAD];
__device__ __align__(16) __nv_bfloat16 g_kh [BHTOT * NSEQ * DHEAD];
__device__ __align__(16) __nv_bfloat16 g_kl [BHTOT * NSEQ * DHEAD];
__device__ __align__(16) __nv_bfloat16 g_vh [BHTOT * NSEQ * DHEAD]; // [bh][d][n]
__device__ __align__(16) __nv_bfloat16 g_vl [BHTOT * NSEQ * DHEAD];

// =========================== PTX helpers (sm_80-safe) =========================
__device__ __forceinline__ uint32_t smem_to_u32(const void* p) {
    uint32_t a;
    asm("{ .reg .u64 t; cvta.to.shared.u64 t, %1; cvt.u32.u64 %0, t; }"
        : "=r"(a) : "l"(p));
    return a;
}
#define CPASYNC(d, s) \
    asm volatile("cp.async.cg.shared.global [%0], [%1], 16;" :: "r"(d), "l"(s))
#define CPCOMMIT() asm volatile("cp.async.commit_group;" ::: "memory")
#define CPWAIT1()  asm volatile("cp.async.wait_group 1;" ::: "memory")
#define CPWAIT0()  asm volatile("cp.async.wait_group 0;" ::: "memory")
#define LDSM4(r, addr) \
    asm volatile("ldmatrix.sync.aligned.m8n8.x4.shared.b16 {%0,%1,%2,%3}, [%4];" \
        : "=r"((r)[0]), "=r"((r)[1]), "=r"((r)[2]), "=r"((r)[3]) : "r"(addr))
#define MMA_BF16(d, a, b0, b1) \
    asm volatile("mma.sync.aligned.m16n8k16.row.col.f32.bf16.bf16.f32 " \
        "{%0,%1,%2,%3}, {%4,%5,%6,%7}, {%8,%9}, {%0,%1,%2,%3};" \
        : "+f"((d)[0]), "+f"((d)[1]), "+f"((d)[2]), "+f"((d)[3]) \
        : "r"((a)[0]), "r"((a)[1]), "r"((a)[2]), "r"((a)[3]), "r"(b0), "r"(b1))

__device__ __forceinline__ void bsplit(float v, __nv_bfloat16& h, __nv_bfloat16& l) {
    h = __float2bfloat16(v);
    l = __float2bfloat16(v - __bfloat162float(h));
}
__device__ __forceinline__ uint32_t pack2(__nv_bfloat16 a, __nv_bfloat16 b) {
    return (uint32_t)__bfloat16_as_ushort(a) |
           ((uint32_t)__bfloat16_as_ushort(b) << 16);
}
// fast exp for y <= 0 (poly 2^f, magic-number split); rel err ~3e-6
__device__ __forceinline__ float fexp(float y) {
    float t = fmaxf(y * 1.4426950408889634f, -60.0f);
    float z = t + 12582912.0f;
    int   i = __float_as_int(z) - 0x4B400000;
    float f = t - (z - 12582912.0f);
    float p = 1.3333558146e-3f;
    p = fmaf(p, f, 9.6181291076e-3f);
    p = fmaf(p, f, 5.5504108664e-2f);
    p = fmaf(p, f, 2.4022650696e-1f);
    p = fmaf(p, f, 6.9314718056e-1f);
    p = fmaf(p, f, 1.0f);
    return __int_as_float(__float_as_int(p) + (i << 23));
}

// ------------------------- LayerNorm -> split bf16 ---------------------------
__global__ void __launch_bounds__(256) ln_kernel(
    const float* __restrict__ x, const float* __restrict__ gamma,
    const float* __restrict__ beta,
    __nv_bfloat16* __restrict__ oh, __nv_bfloat16* __restrict__ ol)
{
    int row = blockIdx.x, tid = threadIdx.x;
    const float* xr = x + (size_t)row * DIMM;
    float v0 = xr[tid], v1 = xr[tid + 256], v2 = xr[tid + 512];
    float s = v0 + v1 + v2, sq = v0 * v0 + v1 * v1 + v2 * v2;
#pragma unroll
    for (int o = 16; o > 0; o >>= 1) {
        s  += __shfl_xor_sync(0xffffffffu, s, o);
        sq += __shfl_xor_sync(0xffffffffu, sq, o);
    }
    __shared__ float red[16];
    if ((tid & 31) == 0) { red[tid >> 5] = s; red[(tid >> 5) + 8] = sq; }
    __syncthreads();
    float ts = 0.f, tq = 0.f;
#pragma unroll
    for (int i = 0; i < 8; i++) { ts += red[i]; tq += red[i + 8]; }
    float mu  = ts * (1.0f / 768.0f);
    float var = tq * (1.0f / 768.0f) - mu * mu;
    float inv = rsqrtf(var + 1e-5f);
    size_t base = (size_t)row * DIMM;
#pragma unroll
    for (int i = 0; i < 3; i++) {
        int c = tid + i * 256;
        float vv = (i == 0 ? v0 : (i == 1 ? v1 : v2));
        float b = beta ? beta[c] : 0.f;
        float y = (vv - mu) * inv * gamma[c] + b;
        __nv_bfloat16 h, l; bsplit(y, h, l);
        oh[base + c] = h; ol[base + c] = l;
    }
}

// ---------------- weight transpose + split: W[K,N] -> Wt[N,K] hi/lo ----------
__global__ void __launch_bounds__(256) wtrans_kernel(
    const float* __restrict__ W, __nv_bfloat16* __restrict__ th,
    __nv_bfloat16* __restrict__ tl, int Kd, int Nd)
{
    __shared__ float t[32][33];
    int tx = threadIdx.x & 31, ty = threadIdx.x >> 5;
    int n0 = blockIdx.x * 32, k0 = blockIdx.y * 32;
#pragma unroll
    for (int i = 0; i < 4; i++)
        t[ty + i * 8][tx] = W[(size_t)(k0 + ty + i * 8) * Nd + n0 + tx];
    __syncthreads();
#pragma unroll
    for (int i = 0; i < 4; i++) {
        int n = n0 + ty + i * 8;
        float v = t[tx][ty + i * 8];
        __nv_bfloat16 h, l; bsplit(v, h, l);
        th[(size_t)n * Kd + k0 + tx] = h;
        tl[(size_t)n * Kd + k0 + tx] = l;
    }
}

// --------------------------- fp32 -> split bf16 ------------------------------
__global__ void __launch_bounds__(256) split_kernel(
    const float* __restrict__ x, __nv_bfloat16* __restrict__ oh,
    __nv_bfloat16* __restrict__ ol)
{
    int i = blockIdx.x * 256 + threadIdx.x;
    __nv_bfloat16 h, l; bsplit(x[i], h, l);
    oh[i] = h; ol[i] = l;
}

// -------------------------- GELU gate -> split bf16 --------------------------
__global__ void __launch_bounds__(256) gate_kernel(
    const float* __restrict__ u, __nv_bfloat16* __restrict__ oh,
    __nv_bfloat16* __restrict__ ol)
{
    int idx = blockIdx.x * 256 + threadIdx.x;
    int row = idx >> 11, c = idx & 2047;
    float a  = u[(size_t)row * (2 * FFI) + c];
    float xg = u[(size_t)row * (2 * FFI) + FFI + c];
    float ge = 0.5f * xg * (1.0f + erff(xg * 0.7071067811865475f));
    __nv_bfloat16 h, l; bsplit(a * ge, h, l);
    oh[idx] = h; ol[idx] = l;
}

// ------------- RoPE + l2norm + scale (+8x for Q) -> split bf16 ---------------
__global__ void __launch_bounds__(256) rope_split_kernel(
    const float* __restrict__ src, int srcStride,
    const float* __restrict__ scale, float mult,
    __nv_bfloat16* __restrict__ dh, __nv_bfloat16* __restrict__ dl)
{
    int row = blockIdx.x, tid = threadIdx.x;
    int hh = tid >> 6, head = blockIdx.y * 4 + hh, d = tid & 63;
    int n = row & 1023, b = row >> 10;
    float v = src[(size_t)row * srcStride + head * DHEAD + d];
    int j = d >> 1, t = j >> 1;
    float p = (j & 1) ? (float)(n >> 5) : (float)(n & 31);
    float ang = p * exp2f(-0.830482024f * (float)t);
    float c = cosf(ang), s = sinf(ang);
    float other = __shfl_xor_sync(0xffffffffu, v, 1);
    float out = (d & 1) ? (other * s + v * c) : (v * c - other * s);
    float ss = out * out;
#pragma unroll
    for (int o = 16; o > 0; o >>= 1) ss += __shfl_xor_sync(0xffffffffu, ss, o);
    __shared__ float s8[8];
    if ((tid & 31) == 0) s8[tid >> 5] = ss;
    __syncthreads();
    float inv = 1.0f / fmaxf(sqrtf(s8[hh * 2] + s8[hh * 2 + 1]), 1e-12f);
    out = out * inv * scale[d] * mult;
    __nv_bfloat16 h, l; bsplit(out, h, l);
    size_t idx = (((size_t)(b * NHEADS + head)) * NSEQ + n) * DHEAD + d;
    dh[idx] = h; dl[idx] = l;
}

// --------- V transpose + split: kv[.,768+c] -> Vt[bh][d][n] hi/lo -------------
__global__ void __launch_bounds__(256) vtrans_split_kernel(
    const float* __restrict__ kv, __nv_bfloat16* __restrict__ vh,
    __nv_bfloat16* __restrict__ vl)
{
    __shared__ float t[32][65];
    int tid = threadIdx.x, bh = blockIdx.y, n0 = blockIdx.x * 32;
    int b = bh / NHEADS, h = bh % NHEADS;
#pragma unroll
    for (int i = 0; i < 8; i++) {
        int nl = (tid >> 6) + i * 4, d = tid & 63;
        t[nl][d] = kv[(size_t)(b * NSEQ + n0 + nl) * (2 * DIMM) + DIMM + h * DHEAD + d];
    }
    __syncthreads();
#pragma unroll
    for (int i = 0; i < 8; i++) {
        int dd = (tid >> 5) + i * 8, nl = tid & 31;
        float v = t[nl][dd];
        __nv_bfloat16 hi, lo; bsplit(v, hi, lo);
        size_t idx = ((size_t)bh * DHEAD + dd) * NSEQ + n0 + nl;
        vh[idx] = hi; vl[idx] = lo;
    }
}

// ================= tensor-core flash attention (split-3 bf16) =================
// block = (bh, 64 queries), 128 threads = 4 warps (16 q-rows each).
// AROW = 72 elems: row stride 144 B (16B-aligned for uint4 staging; ldmatrix
// row bases at banks 4r mod 32 -> conflict-free).
#define AROW 72
__global__ void __launch_bounds__(128) attn_tc_kernel(
    const __nv_bfloat16* __restrict__ Qh, const __nv_bfloat16* __restrict__ Ql,
    const __nv_bfloat16* __restrict__ Kh, const __nv_bfloat16* __restrict__ Kl,
    const __nv_bfloat16* __restrict__ Vh, const __nv_bfloat16* __restrict__ Vl,
    __nv_bfloat16* __restrict__ Oh, __nv_bfloat16* __restrict__ Ol)
{
    __shared__ __align__(16) __nv_bfloat16 sKh[64 * AROW], sKl[64 * AROW];
    __shared__ __align__(16) __nv_bfloat16 sVh[64 * AROW], sVl[64 * AROW];
    __shared__ __align__(16) __nv_bfloat16 sPh[64 * AROW], sPl[64 * AROW];

    int tid = threadIdx.x, lane = tid & 31, w = tid >> 5;
    int bh = blockIdx.y, q0 = blockIdx.x * 64;
    const __nv_bfloat16* qh = Qh + ((size_t)bh * NSEQ + q0) * DHEAD;
    const __nv_bfloat16* ql = Ql + ((size_t)bh * NSEQ + q0) * DHEAD;
    const __nv_bfloat16* kh = Kh + (size_t)bh * NSEQ * DHEAD;
    const __nv_bfloat16* kl = Kl + (size_t)bh * NSEQ * DHEAD;
    const __nv_bfloat16* vh = Vh + (size_t)bh * DHEAD * NSEQ;
    const __nv_bfloat16* vl = Vl + (size_t)bh * DHEAD * NSEQ;
    uint32_t aKh = smem_to_u32(sKh), aKl = smem_to_u32(sKl);
    uint32_t aVh = smem_to_u32(sVh), aVl = smem_to_u32(sVl);
    uint32_t aPh = smem_to_u32(sPh), aPl = smem_to_u32(sPl);

    // stage Q through sP buffers, then keep fragments in registers
#pragma unroll
    for (int i = 0; i < 4; i++) {
        int id = tid + i * 128, r = id >> 3, c8 = (id & 7) * 8;
        *reinterpret_cast<uint4*>(&sPh[r * AROW + c8]) =
            *reinterpret_cast<const uint4*>(qh + r * 64 + c8);
        *reinterpret_cast<uint4*>(&sPl[r * AROW + c8]) =
            *reinterpret_cast<const uint4*>(ql + r * 64 + c8);
    }
    __syncthreads();
    const int lj = lane >> 3, lr = lane & 7, m0 = w * 16;
    uint32_t qhf[4][4], qlf[4][4];
#pragma unroll
    for (int ks = 0; ks < 4; ks++) {
        uint32_t off = (uint32_t)((m0 + (lj & 1) * 8 + lr) * AROW +
                                  ks * 16 + (lj >> 1) * 8) * 2;
        LDSM4(qhf[ks], aPh + off);
        LDSM4(qlf[ks], aPl + off);
    }

    float m1 = -1e30f, m2 = -1e30f, l1 = 0.f, l2 = 0.f;
    float of[8][4];
#pragma unroll
    for (int nt = 0; nt < 8; nt++)
#pragma unroll
        for (int j = 0; j < 4; j++) of[nt][j] = 0.f;

    for (int kt = 0; kt < 16; kt++) {
        __syncthreads();
#pragma unroll
        for (int i = 0; i < 4; i++) {
            int id = tid + i * 128, r = id >> 3, c8 = (id & 7) * 8;
            *reinterpret_cast<uint4*>(&sKh[r * AROW + c8]) =
                *reinterpret_cast<const uint4*>(kh + (kt * 64 + r) * 64 + c8);
            *reinterpret_cast<uint4*>(&sKl[r * AROW + c8]) =
                *reinterpret_cast<const uint4*>(kl + (kt * 64 + r) * 64 + c8);
            *reinterpret_cast<uint4*>(&sVh[r * AROW + c8]) =
                *reinterpret_cast<const uint4*>(vh + r * NSEQ + kt * 64 + c8);
            *reinterpret_cast<uint4*>(&sVl[r * AROW + c8]) =
                *reinterpret_cast<const uint4*>(vl + r * NSEQ + kt * 64 + c8);
        }
        __syncthreads();

        // ---- S = Q K^T (split-3) ----
        float sf[8][4];
#pragma unroll
        for (int nt = 0; nt < 8; nt++)
#pragma unroll
            for (int j = 0; j < 4; j++) sf[nt][j] = 0.f;
#pragma unroll
        for (int ks = 0; ks < 4; ks++) {
#pragma unroll
            for (int bt = 0; bt < 4; bt++) {
                uint32_t khf[4], klf[4];
                uint32_t off = (uint32_t)((bt * 16 + (lj >> 1) * 8 + lr) * AROW +
                                          ks * 16 + (lj & 1) * 8) * 2;
                LDSM4(khf, aKh + off);
                LDSM4(klf, aKl + off);
#pragma unroll
                for (int hf = 0; hf < 2; hf++) {
                    int nt = bt * 2 + hf;
                    MMA_BF16(sf[nt], qhf[ks], khf[hf * 2], khf[hf * 2 + 1]);
                    MMA_BF16(sf[nt], qhf[ks], klf[hf * 2], klf[hf * 2 + 1]);
                    MMA_BF16(sf[nt], qlf[ks], khf[hf * 2], khf[hf * 2 + 1]);
                }
            }
        }

        // ---- online softmax in fragments ----
        float mx1 = -1e30f, mx2 = -1e30f;
#pragma unroll
        for (int nt = 0; nt < 8; nt++) {
            mx1 = fmaxf(mx1, fmaxf(sf[nt][0], sf[nt][1]));
            mx2 = fmaxf(mx2, fmaxf(sf[nt][2], sf[nt][3]));
        }
        mx1 = fmaxf(mx1, __shfl_xor_sync(0xffffffffu, mx1, 1));
        mx1 = fmaxf(mx1, __shfl_xor_sync(0xffffffffu, mx1, 2));
        mx2 = fmaxf(mx2, __shfl_xor_sync(0xffffffffu, mx2, 1));
        mx2 = fmaxf(mx2, __shfl_xor_sync(0xffffffffu, mx2, 2));
        float mn1 = fmaxf(m1, mx1), mn2 = fmaxf(m2, mx2);
        float c1 = fexp(m1 - mn1), c2 = fexp(m2 - mn2);
        float rs1 = 0.f, rs2 = 0.f;
#pragma unroll
        for (int nt = 0; nt < 8; nt++) {
            sf[nt][0] = fexp(sf[nt][0] - mn1);
            sf[nt][1] = fexp(sf[nt][1] - mn1);
            sf[nt][2] = fexp(sf[nt][2] - mn2);
            sf[nt][3] = fexp(sf[nt][3] - mn2);
            rs1 += sf[nt][0] + sf[nt][1];
            rs2 += sf[nt][2] + sf[nt][3];
        }
        rs1 += __shfl_xor_sync(0xffffffffu, rs1, 1);
        rs1 += __shfl_xor_sync(0xffffffffu, rs1, 2);
        rs2 += __shfl_xor_sync(0xffffffffu, rs2, 1);
        rs2 += __shfl_xor_sync(0xffffffffu, rs2, 2);
        l1 = l1 * c1 + rs1; l2 = l2 * c2 + rs2;
        m1 = mn1; m2 = mn2;
#pragma unroll
        for (int nt = 0; nt < 8; nt++) {
            of[nt][0] *= c1; of[nt][1] *= c1;
            of[nt][2] *= c2; of[nt][3] *= c2;
        }

        // ---- store P split into smem (own warp rows only) ----
        int r1 = m0 + (lane >> 2), r2 = r1 + 8, cc = (lane & 3) * 2;
#pragma unroll
        for (int nt = 0; nt < 8; nt++) {
            int col = nt * 8 + cc;
            __nv_bfloat16 h0, l0, h1, lo1;
            bsplit(sf[nt][0], h0, l0); bsplit(sf[nt][1], h1, lo1);
            *reinterpret_cast<uint32_t*>(&sPh[r1 * AROW + col]) = pack2(h0, h1);
            *reinterpret_cast<uint32_t*>(&sPl[r1 * AROW + col]) = pack2(l0, lo1);
            bsplit(sf[nt][2], h0, l0); bsplit(sf[nt][3], h1, lo1);
            *reinterpret_cast<uint32_t*>(&sPh[r2 * AROW + col]) = pack2(h0, h1);
            *reinterpret_cast<uint32_t*>(&sPl[r2 * AROW + col]) = pack2(l0, lo1);
        }
        __syncwarp();

        // ---- O += P V (split-3) ----
#pragma unroll
        for (int ks = 0; ks < 4; ks++) {
            uint32_t phf[4], plf[4];
            uint32_t offp = (uint32_t)((m0 + (lj & 1) * 8 + lr) * AROW +
                                       ks * 16 + (lj >> 1) * 8) * 2;
            LDSM4(phf, aPh + offp);
            LDSM4(plf, aPl + offp);
#pragma unroll
            for (int bt = 0; bt < 4; bt++) {
                uint32_t vhf[4], vlf[4];
                uint32_t offv = (uint32_t)((bt * 16 + (lj >> 1) * 8 + lr) * AROW +
                                           ks * 16 + (lj & 1) * 8) * 2;
                LDSM4(vhf, aVh + offv);
                LDSM4(vlf, aVl + offv);
#pragma unroll
                for (int hf = 0; hf < 2; hf++) {
                    int nt = bt * 2 + hf;
                    MMA_BF16(of[nt], phf, vhf[hf * 2], vhf[hf * 2 + 1]);
                    MMA_BF16(of[nt], phf, vlf[hf * 2], vlf[hf * 2 + 1]);
                    MMA_BF16(of[nt], plf, vhf[hf * 2], vhf[hf * 2 + 1]);
                }
            }
        }
    }

    // ---- epilogue: normalize, split, write straight into wo-GEMM A ----
    int b = bh / NHEADS, hh = bh % NHEADS;
    float inv1 = 1.0f / l1, inv2 = 1.0f / l2;
    int r1 = q0 + m0 + (lane >> 2), cc = (lane & 3) * 2;
    size_t row1 = (size_t)(b * NSEQ + r1) * DIMM + hh * DHEAD;
    size_t row2 = (size_t)(b * NSEQ + r1 + 8) * DIMM + hh * DHEAD;
#pragma unroll
    for (int nt = 0; nt < 8; nt++) {
        int col = nt * 8 + cc;
        __nv_bfloat16 h0, l0, h1, lo1;
        bsplit(of[nt][0] * inv1, h0, l0); bsplit(of[nt][1] * inv1, h1, lo1);
        *reinterpret_cast<uint32_t*>(Oh + row1 + col) = pack2(h0, h1);
        *reinterpret_cast<uint32_t*>(Ol + row1 + col) = pack2(l0, lo1);
        bsplit(of[nt][2] * inv2, h0, l0); bsplit(of[nt][3] * inv2, h1, lo1);
        *reinterpret_cast<uint32_t*>(Oh + row2 + col) = pack2(h0, h1);
        *reinterpret_cast<uint32_t*>(Ol + row2 + col) = pack2(l0, lo1);
    }
}

// =========== HMMA (mma.sync bf16) GEMM: C = A@B^T (+res), split-3 =============
#define SROW   40
#define SMAT   (128 * SROW)
#define SMATB  (SMAT * 2)
#define SSTAGE (4 * SMATB)
#define GSMEM  (2 * SSTAGE)

__global__ void __launch_bounds__(256) gemm_mma(
    const __nv_bfloat16* __restrict__ Ah, const __nv_bfloat16* __restrict__ Al,
    const __nv_bfloat16* __restrict__ Bh, const __nv_bfloat16* __restrict__ Bl,
    const float* __restrict__ res, float* __restrict__ C, int N, int K)
{
    extern __shared__ __align__(16) __nv_bfloat16 sm[];
    const int tid = threadIdx.x, lane = tid & 31, w = tid >> 5;
    const int wr = w & 1, wc = w >> 1;
    const int bm = blockIdx.y * 128, bn = blockIdx.x * 128;
    const int NK = K >> 5;
    const uint32_t sbase = smem_to_u32(sm);

    const int c0 = tid, c1 = tid + 256;
    const int r0 = c0 >> 2, q0 = (c0 & 3) * 8;
    const int r1 = c1 >> 2, q1 = (c1 & 3) * 8;
    const uint32_t d0 = (uint32_t)(r0 * SROW + q0) * 2;
    const uint32_t d1 = (uint32_t)(r1 * SROW + q1) * 2;

    const __nv_bfloat16* gAh = Ah + (size_t)bm * K;
    const __nv_bfloat16* gAl = Al + (size_t)bm * K;
    const __nv_bfloat16* gBh = Bh + (size_t)bn * K;
    const __nv_bfloat16* gBl = Bl + (size_t)bn * K;

    float acc[4][4][4];
#pragma unroll
    for (int a = 0; a < 4; a++)
#pragma unroll
        for (int b = 0; b < 4; b++)
#pragma unroll
            for (int c = 0; c < 4; c++) acc[a][b][c] = 0.f;

    auto issue = [&](int st, int kc) {
        uint32_t sb = sbase + st * SSTAGE;
        int ko = kc * 32;
        CPASYNC(sb + 0 * SMATB + d0, gAh + (size_t)r0 * K + ko + q0);
        CPASYNC(sb + 0 * SMATB + d1, gAh + (size_t)r1 * K + ko + q1);
        CPASYNC(sb + 1 * SMATB + d0, gAl + (size_t)r0 * K + ko + q0);
        CPASYNC(sb + 1 * SMATB + d1, gAl + (size_t)r1 * K + ko + q1);
        CPASYNC(sb + 2 * SMATB + d0, gBh + (size_t)r0 * K + ko + q0);
        CPASYNC(sb + 2 * SMATB + d1, gBh + (size_t)r1 * K + ko + q1);
        CPASYNC(sb + 3 * SMATB + d0, gBl + (size_t)r0 * K + ko + q0);
        CPASYNC(sb + 3 * SMATB + d1, gBl + (size_t)r1 * K + ko + q1);
    };

    issue(0, 0);
    CPCOMMIT();

    const int lj = lane >> 3, lr = lane & 7;

    for (int kc = 0; kc < NK; kc++) {
        bool more = (kc + 1 < NK);
        if (more) { issue((kc + 1) & 1, kc + 1); CPCOMMIT(); }
        if (more) CPWAIT1(); else CPWAIT0();
        __syncthreads();

        uint32_t sb = sbase + (kc & 1) * SSTAGE;
        uint32_t aH = sb, aL = sb + SMATB, bH = sb + 2 * SMATB, bL = sb + 3 * SMATB;

#pragma unroll
        for (int ks = 0; ks < 2; ks++) {
            uint32_t ahf[4][4], alf[4][4], bhf[2][4], blf[2][4];
#pragma unroll
            for (int mi = 0; mi < 4; mi++) {
                int mrow = wr * 64 + mi * 16 + (lj & 1) * 8 + lr;
                int kcol = ks * 16 + (lj >> 1) * 8;
                uint32_t off = (uint32_t)(mrow * SROW + kcol) * 2;
                LDSM4(ahf[mi], aH + off);
                LDSM4(alf[mi], aL + off);
            }
#pragma unroll
            for (int bt = 0; bt < 2; bt++) {
                int nrow = wc * 32 + bt * 16 + (lj >> 1) * 8 + lr;
                int kcol = ks * 16 + (lj & 1) * 8;
                uint32_t off = (uint32_t)(nrow * SROW + kcol) * 2;
                LDSM4(bhf[bt], bH + off);
                LDSM4(blf[bt], bL + off);
            }
#pragma unroll
            for (int mi = 0; mi < 4; mi++)
#pragma unroll
                for (int bt = 0; bt < 2; bt++)
#pragma unroll
                    for (int hf = 0; hf < 2; hf++) {
                        int nt = bt * 2 + hf;
                        MMA_BF16(acc[mi][nt], ahf[mi], bhf[bt][hf * 2], bhf[bt][hf * 2 + 1]);
                        MMA_BF16(acc[mi][nt], ahf[mi], blf[bt][hf * 2], blf[bt][hf * 2 + 1]);
                        MMA_BF16(acc[mi][nt], alf[mi], bhf[bt][hf * 2], bhf[bt][hf * 2 + 1]);
                    }
        }
        __syncthreads();
    }

#pragma unroll
    for (int mi = 0; mi < 4; mi++) {
        int row0 = bm + wr * 64 + mi * 16 + (lane >> 2);
#pragma unroll
        for (int nt = 0; nt < 4; nt++) {
            int col = bn + wc * 32 + nt * 8 + (lane & 3) * 2;
            size_t i0 = (size_t)row0 * N + col;
            size_t i1 = (size_t)(row0 + 8) * N + col;
            float2 v0 = make_float2(acc[mi][nt][0], acc[mi][nt][1]);
            float2 v1 = make_float2(acc[mi][nt][2], acc[mi][nt][3]);
            if (res) {
                float2 a0 = *reinterpret_cast<const float2*>(res + i0);
                float2 a1 = *reinterpret_cast<const float2*>(res + i1);
                v0.x += a0.x; v0.y += a0.y; v1.x += a1.x; v1.y += a1.y;
            }
            *reinterpret_cast<float2*>(C + i0) = v0;
            *reinterpret_cast<float2*>(C + i1) = v1;
        }
    }
}

// ------------------------------ launch ----------------------------------------
extern "C" void kernel_launch(void* const* d_in, const int* in_sizes, int n_in,
                              void* d_out, int out_size)
{
    (void)in_sizes; (void)n_in; (void)out_size;
    const float* x          = (const float*)d_in[0];
    const float* attn_gamma = (const float*)d_in[1];
    const float* wq         = (const float*)d_in[2];
    const float* wkv        = (const float*)d_in[3];
    const float* q_scale    = (const float*)d_in[4];
    const float* k_scale    = (const float*)d_in[5];
    const float* wo         = (const float*)d_in[6];
    const float* ff_gamma   = (const float*)d_in[7];
    const float* ff_beta    = (const float*)d_in[8];
    const float* wff1       = (const float*)d_in[9];
    const float* wff2       = (const float*)d_in[10];
    float* xo = (float*)d_out;

    float *q, *kv, *u;
    __nv_bfloat16 *ah, *al, *wth, *wtl, *qh, *ql, *kh, *kl, *vh, *vl;
    cudaGetSymbolAddress((void**)&q,   g_q);
    cudaGetSymbolAddress((void**)&kv,  g_kv);
    cudaGetSymbolAddress((void**)&u,   g_u);
    cudaGetSymbolAddress((void**)&ah,  g_ah);
    cudaGetSymbolAddress((void**)&al,  g_al);
    cudaGetSymbolAddress((void**)&wth, g_wth);
    cudaGetSymbolAddress((void**)&wtl, g_wtl);
    cudaGetSymbolAddress((void**)&qh,  g_qh);
    cudaGetSymbolAddress((void**)&ql,  g_ql);
    cudaGetSymbolAddress((void**)&kh,  g_kh);
    cudaGetSymbolAddress((void**)&kl,  g_kl);
    cudaGetSymbolAddress((void**)&vh,  g_vh);
    cudaGetSymbolAddress((void**)&vl,  g_vl);

    cudaFuncSetAttribute(gemm_mma, cudaFuncAttributeMaxDynamicSharedMemorySize, GSMEM);

    cudaMemcpyAsync(xo, x, (size_t)MTOK * DIMM * sizeof(float),
                    cudaMemcpyDeviceToDevice);

    for (int i = 0; i < 4; i++) {
        // --- attention block ---
        ln_kernel<<<MTOK, 256>>>(xo, attn_gamma + (size_t)i * DIMM, nullptr, ah, al);
        wtrans_kernel<<<dim3(24, 24), 256>>>(wq + (size_t)i * 768 * 768, wth, wtl, 768, 768);
        gemm_mma<<<dim3(6, 32), 256, GSMEM>>>(ah, al, wth, wtl, nullptr, q, 768, 768);
        split_kernel<<<(MTOK * DIMM) / 256, 256>>>(xo, ah, al);
        wtrans_kernel<<<dim3(48, 24), 256>>>(wkv + (size_t)i * 768 * 1536, wth, wtl, 768, 1536);
        gemm_mma<<<dim3(12, 32), 256, GSMEM>>>(ah, al, wth, wtl, nullptr, kv, 1536, 768);
        rope_split_kernel<<<dim3(MTOK, 3), 256>>>(q, DIMM, q_scale + (size_t)i * DHEAD,
                                                  8.0f, qh, ql);
        rope_split_kernel<<<dim3(MTOK, 3), 256>>>(kv, 2 * DIMM, k_scale + (size_t)i * DHEAD,
                                                  1.0f, kh, kl);
        vtrans_split_kernel<<<dim3(NSEQ / 32, BHTOT), 256>>>(kv, vh, vl);
        attn_tc_kernel<<<dim3(NSEQ / 64, BHTOT), 128>>>(qh, ql, kh, kl, vh, vl, ah, al);
        wtrans_kernel<<<dim3(24, 24), 256>>>(wo + (size_t)i * 768 * 768, wth, wtl, 768, 768);
        gemm_mma<<<dim3(6, 32), 256, GSMEM>>>(ah, al, wth, wtl, xo, xo, 768, 768);
        // --- feed-forward block ---
        ln_kernel<<<MTOK, 256>>>(xo, ff_gamma + (size_t)i * DIMM,
                                 ff_beta + (size_t)i * DIMM, ah, al);
        wtrans_kernel<<<dim3(128, 24), 256>>>(wff1 + (size_t)i * 768 * 4096, wth, wtl, 768, 4096);
        gemm_mma<<<dim3(32, 32), 256, GSMEM>>>(ah, al, wth, wtl, nullptr, u, 4096, 768);
        gate_kernel<<<(MTOK * FFI) / 256, 256>>>(u, ah, al);
        wtrans_kernel<<<dim3(24, 64), 256>>>(wff2 + (size_t)i * 2048 * 768, wth, wtl, 2048, 768);
        gemm_mma<<<dim3(6, 32), 256, GSMEM>>>(ah, al, wth, wtl, xo, xo, 768, 2048);
    }
}

// round 10
// speedup vs baseline: 2.5407x; 1.0873x over previous
#include <cuda_runtime.h>
#include <cuda_bf16.h>
#include <cstdint>
#include <cstddef>

#define DIMM    768
#define MTOK    4096
#define NSEQ    1024
#define NHEADS  12
#define DHEAD   64
#define FFI     2048
#define BHTOT   48

// ---------------- scratch (static device globals; no allocation) -------------
__device__ float g_q [MTOK * DIMM];
__device__ float g_kv[MTOK * 2 * DIMM];
__device__ float g_u [MTOK * 2 * FFI];
__device__ __align__(16) __nv_bfloat16 g_ah [MTOK * FFI];
__device__ __align__(16) __nv_bfloat16 g_al [MTOK * FFI];
__device__ __align__(16) __nv_bfloat16 g_wth[4096 * 768];
__device__ __align__(16) __nv_bfloat16 g_wtl[4096 * 768];
__device__ __align__(16) __nv_bfloat16 g_qh [BHTOT * NSEQ * DHEAD];
__device__ __align__(16) __nv_bfloat16 g_ql [BHTOT * NSEQ * DHEAD];
__device__ __align__(16) __nv_bfloat16 g_kh [BHTOT * NSEQ * DHEAD];
__device__ __align__(16) __nv_bfloat16 g_kl [BHTOT * NSEQ * DHEAD];
__device__ __align__(16) __nv_bfloat16 g_vh [BHTOT * NSEQ * DHEAD]; // [bh][d][n]
__device__ __align__(16) __nv_bfloat16 g_vl [BHTOT * NSEQ * DHEAD];

// =========================== PTX helpers (sm_80-safe) =========================
__device__ __forceinline__ uint32_t smem_to_u32(const void* p) {
    uint32_t a;
    asm("{ .reg .u64 t; cvta.to.shared.u64 t, %1; cvt.u32.u64 %0, t; }"
        : "=r"(a) : "l"(p));
    return a;
}
#define CPASYNC(d, s) \
    asm volatile("cp.async.cg.shared.global [%0], [%1], 16;" :: "r"(d), "l"(s))
#define CPCOMMIT() asm volatile("cp.async.commit_group;" ::: "memory")
#define CPWAIT1()  asm volatile("cp.async.wait_group 1;" ::: "memory")
#define CPWAIT0()  asm volatile("cp.async.wait_group 0;" ::: "memory")
#define LDSM4(r, addr) \
    asm volatile("ldmatrix.sync.aligned.m8n8.x4.shared.b16 {%0,%1,%2,%3}, [%4];" \
        : "=r"((r)[0]), "=r"((r)[1]), "=r"((r)[2]), "=r"((r)[3]) : "r"(addr))
#define MMA_BF16(d, a, b0, b1) \
    asm volatile("mma.sync.aligned.m16n8k16.row.col.f32.bf16.bf16.f32 " \
        "{%0,%1,%2,%3}, {%4,%5,%6,%7}, {%8,%9}, {%0,%1,%2,%3};" \
        : "+f"((d)[0]), "+f"((d)[1]), "+f"((d)[2]), "+f"((d)[3]) \
        : "r"((a)[0]), "r"((a)[1]), "r"((a)[2]), "r"((a)[3]), "r"(b0), "r"(b1))

__device__ __forceinline__ void bsplit(float v, __nv_bfloat16& h, __nv_bfloat16& l) {
    h = __float2bfloat16(v);
    l = __float2bfloat16(v - __bfloat162float(h));
}
__device__ __forceinline__ uint32_t pack2(__nv_bfloat16 a, __nv_bfloat16 b) {
    return (uint32_t)__bfloat16_as_ushort(a) |
           ((uint32_t)__bfloat16_as_ushort(b) << 16);
}
// fast exp for y <= 0 (poly 2^f, magic-number split); rel err ~3e-6
__device__ __forceinline__ float fexp(float y) {
    float t = fmaxf(y * 1.4426950408889634f, -60.0f);
    float z = t + 12582912.0f;
    int   i = __float_as_int(z) - 0x4B400000;
    float f = t - (z - 12582912.0f);
    float p = 1.3333558146e-3f;
    p = fmaf(p, f, 9.6181291076e-3f);
    p = fmaf(p, f, 5.5504108664e-2f);
    p = fmaf(p, f, 2.4022650696e-1f);
    p = fmaf(p, f, 6.9314718056e-1f);
    p = fmaf(p, f, 1.0f);
    return __int_as_float(__float_as_int(p) + (i << 23));
}

// ------------------------- LayerNorm -> split bf16 ---------------------------
__global__ void __launch_bounds__(256) ln_kernel(
    const float* __restrict__ x, const float* __restrict__ gamma,
    const float* __restrict__ beta,
    __nv_bfloat16* __restrict__ oh, __nv_bfloat16* __restrict__ ol)
{
    int row = blockIdx.x, tid = threadIdx.x;
    const float* xr = x + (size_t)row * DIMM;
    float v0 = xr[tid], v1 = xr[tid + 256], v2 = xr[tid + 512];
    float s = v0 + v1 + v2, sq = v0 * v0 + v1 * v1 + v2 * v2;
#pragma unroll
    for (int o = 16; o > 0; o >>= 1) {
        s  += __shfl_xor_sync(0xffffffffu, s, o);
        sq += __shfl_xor_sync(0xffffffffu, sq, o);
    }
    __shared__ float red[16];
    if ((tid & 31) == 0) { red[tid >> 5] = s; red[(tid >> 5) + 8] = sq; }
    __syncthreads();
    float ts = 0.f, tq = 0.f;
#pragma unroll
    for (int i = 0; i < 8; i++) { ts += red[i]; tq += red[i + 8]; }
    float mu  = ts * (1.0f / 768.0f);
    float var = tq * (1.0f / 768.0f) - mu * mu;
    float inv = rsqrtf(var + 1e-5f);
    size_t base = (size_t)row * DIMM;
#pragma unroll
    for (int i = 0; i < 3; i++) {
        int c = tid + i * 256;
        float vv = (i == 0 ? v0 : (i == 1 ? v1 : v2));
        float b = beta ? beta[c] : 0.f;
        float y = (vv - mu) * inv * gamma[c] + b;
        __nv_bfloat16 h, l; bsplit(y, h, l);
        oh[base + c] = h; ol[base + c] = l;
    }
}

// ---------------- weight transpose + split: W[K,N] -> Wt[N,K] hi/lo ----------
__global__ void __launch_bounds__(256) wtrans_kernel(
    const float* __restrict__ W, __nv_bfloat16* __restrict__ th,
    __nv_bfloat16* __restrict__ tl, int Kd, int Nd)
{
    __shared__ float t[32][33];
    int tx = threadIdx.x & 31, ty = threadIdx.x >> 5;
    int n0 = blockIdx.x * 32, k0 = blockIdx.y * 32;
#pragma unroll
    for (int i = 0; i < 4; i++)
        t[ty + i * 8][tx] = W[(size_t)(k0 + ty + i * 8) * Nd + n0 + tx];
    __syncthreads();
#pragma unroll
    for (int i = 0; i < 4; i++) {
        int n = n0 + ty + i * 8;
        float v = t[tx][ty + i * 8];
        __nv_bfloat16 h, l; bsplit(v, h, l);
        th[(size_t)n * Kd + k0 + tx] = h;
        tl[(size_t)n * Kd + k0 + tx] = l;
    }
}

// --------------------------- fp32 -> split bf16 ------------------------------
__global__ void __launch_bounds__(256) split_kernel(
    const float* __restrict__ x, __nv_bfloat16* __restrict__ oh,
    __nv_bfloat16* __restrict__ ol)
{
    int i = blockIdx.x * 256 + threadIdx.x;
    __nv_bfloat16 h, l; bsplit(x[i], h, l);
    oh[i] = h; ol[i] = l;
}

// -------------------------- GELU gate -> split bf16 --------------------------
__global__ void __launch_bounds__(256) gate_kernel(
    const float* __restrict__ u, __nv_bfloat16* __restrict__ oh,
    __nv_bfloat16* __restrict__ ol)
{
    int idx = blockIdx.x * 256 + threadIdx.x;
    int row = idx >> 11, c = idx & 2047;
    float a  = u[(size_t)row * (2 * FFI) + c];
    float xg = u[(size_t)row * (2 * FFI) + FFI + c];
    float ge = 0.5f * xg * (1.0f + erff(xg * 0.7071067811865475f));
    __nv_bfloat16 h, l; bsplit(a * ge, h, l);
    oh[idx] = h; ol[idx] = l;
}

// ------------- RoPE + l2norm + scale (+8x for Q) -> split bf16 ---------------
__global__ void __launch_bounds__(256) rope_split_kernel(
    const float* __restrict__ src, int srcStride,
    const float* __restrict__ scale, float mult,
    __nv_bfloat16* __restrict__ dh, __nv_bfloat16* __restrict__ dl)
{
    int row = blockIdx.x, tid = threadIdx.x;
    int hh = tid >> 6, head = blockIdx.y * 4 + hh, d = tid & 63;
    int n = row & 1023, b = row >> 10;
    float v = src[(size_t)row * srcStride + head * DHEAD + d];
    int j = d >> 1, t = j >> 1;
    float p = (j & 1) ? (float)(n >> 5) : (float)(n & 31);
    float ang = p * exp2f(-0.830482024f * (float)t);
    float c = cosf(ang), s = sinf(ang);
    float other = __shfl_xor_sync(0xffffffffu, v, 1);
    float out = (d & 1) ? (other * s + v * c) : (v * c - other * s);
    float ss = out * out;
#pragma unroll
    for (int o = 16; o > 0; o >>= 1) ss += __shfl_xor_sync(0xffffffffu, ss, o);
    __shared__ float s8[8];
    if ((tid & 31) == 0) s8[tid >> 5] = ss;
    __syncthreads();
    float inv = 1.0f / fmaxf(sqrtf(s8[hh * 2] + s8[hh * 2 + 1]), 1e-12f);
    out = out * inv * scale[d] * mult;
    __nv_bfloat16 h, l; bsplit(out, h, l);
    size_t idx = (((size_t)(b * NHEADS + head)) * NSEQ + n) * DHEAD + d;
    dh[idx] = h; dl[idx] = l;
}

// --------- V transpose + split: kv[.,768+c] -> Vt[bh][d][n] hi/lo -------------
__global__ void __launch_bounds__(256) vtrans_split_kernel(
    const float* __restrict__ kv, __nv_bfloat16* __restrict__ vh,
    __nv_bfloat16* __restrict__ vl)
{
    __shared__ float t[32][65];
    int tid = threadIdx.x, bh = blockIdx.y, n0 = blockIdx.x * 32;
    int b = bh / NHEADS, h = bh % NHEADS;
#pragma unroll
    for (int i = 0; i < 8; i++) {
        int nl = (tid >> 6) + i * 4, d = tid & 63;
        t[nl][d] = kv[(size_t)(b * NSEQ + n0 + nl) * (2 * DIMM) + DIMM + h * DHEAD + d];
    }
    __syncthreads();
#pragma unroll
    for (int i = 0; i < 8; i++) {
        int dd = (tid >> 5) + i * 8, nl = tid & 31;
        float v = t[nl][dd];
        __nv_bfloat16 hi, lo; bsplit(v, hi, lo);
        size_t idx = ((size_t)bh * DHEAD + dd) * NSEQ + n0 + nl;
        vh[idx] = hi; vl[idx] = lo;
    }
}

// ================= tensor-core flash attention (split-3 bf16) =================
#define AROW 72
__global__ void __launch_bounds__(128) attn_tc_kernel(
    const __nv_bfloat16* __restrict__ Qh, const __nv_bfloat16* __restrict__ Ql,
    const __nv_bfloat16* __restrict__ Kh, const __nv_bfloat16* __restrict__ Kl,
    const __nv_bfloat16* __restrict__ Vh, const __nv_bfloat16* __restrict__ Vl,
    __nv_bfloat16* __restrict__ Oh, __nv_bfloat16* __restrict__ Ol)
{
    __shared__ __align__(16) __nv_bfloat16 sKh[64 * AROW], sKl[64 * AROW];
    __shared__ __align__(16) __nv_bfloat16 sVh[64 * AROW], sVl[64 * AROW];
    __shared__ __align__(16) __nv_bfloat16 sPh[64 * AROW], sPl[64 * AROW];

    int tid = threadIdx.x, lane = tid & 31, w = tid >> 5;
    int bh = blockIdx.y, q0 = blockIdx.x * 64;
    const __nv_bfloat16* qh = Qh + ((size_t)bh * NSEQ + q0) * DHEAD;
    const __nv_bfloat16* ql = Ql + ((size_t)bh * NSEQ + q0) * DHEAD;
    const __nv_bfloat16* kh = Kh + (size_t)bh * NSEQ * DHEAD;
    const __nv_bfloat16* kl = Kl + (size_t)bh * NSEQ * DHEAD;
    const __nv_bfloat16* vh = Vh + (size_t)bh * DHEAD * NSEQ;
    const __nv_bfloat16* vl = Vl + (size_t)bh * DHEAD * NSEQ;
    uint32_t aKh = smem_to_u32(sKh), aKl = smem_to_u32(sKl);
    uint32_t aVh = smem_to_u32(sVh), aVl = smem_to_u32(sVl);
    uint32_t aPh = smem_to_u32(sPh), aPl = smem_to_u32(sPl);

#pragma unroll
    for (int i = 0; i < 4; i++) {
        int id = tid + i * 128, r = id >> 3, c8 = (id & 7) * 8;
        *reinterpret_cast<uint4*>(&sPh[r * AROW + c8]) =
            *reinterpret_cast<const uint4*>(qh + r * 64 + c8);
        *reinterpret_cast<uint4*>(&sPl[r * AROW + c8]) =
            *reinterpret_cast<const uint4*>(ql + r * 64 + c8);
    }
    __syncthreads();
    const int lj = lane >> 3, lr = lane & 7, m0 = w * 16;
    uint32_t qhf[4][4], qlf[4][4];
#pragma unroll
    for (int ks = 0; ks < 4; ks++) {
        uint32_t off = (uint32_t)((m0 + (lj & 1) * 8 + lr) * AROW +
                                  ks * 16 + (lj >> 1) * 8) * 2;
        LDSM4(qhf[ks], aPh + off);
        LDSM4(qlf[ks], aPl + off);
    }

    float m1 = -1e30f, m2 = -1e30f, l1 = 0.f, l2 = 0.f;
    float of[8][4];
#pragma unroll
    for (int nt = 0; nt < 8; nt++)
#pragma unroll
        for (int j = 0; j < 4; j++) of[nt][j] = 0.f;

    for (int kt = 0; kt < 16; kt++) {
        __syncthreads();
#pragma unroll
        for (int i = 0; i < 4; i++) {
            int id = tid + i * 128, r = id >> 3, c8 = (id & 7) * 8;
            *reinterpret_cast<uint4*>(&sKh[r * AROW + c8]) =
                *reinterpret_cast<const uint4*>(kh + (kt * 64 + r) * 64 + c8);
            *reinterpret_cast<uint4*>(&sKl[r * AROW + c8]) =
                *reinterpret_cast<const uint4*>(kl + (kt * 64 + r) * 64 + c8);
            *reinterpret_cast<uint4*>(&sVh[r * AROW + c8]) =
                *reinterpret_cast<const uint4*>(vh + r * NSEQ + kt * 64 + c8);
            *reinterpret_cast<uint4*>(&sVl[r * AROW + c8]) =
                *reinterpret_cast<const uint4*>(vl + r * NSEQ + kt * 64 + c8);
        }
        __syncthreads();

        float sf[8][4];
#pragma unroll
        for (int nt = 0; nt < 8; nt++)
#pragma unroll
            for (int j = 0; j < 4; j++) sf[nt][j] = 0.f;
#pragma unroll
        for (int ks = 0; ks < 4; ks++) {
#pragma unroll
            for (int bt = 0; bt < 4; bt++) {
                uint32_t khf[4], klf[4];
                uint32_t off = (uint32_t)((bt * 16 + (lj >> 1) * 8 + lr) * AROW +
                                          ks * 16 + (lj & 1) * 8) * 2;
                LDSM4(khf, aKh + off);
                LDSM4(klf, aKl + off);
#pragma unroll
                for (int hf = 0; hf < 2; hf++) {
                    int nt = bt * 2 + hf;
                    MMA_BF16(sf[nt], qhf[ks], khf[hf * 2], khf[hf * 2 + 1]);
                    MMA_BF16(sf[nt], qhf[ks], klf[hf * 2], klf[hf * 2 + 1]);
                    MMA_BF16(sf[nt], qlf[ks], khf[hf * 2], khf[hf * 2 + 1]);
                }
            }
        }

        float mx1 = -1e30f, mx2 = -1e30f;
#pragma unroll
        for (int nt = 0; nt < 8; nt++) {
            mx1 = fmaxf(mx1, fmaxf(sf[nt][0], sf[nt][1]));
            mx2 = fmaxf(mx2, fmaxf(sf[nt][2], sf[nt][3]));
        }
        mx1 = fmaxf(mx1, __shfl_xor_sync(0xffffffffu, mx1, 1));
        mx1 = fmaxf(mx1, __shfl_xor_sync(0xffffffffu, mx1, 2));
        mx2 = fmaxf(mx2, __shfl_xor_sync(0xffffffffu, mx2, 1));
        mx2 = fmaxf(mx2, __shfl_xor_sync(0xffffffffu, mx2, 2));
        float mn1 = fmaxf(m1, mx1), mn2 = fmaxf(m2, mx2);
        float c1 = fexp(m1 - mn1), c2 = fexp(m2 - mn2);
        float rs1 = 0.f, rs2 = 0.f;
#pragma unroll
        for (int nt = 0; nt < 8; nt++) {
            sf[nt][0] = fexp(sf[nt][0] - mn1);
            sf[nt][1] = fexp(sf[nt][1] - mn1);
            sf[nt][2] = fexp(sf[nt][2] - mn2);
            sf[nt][3] = fexp(sf[nt][3] - mn2);
            rs1 += sf[nt][0] + sf[nt][1];
            rs2 += sf[nt][2] + sf[nt][3];
        }
        rs1 += __shfl_xor_sync(0xffffffffu, rs1, 1);
        rs1 += __shfl_xor_sync(0xffffffffu, rs1, 2);
        rs2 += __shfl_xor_sync(0xffffffffu, rs2, 1);
        rs2 += __shfl_xor_sync(0xffffffffu, rs2, 2);
        l1 = l1 * c1 + rs1; l2 = l2 * c2 + rs2;
        m1 = mn1; m2 = mn2;
#pragma unroll
        for (int nt = 0; nt < 8; nt++) {
            of[nt][0] *= c1; of[nt][1] *= c1;
            of[nt][2] *= c2; of[nt][3] *= c2;
        }

        int r1 = m0 + (lane >> 2), r2 = r1 + 8, cc = (lane & 3) * 2;
#pragma unroll
        for (int nt = 0; nt < 8; nt++) {
            int col = nt * 8 + cc;
            __nv_bfloat16 h0, l0, h1, lo1;
            bsplit(sf[nt][0], h0, l0); bsplit(sf[nt][1], h1, lo1);
            *reinterpret_cast<uint32_t*>(&sPh[r1 * AROW + col]) = pack2(h0, h1);
            *reinterpret_cast<uint32_t*>(&sPl[r1 * AROW + col]) = pack2(l0, lo1);
            bsplit(sf[nt][2], h0, l0); bsplit(sf[nt][3], h1, lo1);
            *reinterpret_cast<uint32_t*>(&sPh[r2 * AROW + col]) = pack2(h0, h1);
            *reinterpret_cast<uint32_t*>(&sPl[r2 * AROW + col]) = pack2(l0, lo1);
        }
        __syncwarp();

#pragma unroll
        for (int ks = 0; ks < 4; ks++) {
            uint32_t phf[4], plf[4];
            uint32_t offp = (uint32_t)((m0 + (lj & 1) * 8 + lr) * AROW +
                                       ks * 16 + (lj >> 1) * 8) * 2;
            LDSM4(phf, aPh + offp);
            LDSM4(plf, aPl + offp);
#pragma unroll
            for (int bt = 0; bt < 4; bt++) {
                uint32_t vhf[4], vlf[4];
                uint32_t offv = (uint32_t)((bt * 16 + (lj >> 1) * 8 + lr) * AROW +
                                           ks * 16 + (lj & 1) * 8) * 2;
                LDSM4(vhf, aVh + offv);
                LDSM4(vlf, aVl + offv);
#pragma unroll
                for (int hf = 0; hf < 2; hf++) {
                    int nt = bt * 2 + hf;
                    MMA_BF16(of[nt], phf, vhf[hf * 2], vhf[hf * 2 + 1]);
                    MMA_BF16(of[nt], phf, vlf[hf * 2], vlf[hf * 2 + 1]);
                    MMA_BF16(of[nt], plf, vhf[hf * 2], vhf[hf * 2 + 1]);
                }
            }
        }
    }

    int b = bh / NHEADS, hh = bh % NHEADS;
    float inv1 = 1.0f / l1, inv2 = 1.0f / l2;
    int r1 = q0 + m0 + (lane >> 2), cc = (lane & 3) * 2;
    size_t row1 = (size_t)(b * NSEQ + r1) * DIMM + hh * DHEAD;
    size_t row2 = (size_t)(b * NSEQ + r1 + 8) * DIMM + hh * DHEAD;
#pragma unroll
    for (int nt = 0; nt < 8; nt++) {
        int col = nt * 8 + cc;
        __nv_bfloat16 h0, l0, h1, lo1;
        bsplit(of[nt][0] * inv1, h0, l0); bsplit(of[nt][1] * inv1, h1, lo1);
        *reinterpret_cast<uint32_t*>(Oh + row1 + col) = pack2(h0, h1);
        *reinterpret_cast<uint32_t*>(Ol + row1 + col) = pack2(l0, lo1);
        bsplit(of[nt][2] * inv2, h0, l0); bsplit(of[nt][3] * inv2, h1, lo1);
        *reinterpret_cast<uint32_t*>(Oh + row2 + col) = pack2(h0, h1);
        *reinterpret_cast<uint32_t*>(Ol + row2 + col) = pack2(l0, lo1);
    }
}

// ====== HMMA GEMM: C = A@B^T (+res), split-3, 3-stage pipeline, BM tiles ======
#define SROW   40
template<int BM>
__global__ void __launch_bounds__(256, (BM == 64 ? 2 : 1)) gemm_mma(
    const __nv_bfloat16* __restrict__ Ah, const __nv_bfloat16* __restrict__ Al,
    const __nv_bfloat16* __restrict__ Bh, const __nv_bfloat16* __restrict__ Bl,
    const float* __restrict__ res, float* __restrict__ C, int N, int K)
{
    constexpr int MI   = BM / 32;               // m16 tiles per warp
    constexpr int ASZB = BM  * SROW * 2;        // bytes per A matrix per stage
    constexpr int BSZB = 128 * SROW * 2;        // bytes per B matrix per stage
    constexpr int STGB = 2 * ASZB + 2 * BSZB;   // stage bytes [Ah|Al|Bh|Bl]

    extern __shared__ __align__(16) __nv_bfloat16 sm[];
    const int tid = threadIdx.x, lane = tid & 31, w = tid >> 5;
    const int wr = w & 1, wc = w >> 1;
    const int bm = blockIdx.y * BM, bn = blockIdx.x * 128;
    const int NK = K >> 5;
    const uint32_t sbase = smem_to_u32(sm);

    const __nv_bfloat16* gAh = Ah + (size_t)bm * K;
    const __nv_bfloat16* gAl = Al + (size_t)bm * K;
    const __nv_bfloat16* gBh = Bh + (size_t)bn * K;
    const __nv_bfloat16* gBl = Bl + (size_t)bn * K;

    float acc[MI][4][4];
#pragma unroll
    for (int a = 0; a < MI; a++)
#pragma unroll
        for (int b = 0; b < 4; b++)
#pragma unroll
            for (int c = 0; c < 4; c++) acc[a][b][c] = 0.f;

    auto issue = [&](int st, int kc) {
        uint32_t sb = sbase + st * STGB;
        int ko = kc * 32;
#pragma unroll
        for (int c = tid; c < BM * 4; c += 256) {
            int r = c >> 2, qq = (c & 3) * 8;
            uint32_t d = (uint32_t)(r * SROW + qq) * 2;
            CPASYNC(sb + d,        gAh + (size_t)r * K + ko + qq);
            CPASYNC(sb + ASZB + d, gAl + (size_t)r * K + ko + qq);
        }
#pragma unroll
        for (int c = tid; c < 512; c += 256) {
            int r = c >> 2, qq = (c & 3) * 8;
            uint32_t d = (uint32_t)(r * SROW + qq) * 2;
            CPASYNC(sb + 2 * ASZB + d,        gBh + (size_t)r * K + ko + qq);
            CPASYNC(sb + 2 * ASZB + BSZB + d, gBl + (size_t)r * K + ko + qq);
        }
    };

    issue(0, 0); CPCOMMIT();
    issue(1, 1); CPCOMMIT();      // NK >= 24 always

    const int lj = lane >> 3, lr = lane & 7;

    for (int kc = 0; kc < NK; kc++) {
        if (kc + 2 <= NK) CPWAIT1(); else CPWAIT0();
        __syncthreads();
        if (kc + 2 < NK) { issue((kc + 2) % 3, kc + 2); CPCOMMIT(); }

        uint32_t sb = sbase + (kc % 3) * STGB;
        uint32_t aH = sb, aL = sb + ASZB;
        uint32_t bH = sb + 2 * ASZB, bL = sb + 2 * ASZB + BSZB;

#pragma unroll
        for (int ks = 0; ks < 2; ks++) {
            uint32_t ahf[MI][4], alf[MI][4], bhf[2][4], blf[2][4];
#pragma unroll
            for (int mi = 0; mi < MI; mi++) {
                int mrow = wr * (BM / 2) + mi * 16 + (lj & 1) * 8 + lr;
                int kcol = ks * 16 + (lj >> 1) * 8;
                uint32_t off = (uint32_t)(mrow * SROW + kcol) * 2;
                LDSM4(ahf[mi], aH + off);
                LDSM4(alf[mi], aL + off);
            }
#pragma unroll
            for (int bt = 0; bt < 2; bt++) {
                int nrow = wc * 32 + bt * 16 + (lj >> 1) * 8 + lr;
                int kcol = ks * 16 + (lj & 1) * 8;
                uint32_t off = (uint32_t)(nrow * SROW + kcol) * 2;
                LDSM4(bhf[bt], bH + off);
                LDSM4(blf[bt], bL + off);
            }
#pragma unroll
            for (int mi = 0; mi < MI; mi++)
#pragma unroll
                for (int bt = 0; bt < 2; bt++)
#pragma unroll
                    for (int hf = 0; hf < 2; hf++) {
                        int nt = bt * 2 + hf;
                        MMA_BF16(acc[mi][nt], ahf[mi], bhf[bt][hf * 2], bhf[bt][hf * 2 + 1]);
                        MMA_BF16(acc[mi][nt], ahf[mi], blf[bt][hf * 2], blf[bt][hf * 2 + 1]);
                        MMA_BF16(acc[mi][nt], alf[mi], bhf[bt][hf * 2], bhf[bt][hf * 2 + 1]);
                    }
        }
    }

#pragma unroll
    for (int mi = 0; mi < MI; mi++) {
        int row0 = bm + wr * (BM / 2) + mi * 16 + (lane >> 2);
#pragma unroll
        for (int nt = 0; nt < 4; nt++) {
            int col = bn + wc * 32 + nt * 8 + (lane & 3) * 2;
            size_t i0 = (size_t)row0 * N + col;
            size_t i1 = (size_t)(row0 + 8) * N + col;
            float2 v0 = make_float2(acc[mi][nt][0], acc[mi][nt][1]);
            float2 v1 = make_float2(acc[mi][nt][2], acc[mi][nt][3]);
            if (res) {
                float2 a0 = *reinterpret_cast<const float2*>(res + i0);
                float2 a1 = *reinterpret_cast<const float2*>(res + i1);
                v0.x += a0.x; v0.y += a0.y; v1.x += a1.x; v1.y += a1.y;
            }
            *reinterpret_cast<float2*>(C + i0) = v0;
            *reinterpret_cast<float2*>(C + i1) = v1;
        }
    }
}

#define GSMEM128 (3 * (2 * 128 * SROW * 2 + 2 * 128 * SROW * 2))
#define GSMEM64  (3 * (2 * 64  * SROW * 2 + 2 * 128 * SROW * 2))

// ------------------------------ launch ----------------------------------------
extern "C" void kernel_launch(void* const* d_in, const int* in_sizes, int n_in,
                              void* d_out, int out_size)
{
    (void)in_sizes; (void)n_in; (void)out_size;
    const float* x          = (const float*)d_in[0];
    const float* attn_gamma = (const float*)d_in[1];
    const float* wq         = (const float*)d_in[2];
    const float* wkv        = (const float*)d_in[3];
    const float* q_scale    = (const float*)d_in[4];
    const float* k_scale    = (const float*)d_in[5];
    const float* wo         = (const float*)d_in[6];
    const float* ff_gamma   = (const float*)d_in[7];
    const float* ff_beta    = (const float*)d_in[8];
    const float* wff1       = (const float*)d_in[9];
    const float* wff2       = (const float*)d_in[10];
    float* xo = (float*)d_out;

    float *q, *kv, *u;
    __nv_bfloat16 *ah, *al, *wth, *wtl, *qh, *ql, *kh, *kl, *vh, *vl;
    cudaGetSymbolAddress((void**)&q,   g_q);
    cudaGetSymbolAddress((void**)&kv,  g_kv);
    cudaGetSymbolAddress((void**)&u,   g_u);
    cudaGetSymbolAddress((void**)&ah,  g_ah);
    cudaGetSymbolAddress((void**)&al,  g_al);
    cudaGetSymbolAddress((void**)&wth, g_wth);
    cudaGetSymbolAddress((void**)&wtl, g_wtl);
    cudaGetSymbolAddress((void**)&qh,  g_qh);
    cudaGetSymbolAddress((void**)&ql,  g_ql);
    cudaGetSymbolAddress((void**)&kh,  g_kh);
    cudaGetSymbolAddress((void**)&kl,  g_kl);
    cudaGetSymbolAddress((void**)&vh,  g_vh);
    cudaGetSymbolAddress((void**)&vl,  g_vl);

    cudaFuncSetAttribute(gemm_mma<128>, cudaFuncAttributeMaxDynamicSharedMemorySize, GSMEM128);
    cudaFuncSetAttribute(gemm_mma<64>,  cudaFuncAttributeMaxDynamicSharedMemorySize, GSMEM64);

    cudaMemcpyAsync(xo, x, (size_t)MTOK * DIMM * sizeof(float),
                    cudaMemcpyDeviceToDevice);

    for (int i = 0; i < 4; i++) {
        // --- attention block ---
        ln_kernel<<<MTOK, 256>>>(xo, attn_gamma + (size_t)i * DIMM, nullptr, ah, al);
        wtrans_kernel<<<dim3(24, 24), 256>>>(wq + (size_t)i * 768 * 768, wth, wtl, 768, 768);
        gemm_mma<64><<<dim3(6, 64), 256, GSMEM64>>>(ah, al, wth, wtl, nullptr, q, 768, 768);
        split_kernel<<<(MTOK * DIMM) / 256, 256>>>(xo, ah, al);
        wtrans_kernel<<<dim3(48, 24), 256>>>(wkv + (size_t)i * 768 * 1536, wth, wtl, 768, 1536);
        gemm_mma<128><<<dim3(12, 32), 256, GSMEM128>>>(ah, al, wth, wtl, nullptr, kv, 1536, 768);
        rope_split_kernel<<<dim3(MTOK, 3), 256>>>(q, DIMM, q_scale + (size_t)i * DHEAD,
                                                  8.0f, qh, ql);
        rope_split_kernel<<<dim3(MTOK, 3), 256>>>(kv, 2 * DIMM, k_scale + (size_t)i * DHEAD,
                                                  1.0f, kh, kl);
        vtrans_split_kernel<<<dim3(NSEQ / 32, BHTOT), 256>>>(kv, vh, vl);
        attn_tc_kernel<<<dim3(NSEQ / 64, BHTOT), 128>>>(qh, ql, kh, kl, vh, vl, ah, al);
        wtrans_kernel<<<dim3(24, 24), 256>>>(wo + (size_t)i * 768 * 768, wth, wtl, 768, 768);
        gemm_mma<64><<<dim3(6, 64), 256, GSMEM64>>>(ah, al, wth, wtl, xo, xo, 768, 768);
        // --- feed-forward block ---
        ln_kernel<<<MTOK, 256>>>(xo, ff_gamma + (size_t)i * DIMM,
                                 ff_beta + (size_t)i * DIMM, ah, al);
        wtrans_kernel<<<dim3(128, 24), 256>>>(wff1 + (size_t)i * 768 * 4096, wth, wtl, 768, 4096);
        gemm_mma<128><<<dim3(32, 32), 256, GSMEM128>>>(ah, al, wth, wtl, nullptr, u, 4096, 768);
        gate_kernel<<<(MTOK * FFI) / 256, 256>>>(u, ah, al);
        wtrans_kernel<<<dim3(24, 64), 256>>>(wff2 + (size_t)i * 2048 * 768, wth, wtl, 2048, 768);
        gemm_mma<64><<<dim3(6, 64), 256, GSMEM64>>>(ah, al, wth, wtl, xo, xo, 768, 2048);
    }
}

// round 11
// speedup vs baseline: 2.6473x; 1.0419x over previous
#include <cuda_runtime.h>
#include <cuda_bf16.h>
#include <cstdint>
#include <cstddef>

#define DIMM    768
#define MTOK    4096
#define NSEQ    1024
#define NHEADS  12
#define DHEAD   64
#define FFI     2048
#define BHTOT   48

// ---------------- scratch (static device globals; no allocation) -------------
__device__ float g_q [MTOK * DIMM];
__device__ float g_kv[MTOK * 2 * DIMM];
__device__ float g_u [MTOK * 2 * FFI];
__device__ __align__(16) __nv_bfloat16 g_ah [MTOK * FFI];
__device__ __align__(16) __nv_bfloat16 g_al [MTOK * FFI];
__device__ __align__(16) __nv_bfloat16 g_xh [MTOK * DIMM];
__device__ __align__(16) __nv_bfloat16 g_xl [MTOK * DIMM];
__device__ __align__(16) __nv_bfloat16 g_wth [4096 * 768];
__device__ __align__(16) __nv_bfloat16 g_wtl [4096 * 768];
__device__ __align__(16) __nv_bfloat16 g_wth2[768 * 2048];
__device__ __align__(16) __nv_bfloat16 g_wtl2[768 * 2048];
__device__ __align__(16) __nv_bfloat16 g_qh [BHTOT * NSEQ * DHEAD];
__device__ __align__(16) __nv_bfloat16 g_ql [BHTOT * NSEQ * DHEAD];
__device__ __align__(16) __nv_bfloat16 g_kh [BHTOT * NSEQ * DHEAD];
__device__ __align__(16) __nv_bfloat16 g_kl [BHTOT * NSEQ * DHEAD];
__device__ __align__(16) __nv_bfloat16 g_vh [BHTOT * NSEQ * DHEAD]; // [bh][d][n]
__device__ __align__(16) __nv_bfloat16 g_vl [BHTOT * NSEQ * DHEAD];

// =========================== PTX helpers (sm_80-safe) =========================
__device__ __forceinline__ uint32_t smem_to_u32(const void* p) {
    uint32_t a;
    asm("{ .reg .u64 t; cvta.to.shared.u64 t, %1; cvt.u32.u64 %0, t; }"
        : "=r"(a) : "l"(p));
    return a;
}
#define CPASYNC(d, s) \
    asm volatile("cp.async.cg.shared.global [%0], [%1], 16;" :: "r"(d), "l"(s))
#define CPCOMMIT() asm volatile("cp.async.commit_group;" ::: "memory")
#define CPWAIT1()  asm volatile("cp.async.wait_group 1;" ::: "memory")
#define CPWAIT0()  asm volatile("cp.async.wait_group 0;" ::: "memory")
#define LDSM4(r, addr) \
    asm volatile("ldmatrix.sync.aligned.m8n8.x4.shared.b16 {%0,%1,%2,%3}, [%4];" \
        : "=r"((r)[0]), "=r"((r)[1]), "=r"((r)[2]), "=r"((r)[3]) : "r"(addr))
#define MMA_BF16(d, a, b0, b1) \
    asm volatile("mma.sync.aligned.m16n8k16.row.col.f32.bf16.bf16.f32 " \
        "{%0,%1,%2,%3}, {%4,%5,%6,%7}, {%8,%9}, {%0,%1,%2,%3};" \
        : "+f"((d)[0]), "+f"((d)[1]), "+f"((d)[2]), "+f"((d)[3]) \
        : "r"((a)[0]), "r"((a)[1]), "r"((a)[2]), "r"((a)[3]), "r"(b0), "r"(b1))

__device__ __forceinline__ void bsplit(float v, __nv_bfloat16& h, __nv_bfloat16& l) {
    h = __float2bfloat16(v);
    l = __float2bfloat16(v - __bfloat162float(h));
}
__device__ __forceinline__ uint32_t pack2(__nv_bfloat16 a, __nv_bfloat16 b) {
    return (uint32_t)__bfloat16_as_ushort(a) |
           ((uint32_t)__bfloat16_as_ushort(b) << 16);
}
// fast exp for y <= 0 (poly 2^f, magic-number split); rel err ~3e-6
__device__ __forceinline__ float fexp(float y) {
    float t = fmaxf(y * 1.4426950408889634f, -60.0f);
    float z = t + 12582912.0f;
    int   i = __float_as_int(z) - 0x4B400000;
    float f = t - (z - 12582912.0f);
    float p = 1.3333558146e-3f;
    p = fmaf(p, f, 9.6181291076e-3f);
    p = fmaf(p, f, 5.5504108664e-2f);
    p = fmaf(p, f, 2.4022650696e-1f);
    p = fmaf(p, f, 6.9314718056e-1f);
    p = fmaf(p, f, 1.0f);
    return __int_as_float(__float_as_int(p) + (i << 23));
}

// ------------------------- LayerNorm -> split bf16 ---------------------------
__global__ void __launch_bounds__(256) ln_kernel(
    const float* __restrict__ x, const float* __restrict__ gamma,
    const float* __restrict__ beta,
    __nv_bfloat16* __restrict__ oh, __nv_bfloat16* __restrict__ ol)
{
    int row = blockIdx.x, tid = threadIdx.x;
    const float* xr = x + (size_t)row * DIMM;
    float v0 = xr[tid], v1 = xr[tid + 256], v2 = xr[tid + 512];
    float s = v0 + v1 + v2, sq = v0 * v0 + v1 * v1 + v2 * v2;
#pragma unroll
    for (int o = 16; o > 0; o >>= 1) {
        s  += __shfl_xor_sync(0xffffffffu, s, o);
        sq += __shfl_xor_sync(0xffffffffu, sq, o);
    }
    __shared__ float red[16];
    if ((tid & 31) == 0) { red[tid >> 5] = s; red[(tid >> 5) + 8] = sq; }
    __syncthreads();
    float ts = 0.f, tq = 0.f;
#pragma unroll
    for (int i = 0; i < 8; i++) { ts += red[i]; tq += red[i + 8]; }
    float mu  = ts * (1.0f / 768.0f);
    float var = tq * (1.0f / 768.0f) - mu * mu;
    float inv = rsqrtf(var + 1e-5f);
    size_t base = (size_t)row * DIMM;
#pragma unroll
    for (int i = 0; i < 3; i++) {
        int c = tid + i * 256;
        float vv = (i == 0 ? v0 : (i == 1 ? v1 : v2));
        float b = beta ? beta[c] : 0.f;
        float y = (vv - mu) * inv * gamma[c] + b;
        __nv_bfloat16 h, l; bsplit(y, h, l);
        oh[base + c] = h; ol[base + c] = l;
    }
}

// ---------------- weight transpose + split: W[K,N] -> Wt[N,K] hi/lo ----------
__global__ void __launch_bounds__(256) wtrans_kernel(
    const float* __restrict__ W, __nv_bfloat16* __restrict__ th,
    __nv_bfloat16* __restrict__ tl, int Kd, int Nd)
{
    __shared__ float t[32][33];
    int tx = threadIdx.x & 31, ty = threadIdx.x >> 5;
    int n0 = blockIdx.x * 32, k0 = blockIdx.y * 32;
#pragma unroll
    for (int i = 0; i < 4; i++)
        t[ty + i * 8][tx] = W[(size_t)(k0 + ty + i * 8) * Nd + n0 + tx];
    __syncthreads();
#pragma unroll
    for (int i = 0; i < 4; i++) {
        int n = n0 + ty + i * 8;
        float v = t[tx][ty + i * 8];
        __nv_bfloat16 h, l; bsplit(v, h, l);
        th[(size_t)n * Kd + k0 + tx] = h;
        tl[(size_t)n * Kd + k0 + tx] = l;
    }
}

// --------------------------- fp32 -> split bf16 ------------------------------
__global__ void __launch_bounds__(256) split_kernel(
    const float* __restrict__ x, __nv_bfloat16* __restrict__ oh,
    __nv_bfloat16* __restrict__ ol)
{
    int i = blockIdx.x * 256 + threadIdx.x;
    __nv_bfloat16 h, l; bsplit(x[i], h, l);
    oh[i] = h; ol[i] = l;
}

// -------------------------- GELU gate -> split bf16 --------------------------
__global__ void __launch_bounds__(256) gate_kernel(
    const float* __restrict__ u, __nv_bfloat16* __restrict__ oh,
    __nv_bfloat16* __restrict__ ol)
{
    int idx = blockIdx.x * 256 + threadIdx.x;
    int row = idx >> 11, c = idx & 2047;
    float a  = u[(size_t)row * (2 * FFI) + c];
    float xg = u[(size_t)row * (2 * FFI) + FFI + c];
    float ge = 0.5f * xg * (1.0f + erff(xg * 0.7071067811865475f));
    __nv_bfloat16 h, l; bsplit(a * ge, h, l);
    oh[idx] = h; ol[idx] = l;
}

// ------------- RoPE + l2norm + scale (+8x for Q) -> split bf16 ---------------
__global__ void __launch_bounds__(256) rope_split_kernel(
    const float* __restrict__ src, int srcStride,
    const float* __restrict__ scale, float mult,
    __nv_bfloat16* __restrict__ dh, __nv_bfloat16* __restrict__ dl)
{
    int row = blockIdx.x, tid = threadIdx.x;
    int hh = tid >> 6, head = blockIdx.y * 4 + hh, d = tid & 63;
    int n = row & 1023, b = row >> 10;
    float v = src[(size_t)row * srcStride + head * DHEAD + d];
    int j = d >> 1, t = j >> 1;
    float p = (j & 1) ? (float)(n >> 5) : (float)(n & 31);
    float ang = p * exp2f(-0.830482024f * (float)t);
    float c = cosf(ang), s = sinf(ang);
    float other = __shfl_xor_sync(0xffffffffu, v, 1);
    float out = (d & 1) ? (other * s + v * c) : (v * c - other * s);
    float ss = out * out;
#pragma unroll
    for (int o = 16; o > 0; o >>= 1) ss += __shfl_xor_sync(0xffffffffu, ss, o);
    __shared__ float s8[8];
    if ((tid & 31) == 0) s8[tid >> 5] = ss;
    __syncthreads();
    float inv = 1.0f / fmaxf(sqrtf(s8[hh * 2] + s8[hh * 2 + 1]), 1e-12f);
    out = out * inv * scale[d] * mult;
    __nv_bfloat16 h, l; bsplit(out, h, l);
    size_t idx = (((size_t)(b * NHEADS + head)) * NSEQ + n) * DHEAD + d;
    dh[idx] = h; dl[idx] = l;
}

// --------- V transpose + split: kv[.,768+c] -> Vt[bh][d][n] hi/lo -------------
__global__ void __launch_bounds__(256) vtrans_split_kernel(
    const float* __restrict__ kv, __nv_bfloat16* __restrict__ vh,
    __nv_bfloat16* __restrict__ vl)
{
    __shared__ float t[32][65];
    int tid = threadIdx.x, bh = blockIdx.y, n0 = blockIdx.x * 32;
    int b = bh / NHEADS, h = bh % NHEADS;
#pragma unroll
    for (int i = 0; i < 8; i++) {
        int nl = (tid >> 6) + i * 4, d = tid & 63;
        t[nl][d] = kv[(size_t)(b * NSEQ + n0 + nl) * (2 * DIMM) + DIMM + h * DHEAD + d];
    }
    __syncthreads();
#pragma unroll
    for (int i = 0; i < 8; i++) {
        int dd = (tid >> 5) + i * 8, nl = tid & 31;
        float v = t[nl][dd];
        __nv_bfloat16 hi, lo; bsplit(v, hi, lo);
        size_t idx = ((size_t)bh * DHEAD + dd) * NSEQ + n0 + nl;
        vh[idx] = hi; vl[idx] = lo;
    }
}

// ================= tensor-core flash attention (split-3 bf16) =================
#define AROW 72
__global__ void __launch_bounds__(128) attn_tc_kernel(
    const __nv_bfloat16* __restrict__ Qh, const __nv_bfloat16* __restrict__ Ql,
    const __nv_bfloat16* __restrict__ Kh, const __nv_bfloat16* __restrict__ Kl,
    const __nv_bfloat16* __restrict__ Vh, const __nv_bfloat16* __restrict__ Vl,
    __nv_bfloat16* __restrict__ Oh, __nv_bfloat16* __restrict__ Ol)
{
    __shared__ __align__(16) __nv_bfloat16 sKh[64 * AROW], sKl[64 * AROW];
    __shared__ __align__(16) __nv_bfloat16 sVh[64 * AROW], sVl[64 * AROW];
    __shared__ __align__(16) __nv_bfloat16 sPh[64 * AROW], sPl[64 * AROW];

    int tid = threadIdx.x, lane = tid & 31, w = tid >> 5;
    int bh = blockIdx.y, q0 = blockIdx.x * 64;
    const __nv_bfloat16* qh = Qh + ((size_t)bh * NSEQ + q0) * DHEAD;
    const __nv_bfloat16* ql = Ql + ((size_t)bh * NSEQ + q0) * DHEAD;
    const __nv_bfloat16* kh = Kh + (size_t)bh * NSEQ * DHEAD;
    const __nv_bfloat16* kl = Kl + (size_t)bh * NSEQ * DHEAD;
    const __nv_bfloat16* vh = Vh + (size_t)bh * DHEAD * NSEQ;
    const __nv_bfloat16* vl = Vl + (size_t)bh * DHEAD * NSEQ;
    uint32_t aKh = smem_to_u32(sKh), aKl = smem_to_u32(sKl);
    uint32_t aVh = smem_to_u32(sVh), aVl = smem_to_u32(sVl);
    uint32_t aPh = smem_to_u32(sPh), aPl = smem_to_u32(sPl);

#pragma unroll
    for (int i = 0; i < 4; i++) {
        int id = tid + i * 128, r = id >> 3, c8 = (id & 7) * 8;
        *reinterpret_cast<uint4*>(&sPh[r * AROW + c8]) =
            *reinterpret_cast<const uint4*>(qh + r * 64 + c8);
        *reinterpret_cast<uint4*>(&sPl[r * AROW + c8]) =
            *reinterpret_cast<const uint4*>(ql + r * 64 + c8);
    }
    __syncthreads();
    const int lj = lane >> 3, lr = lane & 7, m0 = w * 16;
    uint32_t qhf[4][4], qlf[4][4];
#pragma unroll
    for (int ks = 0; ks < 4; ks++) {
        uint32_t off = (uint32_t)((m0 + (lj & 1) * 8 + lr) * AROW +
                                  ks * 16 + (lj >> 1) * 8) * 2;
        LDSM4(qhf[ks], aPh + off);
        LDSM4(qlf[ks], aPl + off);
    }

    float m1 = -1e30f, m2 = -1e30f, l1 = 0.f, l2 = 0.f;
    float of[8][4];
#pragma unroll
    for (int nt = 0; nt < 8; nt++)
#pragma unroll
        for (int j = 0; j < 4; j++) of[nt][j] = 0.f;

    for (int kt = 0; kt < 16; kt++) {
        __syncthreads();
#pragma unroll
        for (int i = 0; i < 4; i++) {
            int id = tid + i * 128, r = id >> 3, c8 = (id & 7) * 8;
            *reinterpret_cast<uint4*>(&sKh[r * AROW + c8]) =
                *reinterpret_cast<const uint4*>(kh + (kt * 64 + r) * 64 + c8);
            *reinterpret_cast<uint4*>(&sKl[r * AROW + c8]) =
                *reinterpret_cast<const uint4*>(kl + (kt * 64 + r) * 64 + c8);
            *reinterpret_cast<uint4*>(&sVh[r * AROW + c8]) =
                *reinterpret_cast<const uint4*>(vh + r * NSEQ + kt * 64 + c8);
            *reinterpret_cast<uint4*>(&sVl[r * AROW + c8]) =
                *reinterpret_cast<const uint4*>(vl + r * NSEQ + kt * 64 + c8);
        }
        __syncthreads();

        float sf[8][4];
#pragma unroll
        for (int nt = 0; nt < 8; nt++)
#pragma unroll
            for (int j = 0; j < 4; j++) sf[nt][j] = 0.f;
#pragma unroll
        for (int ks = 0; ks < 4; ks++) {
#pragma unroll
            for (int bt = 0; bt < 4; bt++) {
                uint32_t khf[4], klf[4];
                uint32_t off = (uint32_t)((bt * 16 + (lj >> 1) * 8 + lr) * AROW +
                                          ks * 16 + (lj & 1) * 8) * 2;
                LDSM4(khf, aKh + off);
                LDSM4(klf, aKl + off);
#pragma unroll
                for (int hf = 0; hf < 2; hf++) {
                    int nt = bt * 2 + hf;
                    MMA_BF16(sf[nt], qhf[ks], khf[hf * 2], khf[hf * 2 + 1]);
                    MMA_BF16(sf[nt], qhf[ks], klf[hf * 2], klf[hf * 2 + 1]);
                    MMA_BF16(sf[nt], qlf[ks], khf[hf * 2], khf[hf * 2 + 1]);
                }
            }
        }

        float mx1 = -1e30f, mx2 = -1e30f;
#pragma unroll
        for (int nt = 0; nt < 8; nt++) {
            mx1 = fmaxf(mx1, fmaxf(sf[nt][0], sf[nt][1]));
            mx2 = fmaxf(mx2, fmaxf(sf[nt][2], sf[nt][3]));
        }
        mx1 = fmaxf(mx1, __shfl_xor_sync(0xffffffffu, mx1, 1));
        mx1 = fmaxf(mx1, __shfl_xor_sync(0xffffffffu, mx1, 2));
        mx2 = fmaxf(mx2, __shfl_xor_sync(0xffffffffu, mx2, 1));
        mx2 = fmaxf(mx2, __shfl_xor_sync(0xffffffffu, mx2, 2));
        float mn1 = fmaxf(m1, mx1), mn2 = fmaxf(m2, mx2);
        float c1 = fexp(m1 - mn1), c2 = fexp(m2 - mn2);
        float rs1 = 0.f, rs2 = 0.f;
#pragma unroll
        for (int nt = 0; nt < 8; nt++) {
            sf[nt][0] = fexp(sf[nt][0] - mn1);
            sf[nt][1] = fexp(sf[nt][1] - mn1);
            sf[nt][2] = fexp(sf[nt][2] - mn2);
            sf[nt][3] = fexp(sf[nt][3] - mn2);
            rs1 += sf[nt][0] + sf[nt][1];
            rs2 += sf[nt][2] + sf[nt][3];
        }
        rs1 += __shfl_xor_sync(0xffffffffu, rs1, 1);
        rs1 += __shfl_xor_sync(0xffffffffu, rs1, 2);
        rs2 += __shfl_xor_sync(0xffffffffu, rs2, 1);
        rs2 += __shfl_xor_sync(0xffffffffu, rs2, 2);
        l1 = l1 * c1 + rs1; l2 = l2 * c2 + rs2;
        m1 = mn1; m2 = mn2;
#pragma unroll
        for (int nt = 0; nt < 8; nt++) {
            of[nt][0] *= c1; of[nt][1] *= c1;
            of[nt][2] *= c2; of[nt][3] *= c2;
        }

        int r1 = m0 + (lane >> 2), r2 = r1 + 8, cc = (lane & 3) * 2;
#pragma unroll
        for (int nt = 0; nt < 8; nt++) {
            int col = nt * 8 + cc;
            __nv_bfloat16 h0, l0, h1, lo1;
            bsplit(sf[nt][0], h0, l0); bsplit(sf[nt][1], h1, lo1);
            *reinterpret_cast<uint32_t*>(&sPh[r1 * AROW + col]) = pack2(h0, h1);
            *reinterpret_cast<uint32_t*>(&sPl[r1 * AROW + col]) = pack2(l0, lo1);
            bsplit(sf[nt][2], h0, l0); bsplit(sf[nt][3], h1, lo1);
            *reinterpret_cast<uint32_t*>(&sPh[r2 * AROW + col]) = pack2(h0, h1);
            *reinterpret_cast<uint32_t*>(&sPl[r2 * AROW + col]) = pack2(l0, lo1);
        }
        __syncwarp();

#pragma unroll
        for (int ks = 0; ks < 4; ks++) {
            uint32_t phf[4], plf[4];
            uint32_t offp = (uint32_t)((m0 + (lj & 1) * 8 + lr) * AROW +
                                       ks * 16 + (lj >> 1) * 8) * 2;
            LDSM4(phf, aPh + offp);
            LDSM4(plf, aPl + offp);
#pragma unroll
            for (int bt = 0; bt < 4; bt++) {
                uint32_t vhf[4], vlf[4];
                uint32_t offv = (uint32_t)((bt * 16 + (lj >> 1) * 8 + lr) * AROW +
                                           ks * 16 + (lj & 1) * 8) * 2;
                LDSM4(vhf, aVh + offv);
                LDSM4(vlf, aVl + offv);
#pragma unroll
                for (int hf = 0; hf < 2; hf++) {
                    int nt = bt * 2 + hf;
                    MMA_BF16(of[nt], phf, vhf[hf * 2], vhf[hf * 2 + 1]);
                    MMA_BF16(of[nt], phf, vlf[hf * 2], vlf[hf * 2 + 1]);
                    MMA_BF16(of[nt], plf, vhf[hf * 2], vhf[hf * 2 + 1]);
                }
            }
        }
    }

    int b = bh / NHEADS, hh = bh % NHEADS;
    float inv1 = 1.0f / l1, inv2 = 1.0f / l2;
    int r1 = q0 + m0 + (lane >> 2), cc = (lane & 3) * 2;
    size_t row1 = (size_t)(b * NSEQ + r1) * DIMM + hh * DHEAD;
    size_t row2 = (size_t)(b * NSEQ + r1 + 8) * DIMM + hh * DHEAD;
#pragma unroll
    for (int nt = 0; nt < 8; nt++) {
        int col = nt * 8 + cc;
        __nv_bfloat16 h0, l0, h1, lo1;
        bsplit(of[nt][0] * inv1, h0, l0); bsplit(of[nt][1] * inv1, h1, lo1);
        *reinterpret_cast<uint32_t*>(Oh + row1 + col) = pack2(h0, h1);
        *reinterpret_cast<uint32_t*>(Ol + row1 + col) = pack2(l0, lo1);
        bsplit(of[nt][2] * inv2, h0, l0); bsplit(of[nt][3] * inv2, h1, lo1);
        *reinterpret_cast<uint32_t*>(Oh + row2 + col) = pack2(h0, h1);
        *reinterpret_cast<uint32_t*>(Ol + row2 + col) = pack2(l0, lo1);
    }
}

// ====== HMMA GEMM: C = A@B^T (+res, +split out), 3-stage pipeline, BM tiles ===
#define SROW   40
template<int BM>
__global__ void __launch_bounds__(256, (BM == 64 ? 2 : 1)) gemm_mma(
    const __nv_bfloat16* __restrict__ Ah, const __nv_bfloat16* __restrict__ Al,
    const __nv_bfloat16* __restrict__ Bh, const __nv_bfloat16* __restrict__ Bl,
    const float* __restrict__ res, float* __restrict__ C,
    __nv_bfloat16* __restrict__ oh, __nv_bfloat16* __restrict__ ol,
    int N, int K)
{
    constexpr int MI   = BM / 32;
    constexpr int ASZB = BM  * SROW * 2;
    constexpr int BSZB = 128 * SROW * 2;
    constexpr int STGB = 2 * ASZB + 2 * BSZB;

    extern __shared__ __align__(16) __nv_bfloat16 sm[];
    const int tid = threadIdx.x, lane = tid & 31, w = tid >> 5;
    const int wr = w & 1, wc = w >> 1;
    const int bm = blockIdx.y * BM, bn = blockIdx.x * 128;
    const int NK = K >> 5;
    const uint32_t sbase = smem_to_u32(sm);

    const __nv_bfloat16* gAh = Ah + (size_t)bm * K;
    const __nv_bfloat16* gAl = Al + (size_t)bm * K;
    const __nv_bfloat16* gBh = Bh + (size_t)bn * K;
    const __nv_bfloat16* gBl = Bl + (size_t)bn * K;

    float acc[MI][4][4];
#pragma unroll
    for (int a = 0; a < MI; a++)
#pragma unroll
        for (int b = 0; b < 4; b++)
#pragma unroll
            for (int c = 0; c < 4; c++) acc[a][b][c] = 0.f;

    auto issue = [&](int st, int kc) {
        uint32_t sb = sbase + st * STGB;
        int ko = kc * 32;
#pragma unroll
        for (int c = tid; c < BM * 4; c += 256) {
            int r = c >> 2, qq = (c & 3) * 8;
            uint32_t d = (uint32_t)(r * SROW + qq) * 2;
            CPASYNC(sb + d,        gAh + (size_t)r * K + ko + qq);
            CPASYNC(sb + ASZB + d, gAl + (size_t)r * K + ko + qq);
        }
#pragma unroll
        for (int c = tid; c < 512; c += 256) {
            int r = c >> 2, qq = (c & 3) * 8;
            uint32_t d = (uint32_t)(r * SROW + qq) * 2;
            CPASYNC(sb + 2 * ASZB + d,        gBh + (size_t)r * K + ko + qq);
            CPASYNC(sb + 2 * ASZB + BSZB + d, gBl + (size_t)r * K + ko + qq);
        }
    };

    issue(0, 0); CPCOMMIT();
    issue(1, 1); CPCOMMIT();

    const int lj = lane >> 3, lr = lane & 7;

    for (int kc = 0; kc < NK; kc++) {
        if (kc + 2 <= NK) CPWAIT1(); else CPWAIT0();
        __syncthreads();
        if (kc + 2 < NK) { issue((kc + 2) % 3, kc + 2); CPCOMMIT(); }

        uint32_t sb = sbase + (kc % 3) * STGB;
        uint32_t aH = sb, aL = sb + ASZB;
        uint32_t bH = sb + 2 * ASZB, bL = sb + 2 * ASZB + BSZB;

#pragma unroll
        for (int ks = 0; ks < 2; ks++) {
            uint32_t ahf[MI][4], alf[MI][4], bhf[2][4], blf[2][4];
#pragma unroll
            for (int mi = 0; mi < MI; mi++) {
                int mrow = wr * (BM / 2) + mi * 16 + (lj & 1) * 8 + lr;
                int kcol = ks * 16 + (lj >> 1) * 8;
                uint32_t off = (uint32_t)(mrow * SROW + kcol) * 2;
                LDSM4(ahf[mi], aH + off);
                LDSM4(alf[mi], aL + off);
            }
#pragma unroll
            for (int bt = 0; bt < 2; bt++) {
                int nrow = wc * 32 + bt * 16 + (lj >> 1) * 8 + lr;
                int kcol = ks * 16 + (lj & 1) * 8;
                uint32_t off = (uint32_t)(nrow * SROW + kcol) * 2;
                LDSM4(bhf[bt], bH + off);
                LDSM4(blf[bt], bL + off);
            }
#pragma unroll
            for (int mi = 0; mi < MI; mi++)
#pragma unroll
                for (int bt = 0; bt < 2; bt++)
#pragma unroll
                    for (int hf = 0; hf < 2; hf++) {
                        int nt = bt * 2 + hf;
                        MMA_BF16(acc[mi][nt], ahf[mi], bhf[bt][hf * 2], bhf[bt][hf * 2 + 1]);
                        MMA_BF16(acc[mi][nt], ahf[mi], blf[bt][hf * 2], blf[bt][hf * 2 + 1]);
                        MMA_BF16(acc[mi][nt], alf[mi], bhf[bt][hf * 2], bhf[bt][hf * 2 + 1]);
                    }
        }
    }

#pragma unroll
    for (int mi = 0; mi < MI; mi++) {
        int row0 = bm + wr * (BM / 2) + mi * 16 + (lane >> 2);
#pragma unroll
        for (int nt = 0; nt < 4; nt++) {
            int col = bn + wc * 32 + nt * 8 + (lane & 3) * 2;
            size_t i0 = (size_t)row0 * N + col;
            size_t i1 = (size_t)(row0 + 8) * N + col;
            float2 v0 = make_float2(acc[mi][nt][0], acc[mi][nt][1]);
            float2 v1 = make_float2(acc[mi][nt][2], acc[mi][nt][3]);
            if (res) {
                float2 a0 = *reinterpret_cast<const float2*>(res + i0);
                float2 a1 = *reinterpret_cast<const float2*>(res + i1);
                v0.x += a0.x; v0.y += a0.y; v1.x += a1.x; v1.y += a1.y;
            }
            *reinterpret_cast<float2*>(C + i0) = v0;
            *reinterpret_cast<float2*>(C + i1) = v1;
            if (oh) {
                __nv_bfloat16 h0, l0, h1, l1;
                bsplit(v0.x, h0, l0); bsplit(v0.y, h1, l1);
                *reinterpret_cast<uint32_t*>(oh + i0) = pack2(h0, h1);
                *reinterpret_cast<uint32_t*>(ol + i0) = pack2(l0, l1);
                bsplit(v1.x, h0, l0); bsplit(v1.y, h1, l1);
                *reinterpret_cast<uint32_t*>(oh + i1) = pack2(h0, h1);
                *reinterpret_cast<uint32_t*>(ol + i1) = pack2(l0, l1);
            }
        }
    }
}

#define GSMEM128 (3 * (2 * 128 * SROW * 2 + 2 * 128 * SROW * 2))
#define GSMEM64  (3 * (2 * 64  * SROW * 2 + 2 * 128 * SROW * 2))

// ------------------------------ launch ----------------------------------------
extern "C" void kernel_launch(void* const* d_in, const int* in_sizes, int n_in,
                              void* d_out, int out_size)
{
    (void)in_sizes; (void)n_in; (void)out_size;
    const float* x          = (const float*)d_in[0];
    const float* attn_gamma = (const float*)d_in[1];
    const float* wq         = (const float*)d_in[2];
    const float* wkv        = (const float*)d_in[3];
    const float* q_scale    = (const float*)d_in[4];
    const float* k_scale    = (const float*)d_in[5];
    const float* wo         = (const float*)d_in[6];
    const float* ff_gamma   = (const float*)d_in[7];
    const float* ff_beta    = (const float*)d_in[8];
    const float* wff1       = (const float*)d_in[9];
    const float* wff2       = (const float*)d_in[10];
    float* xo = (float*)d_out;

    float *q, *kv, *u;
    __nv_bfloat16 *ah, *al, *xh, *xl, *wth, *wtl, *wth2, *wtl2;
    __nv_bfloat16 *qh, *ql, *kh, *kl, *vh, *vl;
    cudaGetSymbolAddress((void**)&q,    g_q);
    cudaGetSymbolAddress((void**)&kv,   g_kv);
    cudaGetSymbolAddress((void**)&u,    g_u);
    cudaGetSymbolAddress((void**)&ah,   g_ah);
    cudaGetSymbolAddress((void**)&al,   g_al);
    cudaGetSymbolAddress((void**)&xh,   g_xh);
    cudaGetSymbolAddress((void**)&xl,   g_xl);
    cudaGetSymbolAddress((void**)&wth,  g_wth);
    cudaGetSymbolAddress((void**)&wtl,  g_wtl);
    cudaGetSymbolAddress((void**)&wth2, g_wth2);
    cudaGetSymbolAddress((void**)&wtl2, g_wtl2);
    cudaGetSymbolAddress((void**)&qh,   g_qh);
    cudaGetSymbolAddress((void**)&ql,   g_ql);
    cudaGetSymbolAddress((void**)&kh,   g_kh);
    cudaGetSymbolAddress((void**)&kl,   g_kl);
    cudaGetSymbolAddress((void**)&vh,   g_vh);
    cudaGetSymbolAddress((void**)&vl,   g_vl);

    // stream + events created once, on the uncaptured correctness call
    static cudaStream_t s2 = nullptr;
    static cudaEvent_t evs[20];
    if (!s2) {
        cudaStreamCreate(&s2);
        for (int i = 0; i < 20; i++)
            cudaEventCreateWithFlags(&evs[i], cudaEventDisableTiming);
        cudaFuncSetAttribute(gemm_mma<128>,
            cudaFuncAttributeMaxDynamicSharedMemorySize, GSMEM128);
        cudaFuncSetAttribute(gemm_mma<64>,
            cudaFuncAttributeMaxDynamicSharedMemorySize, GSMEM64);
    }

    cudaMemcpyAsync(xo, x, (size_t)MTOK * DIMM * sizeof(float),
                    cudaMemcpyDeviceToDevice);
    split_kernel<<<(MTOK * DIMM) / 256, 256>>>(xo, xh, xl);

    for (int i = 0; i < 4; i++) {
        cudaEvent_t eA = evs[i * 5 + 0], eQ = evs[i * 5 + 1], eS = evs[i * 5 + 2];
        cudaEvent_t eO = evs[i * 5 + 3], eF = evs[i * 5 + 4];

        // d: LN for attention; fork point
        ln_kernel<<<MTOK, 256>>>(xo, attn_gamma + (size_t)i * DIMM, nullptr, ah, al);
        cudaEventRecord(eA, 0);

        // s2: kv chain (uses xh/xl from prev ff2 epilogue / initial split)
        cudaStreamWaitEvent(s2, eA, 0);
        wtrans_kernel<<<dim3(48, 24), 256, 0, s2>>>(
            wkv + (size_t)i * 768 * 1536, wth2, wtl2, 768, 1536);
        gemm_mma<128><<<dim3(12, 32), 256, GSMEM128, s2>>>(
            xh, xl, wth2, wtl2, nullptr, kv, nullptr, nullptr, 1536, 768);
        rope_split_kernel<<<dim3(MTOK, 3), 256, 0, s2>>>(
            kv, 2 * DIMM, k_scale + (size_t)i * DHEAD, 1.0f, kh, kl);
        vtrans_split_kernel<<<dim3(NSEQ / 32, BHTOT), 256, 0, s2>>>(kv, vh, vl);

        // d: q chain
        wtrans_kernel<<<dim3(24, 24), 256>>>(
            wq + (size_t)i * 768 * 768, wth, wtl, 768, 768);
        gemm_mma<64><<<dim3(6, 64), 256, GSMEM64>>>(
            ah, al, wth, wtl, nullptr, q, nullptr, nullptr, 768, 768);
        cudaEventRecord(eQ, 0);
        rope_split_kernel<<<dim3(MTOK, 3), 256>>>(
            q, DIMM, q_scale + (size_t)i * DHEAD, 8.0f, qh, ql);

        // s2: wo transpose (wth free after q GEMM)
        cudaStreamWaitEvent(s2, eQ, 0);
        wtrans_kernel<<<dim3(24, 24), 256, 0, s2>>>(
            wo + (size_t)i * 768 * 768, wth, wtl, 768, 768);
        cudaEventRecord(eS, s2);

        // d: attention + wo GEMM
        cudaStreamWaitEvent(0, eS, 0);
        attn_tc_kernel<<<dim3(NSEQ / 64, BHTOT), 128>>>(
            qh, ql, kh, kl, vh, vl, ah, al);
        gemm_mma<64><<<dim3(6, 64), 256, GSMEM64>>>(
            ah, al, wth, wtl, xo, xo, nullptr, nullptr, 768, 768);
        cudaEventRecord(eO, 0);

        // s2: ff weight transposes under attention/wo
        cudaStreamWaitEvent(s2, eO, 0);
        wtrans_kernel<<<dim3(128, 24), 256, 0, s2>>>(
            wff1 + (size_t)i * 768 * 4096, wth, wtl, 768, 4096);
        wtrans_kernel<<<dim3(24, 64), 256, 0, s2>>>(
            wff2 + (size_t)i * 2048 * 768, wth2, wtl2, 2048, 768);
        cudaEventRecord(eF, s2);

        // d: FF block; ff2 epilogue also emits next-layer xh/xl
        ln_kernel<<<MTOK, 256>>>(xo, ff_gamma + (size_t)i * DIMM,
                                 ff_beta + (size_t)i * DIMM, ah, al);
        cudaStreamWaitEvent(0, eF, 0);
        gemm_mma<128><<<dim3(32, 32), 256, GSMEM128>>>(
            ah, al, wth, wtl, nullptr, u, nullptr, nullptr, 4096, 768);
        gate_kernel<<<(MTOK * FFI) / 256, 256>>>(u, ah, al);
        gemm_mma<64><<<dim3(6, 64), 256, GSMEM64>>>(
            ah, al, wth2, wtl2, xo, xo, xh, xl, 768, 2048);
    }
}

// round 12
// speedup vs baseline: 2.7109x; 1.0240x over previous
#include <cuda_runtime.h>
#include <cuda_bf16.h>
#include <cstdint>
#include <cstddef>

#define DIMM    768
#define MTOK    4096
#define NSEQ    1024
#define NHEADS  12
#define DHEAD   64
#define FFI     2048
#define BHTOT   48

// ---------------- scratch (static device globals; no allocation) -------------
__device__ float g_q [MTOK * DIMM];
__device__ float g_kv[MTOK * 2 * DIMM];
__device__ float g_u [MTOK * 2 * FFI];
__device__ __align__(16) __nv_bfloat16 g_ah [MTOK * FFI];
__device__ __align__(16) __nv_bfloat16 g_al [MTOK * FFI];
__device__ __align__(16) __nv_bfloat16 g_xh [MTOK * DIMM];
__device__ __align__(16) __nv_bfloat16 g_xl [MTOK * DIMM];
__device__ __align__(16) __nv_bfloat16 g_wth [4096 * 768];
__device__ __align__(16) __nv_bfloat16 g_wtl [4096 * 768];
__device__ __align__(16) __nv_bfloat16 g_wth2[768 * 2048];
__device__ __align__(16) __nv_bfloat16 g_wtl2[768 * 2048];
__device__ __align__(16) __nv_bfloat16 g_qh [BHTOT * NSEQ * DHEAD];
__device__ __align__(16) __nv_bfloat16 g_ql [BHTOT * NSEQ * DHEAD];
__device__ __align__(16) __nv_bfloat16 g_kh [BHTOT * NSEQ * DHEAD];
__device__ __align__(16) __nv_bfloat16 g_kl [BHTOT * NSEQ * DHEAD];
__device__ __align__(16) __nv_bfloat16 g_vh [BHTOT * NSEQ * DHEAD]; // [bh][d][n]
__device__ __align__(16) __nv_bfloat16 g_vl [BHTOT * NSEQ * DHEAD];

// =========================== PTX helpers (sm_80-safe) =========================
__device__ __forceinline__ uint32_t smem_to_u32(const void* p) {
    uint32_t a;
    asm("{ .reg .u64 t; cvta.to.shared.u64 t, %1; cvt.u32.u64 %0, t; }"
        : "=r"(a) : "l"(p));
    return a;
}
#define CPASYNC(d, s) \
    asm volatile("cp.async.cg.shared.global [%0], [%1], 16;" :: "r"(d), "l"(s))
#define CPCOMMIT() asm volatile("cp.async.commit_group;" ::: "memory")
#define CPWAIT1()  asm volatile("cp.async.wait_group 1;" ::: "memory")
#define CPWAIT0()  asm volatile("cp.async.wait_group 0;" ::: "memory")
#define LDSM4(r, addr) \
    asm volatile("ldmatrix.sync.aligned.m8n8.x4.shared.b16 {%0,%1,%2,%3}, [%4];" \
        : "=r"((r)[0]), "=r"((r)[1]), "=r"((r)[2]), "=r"((r)[3]) : "r"(addr))
#define MMA_BF16(d, a, b0, b1) \
    asm volatile("mma.sync.aligned.m16n8k16.row.col.f32.bf16.bf16.f32 " \
        "{%0,%1,%2,%3}, {%4,%5,%6,%7}, {%8,%9}, {%0,%1,%2,%3};" \
        : "+f"((d)[0]), "+f"((d)[1]), "+f"((d)[2]), "+f"((d)[3]) \
        : "r"((a)[0]), "r"((a)[1]), "r"((a)[2]), "r"((a)[3]), "r"(b0), "r"(b1))

__device__ __forceinline__ void bsplit(float v, __nv_bfloat16& h, __nv_bfloat16& l) {
    h = __float2bfloat16(v);
    l = __float2bfloat16(v - __bfloat162float(h));
}
__device__ __forceinline__ uint32_t pack2(__nv_bfloat16 a, __nv_bfloat16 b) {
    return (uint32_t)__bfloat16_as_ushort(a) |
           ((uint32_t)__bfloat16_as_ushort(b) << 16);
}
// fast exp for y <= 0 (poly 2^f, magic-number split); rel err ~3e-6
__device__ __forceinline__ float fexp(float y) {
    float t = fmaxf(y * 1.4426950408889634f, -60.0f);
    float z = t + 12582912.0f;
    int   i = __float_as_int(z) - 0x4B400000;
    float f = t - (z - 12582912.0f);
    float p = 1.3333558146e-3f;
    p = fmaf(p, f, 9.6181291076e-3f);
    p = fmaf(p, f, 5.5504108664e-2f);
    p = fmaf(p, f, 2.4022650696e-1f);
    p = fmaf(p, f, 6.9314718056e-1f);
    p = fmaf(p, f, 1.0f);
    return __int_as_float(__float_as_int(p) + (i << 23));
}

// ------------------------- LayerNorm -> split bf16 ---------------------------
__global__ void __launch_bounds__(256) ln_kernel(
    const float* __restrict__ x, const float* __restrict__ gamma,
    const float* __restrict__ beta,
    __nv_bfloat16* __restrict__ oh, __nv_bfloat16* __restrict__ ol)
{
    int row = blockIdx.x, tid = threadIdx.x;
    const float* xr = x + (size_t)row * DIMM;
    float v0 = xr[tid], v1 = xr[tid + 256], v2 = xr[tid + 512];
    float s = v0 + v1 + v2, sq = v0 * v0 + v1 * v1 + v2 * v2;
#pragma unroll
    for (int o = 16; o > 0; o >>= 1) {
        s  += __shfl_xor_sync(0xffffffffu, s, o);
        sq += __shfl_xor_sync(0xffffffffu, sq, o);
    }
    __shared__ float red[16];
    if ((tid & 31) == 0) { red[tid >> 5] = s; red[(tid >> 5) + 8] = sq; }
    __syncthreads();
    float ts = 0.f, tq = 0.f;
#pragma unroll
    for (int i = 0; i < 8; i++) { ts += red[i]; tq += red[i + 8]; }
    float mu  = ts * (1.0f / 768.0f);
    float var = tq * (1.0f / 768.0f) - mu * mu;
    float inv = rsqrtf(var + 1e-5f);
    size_t base = (size_t)row * DIMM;
#pragma unroll
    for (int i = 0; i < 3; i++) {
        int c = tid + i * 256;
        float vv = (i == 0 ? v0 : (i == 1 ? v1 : v2));
        float b = beta ? beta[c] : 0.f;
        float y = (vv - mu) * inv * gamma[c] + b;
        __nv_bfloat16 h, l; bsplit(y, h, l);
        oh[base + c] = h; ol[base + c] = l;
    }
}

// ---------------- weight transpose + split: W[K,N] -> Wt[N,K] hi/lo ----------
__global__ void __launch_bounds__(256) wtrans_kernel(
    const float* __restrict__ W, __nv_bfloat16* __restrict__ th,
    __nv_bfloat16* __restrict__ tl, int Kd, int Nd)
{
    __shared__ float t[32][33];
    int tx = threadIdx.x & 31, ty = threadIdx.x >> 5;
    int n0 = blockIdx.x * 32, k0 = blockIdx.y * 32;
#pragma unroll
    for (int i = 0; i < 4; i++)
        t[ty + i * 8][tx] = W[(size_t)(k0 + ty + i * 8) * Nd + n0 + tx];
    __syncthreads();
#pragma unroll
    for (int i = 0; i < 4; i++) {
        int n = n0 + ty + i * 8;
        float v = t[tx][ty + i * 8];
        __nv_bfloat16 h, l; bsplit(v, h, l);
        th[(size_t)n * Kd + k0 + tx] = h;
        tl[(size_t)n * Kd + k0 + tx] = l;
    }
}

// --------------------------- fp32 -> split bf16 ------------------------------
__global__ void __launch_bounds__(256) split_kernel(
    const float* __restrict__ x, __nv_bfloat16* __restrict__ oh,
    __nv_bfloat16* __restrict__ ol)
{
    int i = blockIdx.x * 256 + threadIdx.x;
    __nv_bfloat16 h, l; bsplit(x[i], h, l);
    oh[i] = h; ol[i] = l;
}

// -------------------------- GELU gate -> split bf16 --------------------------
__global__ void __launch_bounds__(256) gate_kernel(
    const float* __restrict__ u, __nv_bfloat16* __restrict__ oh,
    __nv_bfloat16* __restrict__ ol)
{
    int idx = blockIdx.x * 256 + threadIdx.x;
    int row = idx >> 11, c = idx & 2047;
    float a  = u[(size_t)row * (2 * FFI) + c];
    float xg = u[(size_t)row * (2 * FFI) + FFI + c];
    float ge = 0.5f * xg * (1.0f + erff(xg * 0.7071067811865475f));
    __nv_bfloat16 h, l; bsplit(a * ge, h, l);
    oh[idx] = h; ol[idx] = l;
}

// ------------- RoPE + l2norm + scale (+8x for Q) -> split bf16 ---------------
__global__ void __launch_bounds__(256) rope_split_kernel(
    const float* __restrict__ src, int srcStride,
    const float* __restrict__ scale, float mult,
    __nv_bfloat16* __restrict__ dh, __nv_bfloat16* __restrict__ dl)
{
    int row = blockIdx.x, tid = threadIdx.x;
    int hh = tid >> 6, head = blockIdx.y * 4 + hh, d = tid & 63;
    int n = row & 1023, b = row >> 10;
    float v = src[(size_t)row * srcStride + head * DHEAD + d];
    int j = d >> 1, t = j >> 1;
    float p = (j & 1) ? (float)(n >> 5) : (float)(n & 31);
    float ang = p * exp2f(-0.830482024f * (float)t);
    float c = cosf(ang), s = sinf(ang);
    float other = __shfl_xor_sync(0xffffffffu, v, 1);
    float out = (d & 1) ? (other * s + v * c) : (v * c - other * s);
    float ss = out * out;
#pragma unroll
    for (int o = 16; o > 0; o >>= 1) ss += __shfl_xor_sync(0xffffffffu, ss, o);
    __shared__ float s8[8];
    if ((tid & 31) == 0) s8[tid >> 5] = ss;
    __syncthreads();
    float inv = 1.0f / fmaxf(sqrtf(s8[hh * 2] + s8[hh * 2 + 1]), 1e-12f);
    out = out * inv * scale[d] * mult;
    __nv_bfloat16 h, l; bsplit(out, h, l);
    size_t idx = (((size_t)(b * NHEADS + head)) * NSEQ + n) * DHEAD + d;
    dh[idx] = h; dl[idx] = l;
}

// --------- V transpose + split: kv[.,768+c] -> Vt[bh][d][n] hi/lo -------------
__global__ void __launch_bounds__(256) vtrans_split_kernel(
    const float* __restrict__ kv, __nv_bfloat16* __restrict__ vh,
    __nv_bfloat16* __restrict__ vl)
{
    __shared__ float t[32][65];
    int tid = threadIdx.x, bh = blockIdx.y, n0 = blockIdx.x * 32;
    int b = bh / NHEADS, h = bh % NHEADS;
#pragma unroll
    for (int i = 0; i < 8; i++) {
        int nl = (tid >> 6) + i * 4, d = tid & 63;
        t[nl][d] = kv[(size_t)(b * NSEQ + n0 + nl) * (2 * DIMM) + DIMM + h * DHEAD + d];
    }
    __syncthreads();
#pragma unroll
    for (int i = 0; i < 8; i++) {
        int dd = (tid >> 5) + i * 8, nl = tid & 31;
        float v = t[nl][dd];
        __nv_bfloat16 hi, lo; bsplit(v, hi, lo);
        size_t idx = ((size_t)bh * DHEAD + dd) * NSEQ + n0 + nl;
        vh[idx] = hi; vl[idx] = lo;
    }
}

// ================= tensor-core flash attention (split-3 bf16) =================
#define AROW 72
__global__ void __launch_bounds__(128) attn_tc_kernel(
    const __nv_bfloat16* __restrict__ Qh, const __nv_bfloat16* __restrict__ Ql,
    const __nv_bfloat16* __restrict__ Kh, const __nv_bfloat16* __restrict__ Kl,
    const __nv_bfloat16* __restrict__ Vh, const __nv_bfloat16* __restrict__ Vl,
    __nv_bfloat16* __restrict__ Oh, __nv_bfloat16* __restrict__ Ol)
{
    __shared__ __align__(16) __nv_bfloat16 sKh[64 * AROW], sKl[64 * AROW];
    __shared__ __align__(16) __nv_bfloat16 sVh[64 * AROW], sVl[64 * AROW];
    __shared__ __align__(16) __nv_bfloat16 sPh[64 * AROW], sPl[64 * AROW];

    int tid = threadIdx.x, lane = tid & 31, w = tid >> 5;
    int bh = blockIdx.y, q0 = blockIdx.x * 64;
    const __nv_bfloat16* qh = Qh + ((size_t)bh * NSEQ + q0) * DHEAD;
    const __nv_bfloat16* ql = Ql + ((size_t)bh * NSEQ + q0) * DHEAD;
    const __nv_bfloat16* kh = Kh + (size_t)bh * NSEQ * DHEAD;
    const __nv_bfloat16* kl = Kl + (size_t)bh * NSEQ * DHEAD;
    const __nv_bfloat16* vh = Vh + (size_t)bh * DHEAD * NSEQ;
    const __nv_bfloat16* vl = Vl + (size_t)bh * DHEAD * NSEQ;
    uint32_t aKh = smem_to_u32(sKh), aKl = smem_to_u32(sKl);
    uint32_t aVh = smem_to_u32(sVh), aVl = smem_to_u32(sVl);
    uint32_t aPh = smem_to_u32(sPh), aPl = smem_to_u32(sPl);

#pragma unroll
    for (int i = 0; i < 4; i++) {
        int id = tid + i * 128, r = id >> 3, c8 = (id & 7) * 8;
        *reinterpret_cast<uint4*>(&sPh[r * AROW + c8]) =
            *reinterpret_cast<const uint4*>(qh + r * 64 + c8);
        *reinterpret_cast<uint4*>(&sPl[r * AROW + c8]) =
            *reinterpret_cast<const uint4*>(ql + r * 64 + c8);
    }
    __syncthreads();
    const int lj = lane >> 3, lr = lane & 7, m0 = w * 16;
    uint32_t qhf[4][4], qlf[4][4];
#pragma unroll
    for (int ks = 0; ks < 4; ks++) {
        uint32_t off = (uint32_t)((m0 + (lj & 1) * 8 + lr) * AROW +
                                  ks * 16 + (lj >> 1) * 8) * 2;
        LDSM4(qhf[ks], aPh + off);
        LDSM4(qlf[ks], aPl + off);
    }

    float m1 = -1e30f, m2 = -1e30f, l1 = 0.f, l2 = 0.f;
    float of[8][4];
#pragma unroll
    for (int nt = 0; nt < 8; nt++)
#pragma unroll
        for (int j = 0; j < 4; j++) of[nt][j] = 0.f;

    for (int kt = 0; kt < 16; kt++) {
        __syncthreads();
#pragma unroll
        for (int i = 0; i < 4; i++) {
            int id = tid + i * 128, r = id >> 3, c8 = (id & 7) * 8;
            *reinterpret_cast<uint4*>(&sKh[r * AROW + c8]) =
                *reinterpret_cast<const uint4*>(kh + (kt * 64 + r) * 64 + c8);
            *reinterpret_cast<uint4*>(&sKl[r * AROW + c8]) =
                *reinterpret_cast<const uint4*>(kl + (kt * 64 + r) * 64 + c8);
            *reinterpret_cast<uint4*>(&sVh[r * AROW + c8]) =
                *reinterpret_cast<const uint4*>(vh + r * NSEQ + kt * 64 + c8);
            *reinterpret_cast<uint4*>(&sVl[r * AROW + c8]) =
                *reinterpret_cast<const uint4*>(vl + r * NSEQ + kt * 64 + c8);
        }
        __syncthreads();

        // ---- S = Q K^T (split-3, term-major to break acc chains) ----
        float sf[8][4];
#pragma unroll
        for (int nt = 0; nt < 8; nt++)
#pragma unroll
            for (int j = 0; j < 4; j++) sf[nt][j] = 0.f;
#pragma unroll
        for (int ks = 0; ks < 4; ks++) {
            uint32_t khf[4][4], klf[4][4];
#pragma unroll
            for (int bt = 0; bt < 4; bt++) {
                uint32_t off = (uint32_t)((bt * 16 + (lj >> 1) * 8 + lr) * AROW +
                                          ks * 16 + (lj & 1) * 8) * 2;
                LDSM4(khf[bt], aKh + off);
                LDSM4(klf[bt], aKl + off);
            }
#pragma unroll
            for (int bt = 0; bt < 4; bt++)
#pragma unroll
                for (int hf = 0; hf < 2; hf++)
                    MMA_BF16(sf[bt * 2 + hf], qhf[ks], khf[bt][hf * 2], khf[bt][hf * 2 + 1]);
#pragma unroll
            for (int bt = 0; bt < 4; bt++)
#pragma unroll
                for (int hf = 0; hf < 2; hf++)
                    MMA_BF16(sf[bt * 2 + hf], qhf[ks], klf[bt][hf * 2], klf[bt][hf * 2 + 1]);
#pragma unroll
            for (int bt = 0; bt < 4; bt++)
#pragma unroll
                for (int hf = 0; hf < 2; hf++)
                    MMA_BF16(sf[bt * 2 + hf], qlf[ks], khf[bt][hf * 2], khf[bt][hf * 2 + 1]);
        }

        // ---- online softmax in fragments ----
        float mx1 = -1e30f, mx2 = -1e30f;
#pragma unroll
        for (int nt = 0; nt < 8; nt++) {
            mx1 = fmaxf(mx1, fmaxf(sf[nt][0], sf[nt][1]));
            mx2 = fmaxf(mx2, fmaxf(sf[nt][2], sf[nt][3]));
        }
        mx1 = fmaxf(mx1, __shfl_xor_sync(0xffffffffu, mx1, 1));
        mx1 = fmaxf(mx1, __shfl_xor_sync(0xffffffffu, mx1, 2));
        mx2 = fmaxf(mx2, __shfl_xor_sync(0xffffffffu, mx2, 1));
        mx2 = fmaxf(mx2, __shfl_xor_sync(0xffffffffu, mx2, 2));
        float mn1 = fmaxf(m1, mx1), mn2 = fmaxf(m2, mx2);
        float c1 = fexp(m1 - mn1), c2 = fexp(m2 - mn2);
        float rs1 = 0.f, rs2 = 0.f;
#pragma unroll
        for (int nt = 0; nt < 8; nt++) {
            sf[nt][0] = fexp(sf[nt][0] - mn1);
            sf[nt][1] = fexp(sf[nt][1] - mn1);
            sf[nt][2] = fexp(sf[nt][2] - mn2);
            sf[nt][3] = fexp(sf[nt][3] - mn2);
            rs1 += sf[nt][0] + sf[nt][1];
            rs2 += sf[nt][2] + sf[nt][3];
        }
        rs1 += __shfl_xor_sync(0xffffffffu, rs1, 1);
        rs1 += __shfl_xor_sync(0xffffffffu, rs1, 2);
        rs2 += __shfl_xor_sync(0xffffffffu, rs2, 1);
        rs2 += __shfl_xor_sync(0xffffffffu, rs2, 2);
        l1 = l1 * c1 + rs1; l2 = l2 * c2 + rs2;
        m1 = mn1; m2 = mn2;
#pragma unroll
        for (int nt = 0; nt < 8; nt++) {
            of[nt][0] *= c1; of[nt][1] *= c1;
            of[nt][2] *= c2; of[nt][3] *= c2;
        }

        int r1 = m0 + (lane >> 2), r2 = r1 + 8, cc = (lane & 3) * 2;
#pragma unroll
        for (int nt = 0; nt < 8; nt++) {
            int col = nt * 8 + cc;
            __nv_bfloat16 h0, l0, h1, lo1;
            bsplit(sf[nt][0], h0, l0); bsplit(sf[nt][1], h1, lo1);
            *reinterpret_cast<uint32_t*>(&sPh[r1 * AROW + col]) = pack2(h0, h1);
            *reinterpret_cast<uint32_t*>(&sPl[r1 * AROW + col]) = pack2(l0, lo1);
            bsplit(sf[nt][2], h0, l0); bsplit(sf[nt][3], h1, lo1);
            *reinterpret_cast<uint32_t*>(&sPh[r2 * AROW + col]) = pack2(h0, h1);
            *reinterpret_cast<uint32_t*>(&sPl[r2 * AROW + col]) = pack2(l0, lo1);
        }
        __syncwarp();

        // ---- O += P V (split-3, term-major) ----
#pragma unroll
        for (int ks = 0; ks < 4; ks++) {
            uint32_t phf[4], plf[4], vhf[4][4], vlf[4][4];
            uint32_t offp = (uint32_t)((m0 + (lj & 1) * 8 + lr) * AROW +
                                       ks * 16 + (lj >> 1) * 8) * 2;
            LDSM4(phf, aPh + offp);
            LDSM4(plf, aPl + offp);
#pragma unroll
            for (int bt = 0; bt < 4; bt++) {
                uint32_t offv = (uint32_t)((bt * 16 + (lj >> 1) * 8 + lr) * AROW +
                                           ks * 16 + (lj & 1) * 8) * 2;
                LDSM4(vhf[bt], aVh + offv);
                LDSM4(vlf[bt], aVl + offv);
            }
#pragma unroll
            for (int bt = 0; bt < 4; bt++)
#pragma unroll
                for (int hf = 0; hf < 2; hf++)
                    MMA_BF16(of[bt * 2 + hf], phf, vhf[bt][hf * 2], vhf[bt][hf * 2 + 1]);
#pragma unroll
            for (int bt = 0; bt < 4; bt++)
#pragma unroll
                for (int hf = 0; hf < 2; hf++)
                    MMA_BF16(of[bt * 2 + hf], phf, vlf[bt][hf * 2], vlf[bt][hf * 2 + 1]);
#pragma unroll
            for (int bt = 0; bt < 4; bt++)
#pragma unroll
                for (int hf = 0; hf < 2; hf++)
                    MMA_BF16(of[bt * 2 + hf], plf, vhf[bt][hf * 2], vhf[bt][hf * 2 + 1]);
        }
    }

    int b = bh / NHEADS, hh = bh % NHEADS;
    float inv1 = 1.0f / l1, inv2 = 1.0f / l2;
    int r1 = q0 + m0 + (lane >> 2), cc = (lane & 3) * 2;
    size_t row1 = (size_t)(b * NSEQ + r1) * DIMM + hh * DHEAD;
    size_t row2 = (size_t)(b * NSEQ + r1 + 8) * DIMM + hh * DHEAD;
#pragma unroll
    for (int nt = 0; nt < 8; nt++) {
        int col = nt * 8 + cc;
        __nv_bfloat16 h0, l0, h1, lo1;
        bsplit(of[nt][0] * inv1, h0, l0); bsplit(of[nt][1] * inv1, h1, lo1);
        *reinterpret_cast<uint32_t*>(Oh + row1 + col) = pack2(h0, h1);
        *reinterpret_cast<uint32_t*>(Ol + row1 + col) = pack2(l0, lo1);
        bsplit(of[nt][2] * inv2, h0, l0); bsplit(of[nt][3] * inv2, h1, lo1);
        *reinterpret_cast<uint32_t*>(Oh + row2 + col) = pack2(h0, h1);
        *reinterpret_cast<uint32_t*>(Ol + row2 + col) = pack2(l0, lo1);
    }
}

// ====== HMMA GEMM: C = A@B^T (+res, +split out), 3-stage pipeline, BM tiles ===
#define SROW   40
template<int BM>
__global__ void __launch_bounds__(256, (BM == 64 ? 2 : 1)) gemm_mma(
    const __nv_bfloat16* __restrict__ Ah, const __nv_bfloat16* __restrict__ Al,
    const __nv_bfloat16* __restrict__ Bh, const __nv_bfloat16* __restrict__ Bl,
    const float* __restrict__ res, float* __restrict__ C,
    __nv_bfloat16* __restrict__ oh, __nv_bfloat16* __restrict__ ol,
    int N, int K)
{
    constexpr int MI   = BM / 32;
    constexpr int ASZB = BM  * SROW * 2;
    constexpr int BSZB = 128 * SROW * 2;
    constexpr int STGB = 2 * ASZB + 2 * BSZB;

    extern __shared__ __align__(16) __nv_bfloat16 sm[];
    const int tid = threadIdx.x, lane = tid & 31, w = tid >> 5;
    const int wr = w & 1, wc = w >> 1;
    const int bm = blockIdx.y * BM, bn = blockIdx.x * 128;
    const int NK = K >> 5;
    const uint32_t sbase = smem_to_u32(sm);

    const __nv_bfloat16* gAh = Ah + (size_t)bm * K;
    const __nv_bfloat16* gAl = Al + (size_t)bm * K;
    const __nv_bfloat16* gBh = Bh + (size_t)bn * K;
    const __nv_bfloat16* gBl = Bl + (size_t)bn * K;

    float acc[MI][4][4];
#pragma unroll
    for (int a = 0; a < MI; a++)
#pragma unroll
        for (int b = 0; b < 4; b++)
#pragma unroll
            for (int c = 0; c < 4; c++) acc[a][b][c] = 0.f;

    auto issue = [&](int st, int kc) {
        uint32_t sb = sbase + st * STGB;
        int ko = kc * 32;
#pragma unroll
        for (int c = tid; c < BM * 4; c += 256) {
            int r = c >> 2, qq = (c & 3) * 8;
            uint32_t d = (uint32_t)(r * SROW + qq) * 2;
            CPASYNC(sb + d,        gAh + (size_t)r * K + ko + qq);
            CPASYNC(sb + ASZB + d, gAl + (size_t)r * K + ko + qq);
        }
#pragma unroll
        for (int c = tid; c < 512; c += 256) {
            int r = c >> 2, qq = (c & 3) * 8;
            uint32_t d = (uint32_t)(r * SROW + qq) * 2;
            CPASYNC(sb + 2 * ASZB + d,        gBh + (size_t)r * K + ko + qq);
            CPASYNC(sb + 2 * ASZB + BSZB + d, gBl + (size_t)r * K + ko + qq);
        }
    };

    issue(0, 0); CPCOMMIT();
    issue(1, 1); CPCOMMIT();

    const int lj = lane >> 3, lr = lane & 7;

    for (int kc = 0; kc < NK; kc++) {
        if (kc + 2 <= NK) CPWAIT1(); else CPWAIT0();
        __syncthreads();
        if (kc + 2 < NK) { issue((kc + 2) % 3, kc + 2); CPCOMMIT(); }

        uint32_t sb = sbase + (kc % 3) * STGB;
        uint32_t aH = sb, aL = sb + ASZB;
        uint32_t bH = sb + 2 * ASZB, bL = sb + 2 * ASZB + BSZB;

#pragma unroll
        for (int ks = 0; ks < 2; ks++) {
            uint32_t ahf[MI][4], alf[MI][4], bhf[2][4], blf[2][4];
#pragma unroll
            for (int mi = 0; mi < MI; mi++) {
                int mrow = wr * (BM / 2) + mi * 16 + (lj & 1) * 8 + lr;
                int kcol = ks * 16 + (lj >> 1) * 8;
                uint32_t off = (uint32_t)(mrow * SROW + kcol) * 2;
                LDSM4(ahf[mi], aH + off);
                LDSM4(alf[mi], aL + off);
            }
#pragma unroll
            for (int bt = 0; bt < 2; bt++) {
                int nrow = wc * 32 + bt * 16 + (lj >> 1) * 8 + lr;
                int kcol = ks * 16 + (lj & 1) * 8;
                uint32_t off = (uint32_t)(nrow * SROW + kcol) * 2;
                LDSM4(bhf[bt], bH + off);
                LDSM4(blf[bt], bL + off);
            }
            // term-major: break same-accumulator dependency chains
#pragma unroll
            for (int mi = 0; mi < MI; mi++)
#pragma unroll
                for (int bt = 0; bt < 2; bt++)
#pragma unroll
                    for (int hf = 0; hf < 2; hf++)
                        MMA_BF16(acc[mi][bt * 2 + hf], ahf[mi],
                                 bhf[bt][hf * 2], bhf[bt][hf * 2 + 1]);
#pragma unroll
            for (int mi = 0; mi < MI; mi++)
#pragma unroll
                for (int bt = 0; bt < 2; bt++)
#pragma unroll
                    for (int hf = 0; hf < 2; hf++)
                        MMA_BF16(acc[mi][bt * 2 + hf], ahf[mi],
                                 blf[bt][hf * 2], blf[bt][hf * 2 + 1]);
#pragma unroll
            for (int mi = 0; mi < MI; mi++)
#pragma unroll
                for (int bt = 0; bt < 2; bt++)
#pragma unroll
                    for (int hf = 0; hf < 2; hf++)
                        MMA_BF16(acc[mi][bt * 2 + hf], alf[mi],
                                 bhf[bt][hf * 2], bhf[bt][hf * 2 + 1]);
        }
    }

#pragma unroll
    for (int mi = 0; mi < MI; mi++) {
        int row0 = bm + wr * (BM / 2) + mi * 16 + (lane >> 2);
#pragma unroll
        for (int nt = 0; nt < 4; nt++) {
            int col = bn + wc * 32 + nt * 8 + (lane & 3) * 2;
            size_t i0 = (size_t)row0 * N + col;
            size_t i1 = (size_t)(row0 + 8) * N + col;
            float2 v0 = make_float2(acc[mi][nt][0], acc[mi][nt][1]);
            float2 v1 = make_float2(acc[mi][nt][2], acc[mi][nt][3]);
            if (res) {
                float2 a0 = *reinterpret_cast<const float2*>(res + i0);
                float2 a1 = *reinterpret_cast<const float2*>(res + i1);
                v0.x += a0.x; v0.y += a0.y; v1.x += a1.x; v1.y += a1.y;
            }
            *reinterpret_cast<float2*>(C + i0) = v0;
            *reinterpret_cast<float2*>(C + i1) = v1;
            if (oh) {
                __nv_bfloat16 h0, l0, h1, l1;
                bsplit(v0.x, h0, l0); bsplit(v0.y, h1, l1);
                *reinterpret_cast<uint32_t*>(oh + i0) = pack2(h0, h1);
                *reinterpret_cast<uint32_t*>(ol + i0) = pack2(l0, l1);
                bsplit(v1.x, h0, l0); bsplit(v1.y, h1, l1);
                *reinterpret_cast<uint32_t*>(oh + i1) = pack2(h0, h1);
                *reinterpret_cast<uint32_t*>(ol + i1) = pack2(l0, l1);
            }
        }
    }
}

#define GSMEM128 (3 * (2 * 128 * SROW * 2 + 2 * 128 * SROW * 2))
#define GSMEM64  (3 * (2 * 64  * SROW * 2 + 2 * 128 * SROW * 2))

// ------------------------------ launch ----------------------------------------
extern "C" void kernel_launch(void* const* d_in, const int* in_sizes, int n_in,
                              void* d_out, int out_size)
{
    (void)in_sizes; (void)n_in; (void)out_size;
    const float* x          = (const float*)d_in[0];
    const float* attn_gamma = (const float*)d_in[1];
    const float* wq         = (const float*)d_in[2];
    const float* wkv        = (const float*)d_in[3];
    const float* q_scale    = (const float*)d_in[4];
    const float* k_scale    = (const float*)d_in[5];
    const float* wo         = (const float*)d_in[6];
    const float* ff_gamma   = (const float*)d_in[7];
    const float* ff_beta    = (const float*)d_in[8];
    const float* wff1       = (const float*)d_in[9];
    const float* wff2       = (const float*)d_in[10];
    float* xo = (float*)d_out;

    float *q, *kv, *u;
    __nv_bfloat16 *ah, *al, *xh, *xl, *wth, *wtl, *wth2, *wtl2;
    __nv_bfloat16 *qh, *ql, *kh, *kl, *vh, *vl;
    cudaGetSymbolAddress((void**)&q,    g_q);
    cudaGetSymbolAddress((void**)&kv,   g_kv);
    cudaGetSymbolAddress((void**)&u,    g_u);
    cudaGetSymbolAddress((void**)&ah,   g_ah);
    cudaGetSymbolAddress((void**)&al,   g_al);
    cudaGetSymbolAddress((void**)&xh,   g_xh);
    cudaGetSymbolAddress((void**)&xl,   g_xl);
    cudaGetSymbolAddress((void**)&wth,  g_wth);
    cudaGetSymbolAddress((void**)&wtl,  g_wtl);
    cudaGetSymbolAddress((void**)&wth2, g_wth2);
    cudaGetSymbolAddress((void**)&wtl2, g_wtl2);
    cudaGetSymbolAddress((void**)&qh,   g_qh);
    cudaGetSymbolAddress((void**)&ql,   g_ql);
    cudaGetSymbolAddress((void**)&kh,   g_kh);
    cudaGetSymbolAddress((void**)&kl,   g_kl);
    cudaGetSymbolAddress((void**)&vh,   g_vh);
    cudaGetSymbolAddress((void**)&vl,   g_vl);

    // stream + events created once, on the uncaptured correctness call
    static cudaStream_t s2 = nullptr;
    static cudaEvent_t evs[20];
    if (!s2) {
        cudaStreamCreate(&s2);
        for (int i = 0; i < 20; i++)
            cudaEventCreateWithFlags(&evs[i], cudaEventDisableTiming);
        cudaFuncSetAttribute(gemm_mma<128>,
            cudaFuncAttributeMaxDynamicSharedMemorySize, GSMEM128);
        cudaFuncSetAttribute(gemm_mma<64>,
            cudaFuncAttributeMaxDynamicSharedMemorySize, GSMEM64);
    }

    cudaMemcpyAsync(xo, x, (size_t)MTOK * DIMM * sizeof(float),
                    cudaMemcpyDeviceToDevice);
    split_kernel<<<(MTOK * DIMM) / 256, 256>>>(xo, xh, xl);

    for (int i = 0; i < 4; i++) {
        cudaEvent_t eA = evs[i * 5 + 0], eQ = evs[i * 5 + 1], eS = evs[i * 5 + 2];
        cudaEvent_t eO = evs[i * 5 + 3], eF = evs[i * 5 + 4];

        // d: LN for attention; fork point
        ln_kernel<<<MTOK, 256>>>(xo, attn_gamma + (size_t)i * DIMM, nullptr, ah, al);
        cudaEventRecord(eA, 0);

        // s2: kv chain (uses xh/xl from prev ff2 epilogue / initial split)
        cudaStreamWaitEvent(s2, eA, 0);
        wtrans_kernel<<<dim3(48, 24), 256, 0, s2>>>(
            wkv + (size_t)i * 768 * 1536, wth2, wtl2, 768, 1536);
        gemm_mma<128><<<dim3(12, 32), 256, GSMEM128, s2>>>(
            xh, xl, wth2, wtl2, nullptr, kv, nullptr, nullptr, 1536, 768);
        rope_split_kernel<<<dim3(MTOK, 3), 256, 0, s2>>>(
            kv, 2 * DIMM, k_scale + (size_t)i * DHEAD, 1.0f, kh, kl);
        vtrans_split_kernel<<<dim3(NSEQ / 32, BHTOT), 256, 0, s2>>>(kv, vh, vl);

        // d: q chain
        wtrans_kernel<<<dim3(24, 24), 256>>>(
            wq + (size_t)i * 768 * 768, wth, wtl, 768, 768);
        gemm_mma<64><<<dim3(6, 64), 256, GSMEM64>>>(
            ah, al, wth, wtl, nullptr, q, nullptr, nullptr, 768, 768);
        cudaEventRecord(eQ, 0);
        rope_split_kernel<<<dim3(MTOK, 3), 256>>>(
            q, DIMM, q_scale + (size_t)i * DHEAD, 8.0f, qh, ql);

        // s2: wo transpose (wth free after q GEMM)
        cudaStreamWaitEvent(s2, eQ, 0);
        wtrans_kernel<<<dim3(24, 24), 256, 0, s2>>>(
            wo + (size_t)i * 768 * 768, wth, wtl, 768, 768);
        cudaEventRecord(eS, s2);

        // d: attention + wo GEMM
        cudaStreamWaitEvent(0, eS, 0);
        attn_tc_kernel<<<dim3(NSEQ / 64, BHTOT), 128>>>(
            qh, ql, kh, kl, vh, vl, ah, al);
        gemm_mma<64><<<dim3(6, 64), 256, GSMEM64>>>(
            ah, al, wth, wtl, xo, xo, nullptr, nullptr, 768, 768);
        cudaEventRecord(eO, 0);

        // s2: ff weight transposes under attention/wo
        cudaStreamWaitEvent(s2, eO, 0);
        wtrans_kernel<<<dim3(128, 24), 256, 0, s2>>>(
            wff1 + (size_t)i * 768 * 4096, wth, wtl, 768, 4096);
        wtrans_kernel<<<dim3(24, 64), 256, 0, s2>>>(
            wff2 + (size_t)i * 2048 * 768, wth2, wtl2, 2048, 768);
        cudaEventRecord(eF, s2);

        // d: FF block; ff2 epilogue also emits next-layer xh/xl
        ln_kernel<<<MTOK, 256>>>(xo, ff_gamma + (size_t)i * DIMM,
                                 ff_beta + (size_t)i * DIMM, ah, al);
        cudaStreamWaitEvent(0, eF, 0);
        gemm_mma<128><<<dim3(32, 32), 256, GSMEM128>>>(
            ah, al, wth, wtl, nullptr, u, nullptr, nullptr, 4096, 768);
        gate_kernel<<<(MTOK * FFI) / 256, 256>>>(u, ah, al);
        gemm_mma<64><<<dim3(6, 64), 256, GSMEM64>>>(
            ah, al, wth2, wtl2, xo, xo, xh, xl, 768, 2048);
    }
}

// round 13
// speedup vs baseline: 2.8950x; 1.0679x over previous
#include <cuda_runtime.h>
#include <cuda_bf16.h>
#include <cstdint>
#include <cstddef>

#define DIMM    768
#define MTOK    4096
#define NSEQ    1024
#define NHEADS  12
#define DHEAD   64
#define FFI     2048
#define BHTOT   48

// ---------------- scratch (static device globals; no allocation) -------------
__device__ float g_q [MTOK * DIMM];
__device__ float g_kv[MTOK * 2 * DIMM];
__device__ float g_u [MTOK * 2 * FFI];
__device__ __align__(16) __nv_bfloat16 g_ah [MTOK * FFI];
__device__ __align__(16) __nv_bfloat16 g_al [MTOK * FFI];
__device__ __align__(16) __nv_bfloat16 g_xh [MTOK * DIMM];
__device__ __align__(16) __nv_bfloat16 g_xl [MTOK * DIMM];
__device__ __align__(16) __nv_bfloat16 g_wth [4096 * 768];
__device__ __align__(16) __nv_bfloat16 g_wtl [4096 * 768];
__device__ __align__(16) __nv_bfloat16 g_wth2[768 * 2048];
__device__ __align__(16) __nv_bfloat16 g_wtl2[768 * 2048];
__device__ __align__(16) __nv_bfloat16 g_qh [BHTOT * NSEQ * DHEAD];
__device__ __align__(16) __nv_bfloat16 g_ql [BHTOT * NSEQ * DHEAD];
__device__ __align__(16) __nv_bfloat16 g_kh [BHTOT * NSEQ * DHEAD];
__device__ __align__(16) __nv_bfloat16 g_kl [BHTOT * NSEQ * DHEAD];
__device__ __align__(16) __nv_bfloat16 g_vh [BHTOT * NSEQ * DHEAD]; // [bh][d][n]
__device__ __align__(16) __nv_bfloat16 g_vl [BHTOT * NSEQ * DHEAD];

// =========================== PTX helpers (sm_80-safe) =========================
__device__ __forceinline__ uint32_t smem_to_u32(const void* p) {
    uint32_t a;
    asm("{ .reg .u64 t; cvta.to.shared.u64 t, %1; cvt.u32.u64 %0, t; }"
        : "=r"(a) : "l"(p));
    return a;
}
#define CPASYNC(d, s) \
    asm volatile("cp.async.cg.shared.global [%0], [%1], 16;" :: "r"(d), "l"(s))
#define CPCOMMIT() asm volatile("cp.async.commit_group;" ::: "memory")
#define CPWAIT1()  asm volatile("cp.async.wait_group 1;" ::: "memory")
#define CPWAIT0()  asm volatile("cp.async.wait_group 0;" ::: "memory")
#define LDSM4(r, addr) \
    asm volatile("ldmatrix.sync.aligned.m8n8.x4.shared.b16 {%0,%1,%2,%3}, [%4];" \
        : "=r"((r)[0]), "=r"((r)[1]), "=r"((r)[2]), "=r"((r)[3]) : "r"(addr))
#define MMA_BF16(d, a, b0, b1) \
    asm volatile("mma.sync.aligned.m16n8k16.row.col.f32.bf16.bf16.f32 " \
        "{%0,%1,%2,%3}, {%4,%5,%6,%7}, {%8,%9}, {%0,%1,%2,%3};" \
        : "+f"((d)[0]), "+f"((d)[1]), "+f"((d)[2]), "+f"((d)[3]) \
        : "r"((a)[0]), "r"((a)[1]), "r"((a)[2]), "r"((a)[3]), "r"(b0), "r"(b1))

__device__ __forceinline__ void bsplit(float v, __nv_bfloat16& h, __nv_bfloat16& l) {
    h = __float2bfloat16(v);
    l = __float2bfloat16(v - __bfloat162float(h));
}
__device__ __forceinline__ uint32_t pack2(__nv_bfloat16 a, __nv_bfloat16 b) {
    return (uint32_t)__bfloat16_as_ushort(a) |
           ((uint32_t)__bfloat16_as_ushort(b) << 16);
}
// fast exp for y <= 0 (poly 2^f, magic-number split); rel err ~3e-6
__device__ __forceinline__ float fexp(float y) {
    float t = fmaxf(y * 1.4426950408889634f, -60.0f);
    float z = t + 12582912.0f;
    int   i = __float_as_int(z) - 0x4B400000;
    float f = t - (z - 12582912.0f);
    float p = 1.3333558146e-3f;
    p = fmaf(p, f, 9.6181291076e-3f);
    p = fmaf(p, f, 5.5504108664e-2f);
    p = fmaf(p, f, 2.4022650696e-1f);
    p = fmaf(p, f, 6.9314718056e-1f);
    p = fmaf(p, f, 1.0f);
    return __int_as_float(__float_as_int(p) + (i << 23));
}

// ------------------------- LayerNorm -> split bf16 ---------------------------
__global__ void __launch_bounds__(256) ln_kernel(
    const float* __restrict__ x, const float* __restrict__ gamma,
    const float* __restrict__ beta,
    __nv_bfloat16* __restrict__ oh, __nv_bfloat16* __restrict__ ol)
{
    int row = blockIdx.x, tid = threadIdx.x;
    const float* xr = x + (size_t)row * DIMM;
    float v0 = xr[tid], v1 = xr[tid + 256], v2 = xr[tid + 512];
    float s = v0 + v1 + v2, sq = v0 * v0 + v1 * v1 + v2 * v2;
#pragma unroll
    for (int o = 16; o > 0; o >>= 1) {
        s  += __shfl_xor_sync(0xffffffffu, s, o);
        sq += __shfl_xor_sync(0xffffffffu, sq, o);
    }
    __shared__ float red[16];
    if ((tid & 31) == 0) { red[tid >> 5] = s; red[(tid >> 5) + 8] = sq; }
    __syncthreads();
    float ts = 0.f, tq = 0.f;
#pragma unroll
    for (int i = 0; i < 8; i++) { ts += red[i]; tq += red[i + 8]; }
    float mu  = ts * (1.0f / 768.0f);
    float var = tq * (1.0f / 768.0f) - mu * mu;
    float inv = rsqrtf(var + 1e-5f);
    size_t base = (size_t)row * DIMM;
#pragma unroll
    for (int i = 0; i < 3; i++) {
        int c = tid + i * 256;
        float vv = (i == 0 ? v0 : (i == 1 ? v1 : v2));
        float b = beta ? beta[c] : 0.f;
        float y = (vv - mu) * inv * gamma[c] + b;
        __nv_bfloat16 h, l; bsplit(y, h, l);
        oh[base + c] = h; ol[base + c] = l;
    }
}

// ---------------- weight transpose + split: W[K,N] -> Wt[N,K] hi/lo ----------
__global__ void __launch_bounds__(256) wtrans_kernel(
    const float* __restrict__ W, __nv_bfloat16* __restrict__ th,
    __nv_bfloat16* __restrict__ tl, int Kd, int Nd)
{
    __shared__ float t[32][33];
    int tx = threadIdx.x & 31, ty = threadIdx.x >> 5;
    int n0 = blockIdx.x * 32, k0 = blockIdx.y * 32;
#pragma unroll
    for (int i = 0; i < 4; i++)
        t[ty + i * 8][tx] = W[(size_t)(k0 + ty + i * 8) * Nd + n0 + tx];
    __syncthreads();
#pragma unroll
    for (int i = 0; i < 4; i++) {
        int n = n0 + ty + i * 8;
        float v = t[tx][ty + i * 8];
        __nv_bfloat16 h, l; bsplit(v, h, l);
        th[(size_t)n * Kd + k0 + tx] = h;
        tl[(size_t)n * Kd + k0 + tx] = l;
    }
}

// --------------------------- fp32 -> split bf16 ------------------------------
__global__ void __launch_bounds__(256) split_kernel(
    const float* __restrict__ x, __nv_bfloat16* __restrict__ oh,
    __nv_bfloat16* __restrict__ ol)
{
    int i = blockIdx.x * 256 + threadIdx.x;
    __nv_bfloat16 h, l; bsplit(x[i], h, l);
    oh[i] = h; ol[i] = l;
}

// -------------------------- GELU gate -> split bf16 --------------------------
__global__ void __launch_bounds__(256) gate_kernel(
    const float* __restrict__ u, __nv_bfloat16* __restrict__ oh,
    __nv_bfloat16* __restrict__ ol)
{
    int idx = blockIdx.x * 256 + threadIdx.x;
    int row = idx >> 11, c = idx & 2047;
    float a  = u[(size_t)row * (2 * FFI) + c];
    float xg = u[(size_t)row * (2 * FFI) + FFI + c];
    float ge = 0.5f * xg * (1.0f + erff(xg * 0.7071067811865475f));
    __nv_bfloat16 h, l; bsplit(a * ge, h, l);
    oh[idx] = h; ol[idx] = l;
}

// ------------- RoPE + l2norm + scale (+8x for Q) -> split bf16 ---------------
__global__ void __launch_bounds__(256) rope_split_kernel(
    const float* __restrict__ src, int srcStride,
    const float* __restrict__ scale, float mult,
    __nv_bfloat16* __restrict__ dh, __nv_bfloat16* __restrict__ dl)
{
    int row = blockIdx.x, tid = threadIdx.x;
    int hh = tid >> 6, head = blockIdx.y * 4 + hh, d = tid & 63;
    int n = row & 1023, b = row >> 10;
    float v = src[(size_t)row * srcStride + head * DHEAD + d];
    int j = d >> 1, t = j >> 1;
    float p = (j & 1) ? (float)(n >> 5) : (float)(n & 31);
    float ang = p * exp2f(-0.830482024f * (float)t);
    float c = cosf(ang), s = sinf(ang);
    float other = __shfl_xor_sync(0xffffffffu, v, 1);
    float out = (d & 1) ? (other * s + v * c) : (v * c - other * s);
    float ss = out * out;
#pragma unroll
    for (int o = 16; o > 0; o >>= 1) ss += __shfl_xor_sync(0xffffffffu, ss, o);
    __shared__ float s8[8];
    if ((tid & 31) == 0) s8[tid >> 5] = ss;
    __syncthreads();
    float inv = 1.0f / fmaxf(sqrtf(s8[hh * 2] + s8[hh * 2 + 1]), 1e-12f);
    out = out * inv * scale[d] * mult;
    __nv_bfloat16 h, l; bsplit(out, h, l);
    size_t idx = (((size_t)(b * NHEADS + head)) * NSEQ + n) * DHEAD + d;
    dh[idx] = h; dl[idx] = l;
}

// --------- V transpose + split: kv[.,768+c] -> Vt[bh][d][n] hi/lo -------------
__global__ void __launch_bounds__(256) vtrans_split_kernel(
    const float* __restrict__ kv, __nv_bfloat16* __restrict__ vh,
    __nv_bfloat16* __restrict__ vl)
{
    __shared__ float t[32][65];
    int tid = threadIdx.x, bh = blockIdx.y, n0 = blockIdx.x * 32;
    int b = bh / NHEADS, h = bh % NHEADS;
#pragma unroll
    for (int i = 0; i < 8; i++) {
        int nl = (tid >> 6) + i * 4, d = tid & 63;
        t[nl][d] = kv[(size_t)(b * NSEQ + n0 + nl) * (2 * DIMM) + DIMM + h * DHEAD + d];
    }
    __syncthreads();
#pragma unroll
    for (int i = 0; i < 8; i++) {
        int dd = (tid >> 5) + i * 8, nl = tid & 31;
        float v = t[nl][dd];
        __nv_bfloat16 hi, lo; bsplit(v, hi, lo);
        size_t idx = ((size_t)bh * DHEAD + dd) * NSEQ + n0 + nl;
        vh[idx] = hi; vl[idx] = lo;
    }
}

// ================= tensor-core flash attention (split-3 bf16) =================
#define AROW 72
__global__ void __launch_bounds__(128) attn_tc_kernel(
    const __nv_bfloat16* __restrict__ Qh, const __nv_bfloat16* __restrict__ Ql,
    const __nv_bfloat16* __restrict__ Kh, const __nv_bfloat16* __restrict__ Kl,
    const __nv_bfloat16* __restrict__ Vh, const __nv_bfloat16* __restrict__ Vl,
    __nv_bfloat16* __restrict__ Oh, __nv_bfloat16* __restrict__ Ol)
{
    __shared__ __align__(16) __nv_bfloat16 sKh[64 * AROW], sKl[64 * AROW];
    __shared__ __align__(16) __nv_bfloat16 sVh[64 * AROW], sVl[64 * AROW];
    __shared__ __align__(16) __nv_bfloat16 sPh[64 * AROW], sPl[64 * AROW];

    int tid = threadIdx.x, lane = tid & 31, w = tid >> 5;
    int bh = blockIdx.y, q0 = blockIdx.x * 64;
    const __nv_bfloat16* qh = Qh + ((size_t)bh * NSEQ + q0) * DHEAD;
    const __nv_bfloat16* ql = Ql + ((size_t)bh * NSEQ + q0) * DHEAD;
    const __nv_bfloat16* kh = Kh + (size_t)bh * NSEQ * DHEAD;
    const __nv_bfloat16* kl = Kl + (size_t)bh * NSEQ * DHEAD;
    const __nv_bfloat16* vh = Vh + (size_t)bh * DHEAD * NSEQ;
    const __nv_bfloat16* vl = Vl + (size_t)bh * DHEAD * NSEQ;
    uint32_t aKh = smem_to_u32(sKh), aKl = smem_to_u32(sKl);
    uint32_t aVh = smem_to_u32(sVh), aVl = smem_to_u32(sVl);
    uint32_t aPh = smem_to_u32(sPh), aPl = smem_to_u32(sPl);

#pragma unroll
    for (int i = 0; i < 4; i++) {
        int id = tid + i * 128, r = id >> 3, c8 = (id & 7) * 8;
        *reinterpret_cast<uint4*>(&sPh[r * AROW + c8]) =
            *reinterpret_cast<const uint4*>(qh + r * 64 + c8);
        *reinterpret_cast<uint4*>(&sPl[r * AROW + c8]) =
            *reinterpret_cast<const uint4*>(ql + r * 64 + c8);
    }
    __syncthreads();
    const int lj = lane >> 3, lr = lane & 7, m0 = w * 16;
    uint32_t qhf[4][4], qlf[4][4];
#pragma unroll
    for (int ks = 0; ks < 4; ks++) {
        uint32_t off = (uint32_t)((m0 + (lj & 1) * 8 + lr) * AROW +
                                  ks * 16 + (lj >> 1) * 8) * 2;
        LDSM4(qhf[ks], aPh + off);
        LDSM4(qlf[ks], aPl + off);
    }

    float m1 = -1e30f, m2 = -1e30f, l1 = 0.f, l2 = 0.f;
    float of[8][4];
#pragma unroll
    for (int nt = 0; nt < 8; nt++)
#pragma unroll
        for (int j = 0; j < 4; j++) of[nt][j] = 0.f;

    for (int kt = 0; kt < 16; kt++) {
        __syncthreads();
#pragma unroll
        for (int i = 0; i < 4; i++) {
            int id = tid + i * 128, r = id >> 3, c8 = (id & 7) * 8;
            *reinterpret_cast<uint4*>(&sKh[r * AROW + c8]) =
                *reinterpret_cast<const uint4*>(kh + (kt * 64 + r) * 64 + c8);
            *reinterpret_cast<uint4*>(&sKl[r * AROW + c8]) =
                *reinterpret_cast<const uint4*>(kl + (kt * 64 + r) * 64 + c8);
            *reinterpret_cast<uint4*>(&sVh[r * AROW + c8]) =
                *reinterpret_cast<const uint4*>(vh + r * NSEQ + kt * 64 + c8);
            *reinterpret_cast<uint4*>(&sVl[r * AROW + c8]) =
                *reinterpret_cast<const uint4*>(vl + r * NSEQ + kt * 64 + c8);
        }
        __syncthreads();

        // ---- S = Q K^T (split-3, term-major) ----
        float sf[8][4];
#pragma unroll
        for (int nt = 0; nt < 8; nt++)
#pragma unroll
            for (int j = 0; j < 4; j++) sf[nt][j] = 0.f;
#pragma unroll
        for (int ks = 0; ks < 4; ks++) {
            uint32_t khf[4][4], klf[4][4];
#pragma unroll
            for (int bt = 0; bt < 4; bt++) {
                uint32_t off = (uint32_t)((bt * 16 + (lj >> 1) * 8 + lr) * AROW +
                                          ks * 16 + (lj & 1) * 8) * 2;
                LDSM4(khf[bt], aKh + off);
                LDSM4(klf[bt], aKl + off);
            }
#pragma unroll
            for (int bt = 0; bt < 4; bt++)
#pragma unroll
                for (int hf = 0; hf < 2; hf++)
                    MMA_BF16(sf[bt * 2 + hf], qhf[ks], khf[bt][hf * 2], khf[bt][hf * 2 + 1]);
#pragma unroll
            for (int bt = 0; bt < 4; bt++)
#pragma unroll
                for (int hf = 0; hf < 2; hf++)
                    MMA_BF16(sf[bt * 2 + hf], qhf[ks], klf[bt][hf * 2], klf[bt][hf * 2 + 1]);
#pragma unroll
            for (int bt = 0; bt < 4; bt++)
#pragma unroll
                for (int hf = 0; hf < 2; hf++)
                    MMA_BF16(sf[bt * 2 + hf], qlf[ks], khf[bt][hf * 2], khf[bt][hf * 2 + 1]);
        }

        // ---- online softmax in fragments ----
        float mx1 = -1e30f, mx2 = -1e30f;
#pragma unroll
        for (int nt = 0; nt < 8; nt++) {
            mx1 = fmaxf(mx1, fmaxf(sf[nt][0], sf[nt][1]));
            mx2 = fmaxf(mx2, fmaxf(sf[nt][2], sf[nt][3]));
        }
        mx1 = fmaxf(mx1, __shfl_xor_sync(0xffffffffu, mx1, 1));
        mx1 = fmaxf(mx1, __shfl_xor_sync(0xffffffffu, mx1, 2));
        mx2 = fmaxf(mx2, __shfl_xor_sync(0xffffffffu, mx2, 1));
        mx2 = fmaxf(mx2, __shfl_xor_sync(0xffffffffu, mx2, 2));
        float mn1 = fmaxf(m1, mx1), mn2 = fmaxf(m2, mx2);
        float c1 = fexp(m1 - mn1), c2 = fexp(m2 - mn2);
        float rs1 = 0.f, rs2 = 0.f;
#pragma unroll
        for (int nt = 0; nt < 8; nt++) {
            sf[nt][0] = fexp(sf[nt][0] - mn1);
            sf[nt][1] = fexp(sf[nt][1] - mn1);
            sf[nt][2] = fexp(sf[nt][2] - mn2);
            sf[nt][3] = fexp(sf[nt][3] - mn2);
            rs1 += sf[nt][0] + sf[nt][1];
            rs2 += sf[nt][2] + sf[nt][3];
        }
        rs1 += __shfl_xor_sync(0xffffffffu, rs1, 1);
        rs1 += __shfl_xor_sync(0xffffffffu, rs1, 2);
        rs2 += __shfl_xor_sync(0xffffffffu, rs2, 1);
        rs2 += __shfl_xor_sync(0xffffffffu, rs2, 2);
        l1 = l1 * c1 + rs1; l2 = l2 * c2 + rs2;
        m1 = mn1; m2 = mn2;
#pragma unroll
        for (int nt = 0; nt < 8; nt++) {
            of[nt][0] *= c1; of[nt][1] *= c1;
            of[nt][2] *= c2; of[nt][3] *= c2;
        }

        int r1 = m0 + (lane >> 2), r2 = r1 + 8, cc = (lane & 3) * 2;
#pragma unroll
        for (int nt = 0; nt < 8; nt++) {
            int col = nt * 8 + cc;
            __nv_bfloat16 h0, l0, h1, lo1;
            bsplit(sf[nt][0], h0, l0); bsplit(sf[nt][1], h1, lo1);
            *reinterpret_cast<uint32_t*>(&sPh[r1 * AROW + col]) = pack2(h0, h1);
            *reinterpret_cast<uint32_t*>(&sPl[r1 * AROW + col]) = pack2(l0, lo1);
            bsplit(sf[nt][2], h0, l0); bsplit(sf[nt][3], h1, lo1);
            *reinterpret_cast<uint32_t*>(&sPh[r2 * AROW + col]) = pack2(h0, h1);
            *reinterpret_cast<uint32_t*>(&sPl[r2 * AROW + col]) = pack2(l0, lo1);
        }
        __syncwarp();

        // ---- O += P V (split-3, term-major) ----
#pragma unroll
        for (int ks = 0; ks < 4; ks++) {
            uint32_t phf[4], plf[4], vhf[4][4], vlf[4][4];
            uint32_t offp = (uint32_t)((m0 + (lj & 1) * 8 + lr) * AROW +
                                       ks * 16 + (lj >> 1) * 8) * 2;
            LDSM4(phf, aPh + offp);
            LDSM4(plf, aPl + offp);
#pragma unroll
            for (int bt = 0; bt < 4; bt++) {
                uint32_t offv = (uint32_t)((bt * 16 + (lj >> 1) * 8 + lr) * AROW +
                                           ks * 16 + (lj & 1) * 8) * 2;
                LDSM4(vhf[bt], aVh + offv);
                LDSM4(vlf[bt], aVl + offv);
            }
#pragma unroll
            for (int bt = 0; bt < 4; bt++)
#pragma unroll
                for (int hf = 0; hf < 2; hf++)
                    MMA_BF16(of[bt * 2 + hf], phf, vhf[bt][hf * 2], vhf[bt][hf * 2 + 1]);
#pragma unroll
            for (int bt = 0; bt < 4; bt++)
#pragma unroll
                for (int hf = 0; hf < 2; hf++)
                    MMA_BF16(of[bt * 2 + hf], phf, vlf[bt][hf * 2], vlf[bt][hf * 2 + 1]);
#pragma unroll
            for (int bt = 0; bt < 4; bt++)
#pragma unroll
                for (int hf = 0; hf < 2; hf++)
                    MMA_BF16(of[bt * 2 + hf], plf, vhf[bt][hf * 2], vhf[bt][hf * 2 + 1]);
        }
    }

    int b = bh / NHEADS, hh = bh % NHEADS;
    float inv1 = 1.0f / l1, inv2 = 1.0f / l2;
    int r1 = q0 + m0 + (lane >> 2), cc = (lane & 3) * 2;
    size_t row1 = (size_t)(b * NSEQ + r1) * DIMM + hh * DHEAD;
    size_t row2 = (size_t)(b * NSEQ + r1 + 8) * DIMM + hh * DHEAD;
#pragma unroll
    for (int nt = 0; nt < 8; nt++) {
        int col = nt * 8 + cc;
        __nv_bfloat16 h0, l0, h1, lo1;
        bsplit(of[nt][0] * inv1, h0, l0); bsplit(of[nt][1] * inv1, h1, lo1);
        *reinterpret_cast<uint32_t*>(Oh + row1 + col) = pack2(h0, h1);
        *reinterpret_cast<uint32_t*>(Ol + row1 + col) = pack2(l0, lo1);
        bsplit(of[nt][2] * inv2, h0, l0); bsplit(of[nt][3] * inv2, h1, lo1);
        *reinterpret_cast<uint32_t*>(Oh + row2 + col) = pack2(h0, h1);
        *reinterpret_cast<uint32_t*>(Ol + row2 + col) = pack2(l0, lo1);
    }
}

// ====== HMMA GEMM: C = A@B^T (+res, +split out) ==============================
// BM=128: 2-stage pipeline + 2 CTAs/SM (reg cap 128) — occupancy push.
// BM=64 : 3-stage pipeline, 2 CTAs/SM (fits naturally).
#define SROW   40
template<int BM>
__global__ void __launch_bounds__(256, 2) gemm_mma(
    const __nv_bfloat16* __restrict__ Ah, const __nv_bfloat16* __restrict__ Al,
    const __nv_bfloat16* __restrict__ Bh, const __nv_bfloat16* __restrict__ Bl,
    const float* __restrict__ res, float* __restrict__ C,
    __nv_bfloat16* __restrict__ oh, __nv_bfloat16* __restrict__ ol,
    int N, int K)
{
    constexpr int MI     = BM / 32;
    constexpr int STAGES = (BM == 128 ? 2 : 3);
    constexpr int ASZB   = BM  * SROW * 2;
    constexpr int BSZB   = 128 * SROW * 2;
    constexpr int STGB   = 2 * ASZB + 2 * BSZB;

    extern __shared__ __align__(16) __nv_bfloat16 sm[];
    const int tid = threadIdx.x, lane = tid & 31, w = tid >> 5;
    const int wr = w & 1, wc = w >> 1;
    const int bm = blockIdx.y * BM, bn = blockIdx.x * 128;
    const int NK = K >> 5;
    const uint32_t sbase = smem_to_u32(sm);

    const __nv_bfloat16* gAh = Ah + (size_t)bm * K;
    const __nv_bfloat16* gAl = Al + (size_t)bm * K;
    const __nv_bfloat16* gBh = Bh + (size_t)bn * K;
    const __nv_bfloat16* gBl = Bl + (size_t)bn * K;

    float acc[MI][4][4];
#pragma unroll
    for (int a = 0; a < MI; a++)
#pragma unroll
        for (int b = 0; b < 4; b++)
#pragma unroll
            for (int c = 0; c < 4; c++) acc[a][b][c] = 0.f;

    auto issue = [&](int st, int kc) {
        uint32_t sb = sbase + st * STGB;
        int ko = kc * 32;
#pragma unroll
        for (int c = tid; c < BM * 4; c += 256) {
            int r = c >> 2, qq = (c & 3) * 8;
            uint32_t d = (uint32_t)(r * SROW + qq) * 2;
            CPASYNC(sb + d,        gAh + (size_t)r * K + ko + qq);
            CPASYNC(sb + ASZB + d, gAl + (size_t)r * K + ko + qq);
        }
#pragma unroll
        for (int c = tid; c < 512; c += 256) {
            int r = c >> 2, qq = (c & 3) * 8;
            uint32_t d = (uint32_t)(r * SROW + qq) * 2;
            CPASYNC(sb + 2 * ASZB + d,        gBh + (size_t)r * K + ko + qq);
            CPASYNC(sb + 2 * ASZB + BSZB + d, gBl + (size_t)r * K + ko + qq);
        }
    };

    issue(0, 0); CPCOMMIT();
    issue(1, 1); CPCOMMIT();

    const int lj = lane >> 3, lr = lane & 7;

    for (int kc = 0; kc < NK; kc++) {
        if (kc + 2 <= NK) CPWAIT1(); else CPWAIT0();
        __syncthreads();
        if (STAGES == 3 && kc + 2 < NK) { issue((kc + 2) % 3, kc + 2); CPCOMMIT(); }

        uint32_t sb = sbase + (kc % STAGES) * STGB;
        uint32_t aH = sb, aL = sb + ASZB;
        uint32_t bH = sb + 2 * ASZB, bL = sb + 2 * ASZB + BSZB;

#pragma unroll
        for (int ks = 0; ks < 2; ks++) {
            uint32_t ahf[MI][4], alf[MI][4], bhf[2][4], blf[2][4];
#pragma unroll
            for (int mi = 0; mi < MI; mi++) {
                int mrow = wr * (BM / 2) + mi * 16 + (lj & 1) * 8 + lr;
                int kcol = ks * 16 + (lj >> 1) * 8;
                uint32_t off = (uint32_t)(mrow * SROW + kcol) * 2;
                LDSM4(ahf[mi], aH + off);
                LDSM4(alf[mi], aL + off);
            }
#pragma unroll
            for (int bt = 0; bt < 2; bt++) {
                int nrow = wc * 32 + bt * 16 + (lj >> 1) * 8 + lr;
                int kcol = ks * 16 + (lj & 1) * 8;
                uint32_t off = (uint32_t)(nrow * SROW + kcol) * 2;
                LDSM4(bhf[bt], bH + off);
                LDSM4(blf[bt], bL + off);
            }
#pragma unroll
            for (int mi = 0; mi < MI; mi++)
#pragma unroll
                for (int bt = 0; bt < 2; bt++)
#pragma unroll
                    for (int hf = 0; hf < 2; hf++)
                        MMA_BF16(acc[mi][bt * 2 + hf], ahf[mi],
                                 bhf[bt][hf * 2], bhf[bt][hf * 2 + 1]);
#pragma unroll
            for (int mi = 0; mi < MI; mi++)
#pragma unroll
                for (int bt = 0; bt < 2; bt++)
#pragma unroll
                    for (int hf = 0; hf < 2; hf++)
                        MMA_BF16(acc[mi][bt * 2 + hf], ahf[mi],
                                 blf[bt][hf * 2], blf[bt][hf * 2 + 1]);
#pragma unroll
            for (int mi = 0; mi < MI; mi++)
#pragma unroll
                for (int bt = 0; bt < 2; bt++)
#pragma unroll
                    for (int hf = 0; hf < 2; hf++)
                        MMA_BF16(acc[mi][bt * 2 + hf], alf[mi],
                                 bhf[bt][hf * 2], bhf[bt][hf * 2 + 1]);
        }
        if (STAGES == 2) {
            __syncthreads();
            if (kc + 2 < NK) { issue((kc + 2) & 1, kc + 2); CPCOMMIT(); }
        }
    }

#pragma unroll
    for (int mi = 0; mi < MI; mi++) {
        int row0 = bm + wr * (BM / 2) + mi * 16 + (lane >> 2);
#pragma unroll
        for (int nt = 0; nt < 4; nt++) {
            int col = bn + wc * 32 + nt * 8 + (lane & 3) * 2;
            size_t i0 = (size_t)row0 * N + col;
            size_t i1 = (size_t)(row0 + 8) * N + col;
            float2 v0 = make_float2(acc[mi][nt][0], acc[mi][nt][1]);
            float2 v1 = make_float2(acc[mi][nt][2], acc[mi][nt][3]);
            if (res) {
                float2 a0 = *reinterpret_cast<const float2*>(res + i0);
                float2 a1 = *reinterpret_cast<const float2*>(res + i1);
                v0.x += a0.x; v0.y += a0.y; v1.x += a1.x; v1.y += a1.y;
            }
            *reinterpret_cast<float2*>(C + i0) = v0;
            *reinterpret_cast<float2*>(C + i1) = v1;
            if (oh) {
                __nv_bfloat16 h0, l0, h1, l1;
                bsplit(v0.x, h0, l0); bsplit(v0.y, h1, l1);
                *reinterpret_cast<uint32_t*>(oh + i0) = pack2(h0, h1);
                *reinterpret_cast<uint32_t*>(ol + i0) = pack2(l0, l1);
                bsplit(v1.x, h0, l0); bsplit(v1.y, h1, l1);
                *reinterpret_cast<uint32_t*>(oh + i1) = pack2(h0, h1);
                *reinterpret_cast<uint32_t*>(ol + i1) = pack2(l0, l1);
            }
        }
    }
}

#define GSMEM128 (2 * (2 * 128 * SROW * 2 + 2 * 128 * SROW * 2))
#define GSMEM64  (3 * (2 * 64  * SROW * 2 + 2 * 128 * SROW * 2))

// ------------------------------ launch ----------------------------------------
extern "C" void kernel_launch(void* const* d_in, const int* in_sizes, int n_in,
                              void* d_out, int out_size)
{
    (void)in_sizes; (void)n_in; (void)out_size;
    const float* x          = (const float*)d_in[0];
    const float* attn_gamma = (const float*)d_in[1];
    const float* wq         = (const float*)d_in[2];
    const float* wkv        = (const float*)d_in[3];
    const float* q_scale    = (const float*)d_in[4];
    const float* k_scale    = (const float*)d_in[5];
    const float* wo         = (const float*)d_in[6];
    const float* ff_gamma   = (const float*)d_in[7];
    const float* ff_beta    = (const float*)d_in[8];
    const float* wff1       = (const float*)d_in[9];
    const float* wff2       = (const float*)d_in[10];
    float* xo = (float*)d_out;

    float *q, *kv, *u;
    __nv_bfloat16 *ah, *al, *xh, *xl, *wth, *wtl, *wth2, *wtl2;
    __nv_bfloat16 *qh, *ql, *kh, *kl, *vh, *vl;
    cudaGetSymbolAddress((void**)&q,    g_q);
    cudaGetSymbolAddress((void**)&kv,   g_kv);
    cudaGetSymbolAddress((void**)&u,    g_u);
    cudaGetSymbolAddress((void**)&ah,   g_ah);
    cudaGetSymbolAddress((void**)&al,   g_al);
    cudaGetSymbolAddress((void**)&xh,   g_xh);
    cudaGetSymbolAddress((void**)&xl,   g_xl);
    cudaGetSymbolAddress((void**)&wth,  g_wth);
    cudaGetSymbolAddress((void**)&wtl,  g_wtl);
    cudaGetSymbolAddress((void**)&wth2, g_wth2);
    cudaGetSymbolAddress((void**)&wtl2, g_wtl2);
    cudaGetSymbolAddress((void**)&qh,   g_qh);
    cudaGetSymbolAddress((void**)&ql,   g_ql);
    cudaGetSymbolAddress((void**)&kh,   g_kh);
    cudaGetSymbolAddress((void**)&kl,   g_kl);
    cudaGetSymbolAddress((void**)&vh,   g_vh);
    cudaGetSymbolAddress((void**)&vl,   g_vl);

    // stream + events created once, on the uncaptured correctness call
    static cudaStream_t s2 = nullptr;
    static cudaEvent_t evs[20];
    if (!s2) {
        cudaStreamCreate(&s2);
        for (int i = 0; i < 20; i++)
            cudaEventCreateWithFlags(&evs[i], cudaEventDisableTiming);
        cudaFuncSetAttribute(gemm_mma<128>,
            cudaFuncAttributeMaxDynamicSharedMemorySize, GSMEM128);
        cudaFuncSetAttribute(gemm_mma<64>,
            cudaFuncAttributeMaxDynamicSharedMemorySize, GSMEM64);
    }

    cudaMemcpyAsync(xo, x, (size_t)MTOK * DIMM * sizeof(float),
                    cudaMemcpyDeviceToDevice);
    split_kernel<<<(MTOK * DIMM) / 256, 256>>>(xo, xh, xl);

    for (int i = 0; i < 4; i++) {
        cudaEvent_t eA = evs[i * 5 + 0], eQ = evs[i * 5 + 1], eS = evs[i * 5 + 2];
        cudaEvent_t eO = evs[i * 5 + 3], eF = evs[i * 5 + 4];

        // d: LN for attention; fork point
        ln_kernel<<<MTOK, 256>>>(xo, attn_gamma + (size_t)i * DIMM, nullptr, ah, al);
        cudaEventRecord(eA, 0);

        // s2: kv chain (uses xh/xl from prev ff2 epilogue / initial split)
        cudaStreamWaitEvent(s2, eA, 0);
        wtrans_kernel<<<dim3(48, 24), 256, 0, s2>>>(
            wkv + (size_t)i * 768 * 1536, wth2, wtl2, 768, 1536);
        gemm_mma<128><<<dim3(12, 32), 256, GSMEM128, s2>>>(
            xh, xl, wth2, wtl2, nullptr, kv, nullptr, nullptr, 1536, 768);
        rope_split_kernel<<<dim3(MTOK, 3), 256, 0, s2>>>(
            kv, 2 * DIMM, k_scale + (size_t)i * DHEAD, 1.0f, kh, kl);
        vtrans_split_kernel<<<dim3(NSEQ / 32, BHTOT), 256, 0, s2>>>(kv, vh, vl);

        // d: q chain
        wtrans_kernel<<<dim3(24, 24), 256>>>(
            wq + (size_t)i * 768 * 768, wth, wtl, 768, 768);
        gemm_mma<64><<<dim3(6, 64), 256, GSMEM64>>>(
            ah, al, wth, wtl, nullptr, q, nullptr, nullptr, 768, 768);
        cudaEventRecord(eQ, 0);
        rope_split_kernel<<<dim3(MTOK, 3), 256>>>(
            q, DIMM, q_scale + (size_t)i * DHEAD, 8.0f, qh, ql);

        // s2: wo transpose (wth free after q GEMM)
        cudaStreamWaitEvent(s2, eQ, 0);
        wtrans_kernel<<<dim3(24, 24), 256, 0, s2>>>(
            wo + (size_t)i * 768 * 768, wth, wtl, 768, 768);
        cudaEventRecord(eS, s2);

        // d: attention + wo GEMM
        cudaStreamWaitEvent(0, eS, 0);
        attn_tc_kernel<<<dim3(NSEQ / 64, BHTOT), 128>>>(
            qh, ql, kh, kl, vh, vl, ah, al);
        gemm_mma<64><<<dim3(6, 64), 256, GSMEM64>>>(
            ah, al, wth, wtl, xo, xo, nullptr, nullptr, 768, 768);
        cudaEventRecord(eO, 0);

        // s2: ff weight transposes under attention/wo
        cudaStreamWaitEvent(s2, eO, 0);
        wtrans_kernel<<<dim3(128, 24), 256, 0, s2>>>(
            wff1 + (size_t)i * 768 * 4096, wth, wtl, 768, 4096);
        wtrans_kernel<<<dim3(24, 64), 256, 0, s2>>>(
            wff2 + (size_t)i * 2048 * 768, wth2, wtl2, 2048, 768);
        cudaEventRecord(eF, s2);

        // d: FF block; ff2 epilogue also emits next-layer xh/xl
        ln_kernel<<<MTOK, 256>>>(xo, ff_gamma + (size_t)i * DIMM,
                                 ff_beta + (size_t)i * DIMM, ah, al);
        cudaStreamWaitEvent(0, eF, 0);
        gemm_mma<128><<<dim3(32, 32), 256, GSMEM128>>>(
            ah, al, wth, wtl, nullptr, u, nullptr, nullptr, 4096, 768);
        gate_kernel<<<(MTOK * FFI) / 256, 256>>>(u, ah, al);
        gemm_mma<64><<<dim3(6, 64), 256, GSMEM64>>>(
            ah, al, wth2, wtl2, xo, xo, xh, xl, 768, 2048);
    }
}

// round 14
// speedup vs baseline: 3.2157x; 1.1108x over previous
#include <cuda_runtime.h>
#include <cuda_bf16.h>
#include <cstdint>
#include <cstddef>

#define DIMM    768
#define MTOK    4096
#define NSEQ    1024
#define NHEADS  12
#define DHEAD   64
#define FFI     2048
#define BHTOT   48

// ---------------- scratch (static device globals; no allocation) -------------
__device__ float g_q [MTOK * DIMM];
__device__ float g_kv[MTOK * 2 * DIMM];
__device__ float g_u [MTOK * 2 * FFI];
__device__ __align__(16) __nv_bfloat16 g_ah [MTOK * FFI];
__device__ __align__(16) __nv_bfloat16 g_al [MTOK * FFI];
__device__ __align__(16) __nv_bfloat16 g_xh [MTOK * DIMM];
__device__ __align__(16) __nv_bfloat16 g_xl [MTOK * DIMM];
__device__ __align__(16) __nv_bfloat16 g_wth [4096 * 768];
__device__ __align__(16) __nv_bfloat16 g_wtl [4096 * 768];
__device__ __align__(16) __nv_bfloat16 g_wth2[768 * 2048];
__device__ __align__(16) __nv_bfloat16 g_wtl2[768 * 2048];
__device__ __align__(16) __nv_bfloat16 g_qh [BHTOT * NSEQ * DHEAD];
__device__ __align__(16) __nv_bfloat16 g_ql [BHTOT * NSEQ * DHEAD];
__device__ __align__(16) __nv_bfloat16 g_kh [BHTOT * NSEQ * DHEAD];
__device__ __align__(16) __nv_bfloat16 g_kl [BHTOT * NSEQ * DHEAD];
__device__ __align__(16) __nv_bfloat16 g_vh [BHTOT * NSEQ * DHEAD]; // [bh][d][n]
__device__ __align__(16) __nv_bfloat16 g_vl [BHTOT * NSEQ * DHEAD];

// =========================== PTX helpers (sm_80-safe) =========================
__device__ __forceinline__ uint32_t smem_to_u32(const void* p) {
    uint32_t a;
    asm("{ .reg .u64 t; cvta.to.shared.u64 t, %1; cvt.u32.u64 %0, t; }"
        : "=r"(a) : "l"(p));
    return a;
}
#define CPASYNC(d, s) \
    asm volatile("cp.async.cg.shared.global [%0], [%1], 16;" :: "r"(d), "l"(s))
#define CPCOMMIT() asm volatile("cp.async.commit_group;" ::: "memory")
#define CPWAIT2()  asm volatile("cp.async.wait_group 2;" ::: "memory")
#define CPWAIT1()  asm volatile("cp.async.wait_group 1;" ::: "memory")
#define CPWAIT0()  asm volatile("cp.async.wait_group 0;" ::: "memory")
#define LDSM4(r, addr) \
    asm volatile("ldmatrix.sync.aligned.m8n8.x4.shared.b16 {%0,%1,%2,%3}, [%4];" \
        : "=r"((r)[0]), "=r"((r)[1]), "=r"((r)[2]), "=r"((r)[3]) : "r"(addr))
#define MMA_BF16(d, a, b0, b1) \
    asm volatile("mma.sync.aligned.m16n8k16.row.col.f32.bf16.bf16.f32 " \
        "{%0,%1,%2,%3}, {%4,%5,%6,%7}, {%8,%9}, {%0,%1,%2,%3};" \
        : "+f"((d)[0]), "+f"((d)[1]), "+f"((d)[2]), "+f"((d)[3]) \
        : "r"((a)[0]), "r"((a)[1]), "r"((a)[2]), "r"((a)[3]), "r"(b0), "r"(b1))

__device__ __forceinline__ void bsplit(float v, __nv_bfloat16& h, __nv_bfloat16& l) {
    h = __float2bfloat16(v);
    l = __float2bfloat16(v - __bfloat162float(h));
}
__device__ __forceinline__ uint32_t pack2(__nv_bfloat16 a, __nv_bfloat16 b) {
    return (uint32_t)__bfloat16_as_ushort(a) |
           ((uint32_t)__bfloat16_as_ushort(b) << 16);
}
// fast exp for y <= 0 (poly 2^f, magic-number split); rel err ~3e-6
__device__ __forceinline__ float fexp(float y) {
    float t = fmaxf(y * 1.4426950408889634f, -60.0f);
    float z = t + 12582912.0f;
    int   i = __float_as_int(z) - 0x4B400000;
    float f = t - (z - 12582912.0f);
    float p = 1.3333558146e-3f;
    p = fmaf(p, f, 9.6181291076e-3f);
    p = fmaf(p, f, 5.5504108664e-2f);
    p = fmaf(p, f, 2.4022650696e-1f);
    p = fmaf(p, f, 6.9314718056e-1f);
    p = fmaf(p, f, 1.0f);
    return __int_as_float(__float_as_int(p) + (i << 23));
}

// ------------------------- LayerNorm -> split bf16 ---------------------------
__global__ void __launch_bounds__(256) ln_kernel(
    const float* __restrict__ x, const float* __restrict__ gamma,
    const float* __restrict__ beta,
    __nv_bfloat16* __restrict__ oh, __nv_bfloat16* __restrict__ ol)
{
    int row = blockIdx.x, tid = threadIdx.x;
    const float* xr = x + (size_t)row * DIMM;
    float v0 = xr[tid], v1 = xr[tid + 256], v2 = xr[tid + 512];
    float s = v0 + v1 + v2, sq = v0 * v0 + v1 * v1 + v2 * v2;
#pragma unroll
    for (int o = 16; o > 0; o >>= 1) {
        s  += __shfl_xor_sync(0xffffffffu, s, o);
        sq += __shfl_xor_sync(0xffffffffu, sq, o);
    }
    __shared__ float red[16];
    if ((tid & 31) == 0) { red[tid >> 5] = s; red[(tid >> 5) + 8] = sq; }
    __syncthreads();
    float ts = 0.f, tq = 0.f;
#pragma unroll
    for (int i = 0; i < 8; i++) { ts += red[i]; tq += red[i + 8]; }
    float mu  = ts * (1.0f / 768.0f);
    float var = tq * (1.0f / 768.0f) - mu * mu;
    float inv = rsqrtf(var + 1e-5f);
    size_t base = (size_t)row * DIMM;
#pragma unroll
    for (int i = 0; i < 3; i++) {
        int c = tid + i * 256;
        float vv = (i == 0 ? v0 : (i == 1 ? v1 : v2));
        float b = beta ? beta[c] : 0.f;
        float y = (vv - mu) * inv * gamma[c] + b;
        __nv_bfloat16 h, l; bsplit(y, h, l);
        oh[base + c] = h; ol[base + c] = l;
    }
}

// ---------------- weight transpose + split: W[K,N] -> Wt[N,K] hi/lo ----------
__global__ void __launch_bounds__(256) wtrans_kernel(
    const float* __restrict__ W, __nv_bfloat16* __restrict__ th,
    __nv_bfloat16* __restrict__ tl, int Kd, int Nd)
{
    __shared__ float t[32][33];
    int tx = threadIdx.x & 31, ty = threadIdx.x >> 5;
    int n0 = blockIdx.x * 32, k0 = blockIdx.y * 32;
#pragma unroll
    for (int i = 0; i < 4; i++)
        t[ty + i * 8][tx] = W[(size_t)(k0 + ty + i * 8) * Nd + n0 + tx];
    __syncthreads();
#pragma unroll
    for (int i = 0; i < 4; i++) {
        int n = n0 + ty + i * 8;
        float v = t[tx][ty + i * 8];
        __nv_bfloat16 h, l; bsplit(v, h, l);
        th[(size_t)n * Kd + k0 + tx] = h;
        tl[(size_t)n * Kd + k0 + tx] = l;
    }
}

// --------------------------- fp32 -> split bf16 ------------------------------
__global__ void __launch_bounds__(256) split_kernel(
    const float* __restrict__ x, __nv_bfloat16* __restrict__ oh,
    __nv_bfloat16* __restrict__ ol)
{
    int i = blockIdx.x * 256 + threadIdx.x;
    __nv_bfloat16 h, l; bsplit(x[i], h, l);
    oh[i] = h; ol[i] = l;
}

// -------------------------- GELU gate -> split bf16 --------------------------
__global__ void __launch_bounds__(256) gate_kernel(
    const float* __restrict__ u, __nv_bfloat16* __restrict__ oh,
    __nv_bfloat16* __restrict__ ol)
{
    int idx = blockIdx.x * 256 + threadIdx.x;
    int row = idx >> 11, c = idx & 2047;
    float a  = u[(size_t)row * (2 * FFI) + c];
    float xg = u[(size_t)row * (2 * FFI) + FFI + c];
    float ge = 0.5f * xg * (1.0f + erff(xg * 0.7071067811865475f));
    __nv_bfloat16 h, l; bsplit(a * ge, h, l);
    oh[idx] = h; ol[idx] = l;
}

// ------------- RoPE + l2norm + scale (+8x for Q) -> split bf16 ---------------
__global__ void __launch_bounds__(256) rope_split_kernel(
    const float* __restrict__ src, int srcStride,
    const float* __restrict__ scale, float mult,
    __nv_bfloat16* __restrict__ dh, __nv_bfloat16* __restrict__ dl)
{
    int row = blockIdx.x, tid = threadIdx.x;
    int hh = tid >> 6, head = blockIdx.y * 4 + hh, d = tid & 63;
    int n = row & 1023, b = row >> 10;
    float v = src[(size_t)row * srcStride + head * DHEAD + d];
    int j = d >> 1, t = j >> 1;
    float p = (j & 1) ? (float)(n >> 5) : (float)(n & 31);
    float ang = p * exp2f(-0.830482024f * (float)t);
    float c = cosf(ang), s = sinf(ang);
    float other = __shfl_xor_sync(0xffffffffu, v, 1);
    float out = (d & 1) ? (other * s + v * c) : (v * c - other * s);
    float ss = out * out;
#pragma unroll
    for (int o = 16; o > 0; o >>= 1) ss += __shfl_xor_sync(0xffffffffu, ss, o);
    __shared__ float s8[8];
    if ((tid & 31) == 0) s8[tid >> 5] = ss;
    __syncthreads();
    float inv = 1.0f / fmaxf(sqrtf(s8[hh * 2] + s8[hh * 2 + 1]), 1e-12f);
    out = out * inv * scale[d] * mult;
    __nv_bfloat16 h, l; bsplit(out, h, l);
    size_t idx = (((size_t)(b * NHEADS + head)) * NSEQ + n) * DHEAD + d;
    dh[idx] = h; dl[idx] = l;
}

// --------- V transpose + split: kv[.,768+c] -> Vt[bh][d][n] hi/lo -------------
__global__ void __launch_bounds__(256) vtrans_split_kernel(
    const float* __restrict__ kv, __nv_bfloat16* __restrict__ vh,
    __nv_bfloat16* __restrict__ vl)
{
    __shared__ float t[32][65];
    int tid = threadIdx.x, bh = blockIdx.y, n0 = blockIdx.x * 32;
    int b = bh / NHEADS, h = bh % NHEADS;
#pragma unroll
    for (int i = 0; i < 8; i++) {
        int nl = (tid >> 6) + i * 4, d = tid & 63;
        t[nl][d] = kv[(size_t)(b * NSEQ + n0 + nl) * (2 * DIMM) + DIMM + h * DHEAD + d];
    }
    __syncthreads();
#pragma unroll
    for (int i = 0; i < 8; i++) {
        int dd = (tid >> 5) + i * 8, nl = tid & 31;
        float v = t[nl][dd];
        __nv_bfloat16 hi, lo; bsplit(v, hi, lo);
        size_t idx = ((size_t)bh * DHEAD + dd) * NSEQ + n0 + nl;
        vh[idx] = hi; vl[idx] = lo;
    }
}

// ================= tensor-core flash attention (split-3 bf16) =================
#define AROW 72
__global__ void __launch_bounds__(128) attn_tc_kernel(
    const __nv_bfloat16* __restrict__ Qh, const __nv_bfloat16* __restrict__ Ql,
    const __nv_bfloat16* __restrict__ Kh, const __nv_bfloat16* __restrict__ Kl,
    const __nv_bfloat16* __restrict__ Vh, const __nv_bfloat16* __restrict__ Vl,
    __nv_bfloat16* __restrict__ Oh, __nv_bfloat16* __restrict__ Ol)
{
    __shared__ __align__(16) __nv_bfloat16 sKh[64 * AROW], sKl[64 * AROW];
    __shared__ __align__(16) __nv_bfloat16 sVh[64 * AROW], sVl[64 * AROW];
    __shared__ __align__(16) __nv_bfloat16 sPh[64 * AROW], sPl[64 * AROW];

    int tid = threadIdx.x, lane = tid & 31, w = tid >> 5;
    int bh = blockIdx.y, q0 = blockIdx.x * 64;
    const __nv_bfloat16* qh = Qh + ((size_t)bh * NSEQ + q0) * DHEAD;
    const __nv_bfloat16* ql = Ql + ((size_t)bh * NSEQ + q0) * DHEAD;
    const __nv_bfloat16* kh = Kh + (size_t)bh * NSEQ * DHEAD;
    const __nv_bfloat16* kl = Kl + (size_t)bh * NSEQ * DHEAD;
    const __nv_bfloat16* vh = Vh + (size_t)bh * DHEAD * NSEQ;
    const __nv_bfloat16* vl = Vl + (size_t)bh * DHEAD * NSEQ;
    uint32_t aKh = smem_to_u32(sKh), aKl = smem_to_u32(sKl);
    uint32_t aVh = smem_to_u32(sVh), aVl = smem_to_u32(sVl);
    uint32_t aPh = smem_to_u32(sPh), aPl = smem_to_u32(sPl);

#pragma unroll
    for (int i = 0; i < 4; i++) {
        int id = tid + i * 128, r = id >> 3, c8 = (id & 7) * 8;
        *reinterpret_cast<uint4*>(&sPh[r * AROW + c8]) =
            *reinterpret_cast<const uint4*>(qh + r * 64 + c8);
        *reinterpret_cast<uint4*>(&sPl[r * AROW + c8]) =
            *reinterpret_cast<const uint4*>(ql + r * 64 + c8);
    }
    __syncthreads();
    const int lj = lane >> 3, lr = lane & 7, m0 = w * 16;
    uint32_t qhf[4][4], qlf[4][4];
#pragma unroll
    for (int ks = 0; ks < 4; ks++) {
        uint32_t off = (uint32_t)((m0 + (lj & 1) * 8 + lr) * AROW +
                                  ks * 16 + (lj >> 1) * 8) * 2;
        LDSM4(qhf[ks], aPh + off);
        LDSM4(qlf[ks], aPl + off);
    }

    float m1 = -1e30f, m2 = -1e30f, l1 = 0.f, l2 = 0.f;
    float of[8][4];
#pragma unroll
    for (int nt = 0; nt < 8; nt++)
#pragma unroll
        for (int j = 0; j < 4; j++) of[nt][j] = 0.f;

    for (int kt = 0; kt < 16; kt++) {
        __syncthreads();
#pragma unroll
        for (int i = 0; i < 4; i++) {
            int id = tid + i * 128, r = id >> 3, c8 = (id & 7) * 8;
            *reinterpret_cast<uint4*>(&sKh[r * AROW + c8]) =
                *reinterpret_cast<const uint4*>(kh + (kt * 64 + r) * 64 + c8);
            *reinterpret_cast<uint4*>(&sKl[r * AROW + c8]) =
                *reinterpret_cast<const uint4*>(kl + (kt * 64 + r) * 64 + c8);
            *reinterpret_cast<uint4*>(&sVh[r * AROW + c8]) =
                *reinterpret_cast<const uint4*>(vh + r * NSEQ + kt * 64 + c8);
            *reinterpret_cast<uint4*>(&sVl[r * AROW + c8]) =
                *reinterpret_cast<const uint4*>(vl + r * NSEQ + kt * 64 + c8);
        }
        __syncthreads();

        // ---- S = Q K^T (split-3, term-major) ----
        float sf[8][4];
#pragma unroll
        for (int nt = 0; nt < 8; nt++)
#pragma unroll
            for (int j = 0; j < 4; j++) sf[nt][j] = 0.f;
#pragma unroll
        for (int ks = 0; ks < 4; ks++) {
            uint32_t khf[4][4], klf[4][4];
#pragma unroll
            for (int bt = 0; bt < 4; bt++) {
                uint32_t off = (uint32_t)((bt * 16 + (lj >> 1) * 8 + lr) * AROW +
                                          ks * 16 + (lj & 1) * 8) * 2;
                LDSM4(khf[bt], aKh + off);
                LDSM4(klf[bt], aKl + off);
            }
#pragma unroll
            for (int bt = 0; bt < 4; bt++)
#pragma unroll
                for (int hf = 0; hf < 2; hf++)
                    MMA_BF16(sf[bt * 2 + hf], qhf[ks], khf[bt][hf * 2], khf[bt][hf * 2 + 1]);
#pragma unroll
            for (int bt = 0; bt < 4; bt++)
#pragma unroll
                for (int hf = 0; hf < 2; hf++)
                    MMA_BF16(sf[bt * 2 + hf], qhf[ks], klf[bt][hf * 2], klf[bt][hf * 2 + 1]);
#pragma unroll
            for (int bt = 0; bt < 4; bt++)
#pragma unroll
                for (int hf = 0; hf < 2; hf++)
                    MMA_BF16(sf[bt * 2 + hf], qlf[ks], khf[bt][hf * 2], khf[bt][hf * 2 + 1]);
        }

        // ---- online softmax in fragments ----
        float mx1 = -1e30f, mx2 = -1e30f;
#pragma unroll
        for (int nt = 0; nt < 8; nt++) {
            mx1 = fmaxf(mx1, fmaxf(sf[nt][0], sf[nt][1]));
            mx2 = fmaxf(mx2, fmaxf(sf[nt][2], sf[nt][3]));
        }
        mx1 = fmaxf(mx1, __shfl_xor_sync(0xffffffffu, mx1, 1));
        mx1 = fmaxf(mx1, __shfl_xor_sync(0xffffffffu, mx1, 2));
        mx2 = fmaxf(mx2, __shfl_xor_sync(0xffffffffu, mx2, 1));
        mx2 = fmaxf(mx2, __shfl_xor_sync(0xffffffffu, mx2, 2));
        float mn1 = fmaxf(m1, mx1), mn2 = fmaxf(m2, mx2);
        float c1 = fexp(m1 - mn1), c2 = fexp(m2 - mn2);
        float rs1 = 0.f, rs2 = 0.f;
#pragma unroll
        for (int nt = 0; nt < 8; nt++) {
            sf[nt][0] = fexp(sf[nt][0] - mn1);
            sf[nt][1] = fexp(sf[nt][1] - mn1);
            sf[nt][2] = fexp(sf[nt][2] - mn2);
            sf[nt][3] = fexp(sf[nt][3] - mn2);
            rs1 += sf[nt][0] + sf[nt][1];
            rs2 += sf[nt][2] + sf[nt][3];
        }
        rs1 += __shfl_xor_sync(0xffffffffu, rs1, 1);
        rs1 += __shfl_xor_sync(0xffffffffu, rs1, 2);
        rs2 += __shfl_xor_sync(0xffffffffu, rs2, 1);
        rs2 += __shfl_xor_sync(0xffffffffu, rs2, 2);
        l1 = l1 * c1 + rs1; l2 = l2 * c2 + rs2;
        m1 = mn1; m2 = mn2;
#pragma unroll
        for (int nt = 0; nt < 8; nt++) {
            of[nt][0] *= c1; of[nt][1] *= c1;
            of[nt][2] *= c2; of[nt][3] *= c2;
        }

        int r1 = m0 + (lane >> 2), r2 = r1 + 8, cc = (lane & 3) * 2;
#pragma unroll
        for (int nt = 0; nt < 8; nt++) {
            int col = nt * 8 + cc;
            __nv_bfloat16 h0, l0, h1, lo1;
            bsplit(sf[nt][0], h0, l0); bsplit(sf[nt][1], h1, lo1);
            *reinterpret_cast<uint32_t*>(&sPh[r1 * AROW + col]) = pack2(h0, h1);
            *reinterpret_cast<uint32_t*>(&sPl[r1 * AROW + col]) = pack2(l0, lo1);
            bsplit(sf[nt][2], h0, l0); bsplit(sf[nt][3], h1, lo1);
            *reinterpret_cast<uint32_t*>(&sPh[r2 * AROW + col]) = pack2(h0, h1);
            *reinterpret_cast<uint32_t*>(&sPl[r2 * AROW + col]) = pack2(l0, lo1);
        }
        __syncwarp();

        // ---- O += P V (split-3, term-major) ----
#pragma unroll
        for (int ks = 0; ks < 4; ks++) {
            uint32_t phf[4], plf[4], vhf[4][4], vlf[4][4];
            uint32_t offp = (uint32_t)((m0 + (lj & 1) * 8 + lr) * AROW +
                                       ks * 16 + (lj >> 1) * 8) * 2;
            LDSM4(phf, aPh + offp);
            LDSM4(plf, aPl + offp);
#pragma unroll
            for (int bt = 0; bt < 4; bt++) {
                uint32_t offv = (uint32_t)((bt * 16 + (lj >> 1) * 8 + lr) * AROW +
                                           ks * 16 + (lj & 1) * 8) * 2;
                LDSM4(vhf[bt], aVh + offv);
                LDSM4(vlf[bt], aVl + offv);
            }
#pragma unroll
            for (int bt = 0; bt < 4; bt++)
#pragma unroll
                for (int hf = 0; hf < 2; hf++)
                    MMA_BF16(of[bt * 2 + hf], phf, vhf[bt][hf * 2], vhf[bt][hf * 2 + 1]);
#pragma unroll
            for (int bt = 0; bt < 4; bt++)
#pragma unroll
                for (int hf = 0; hf < 2; hf++)
                    MMA_BF16(of[bt * 2 + hf], phf, vlf[bt][hf * 2], vlf[bt][hf * 2 + 1]);
#pragma unroll
            for (int bt = 0; bt < 4; bt++)
#pragma unroll
                for (int hf = 0; hf < 2; hf++)
                    MMA_BF16(of[bt * 2 + hf], plf, vhf[bt][hf * 2], vhf[bt][hf * 2 + 1]);
        }
    }

    int b = bh / NHEADS, hh = bh % NHEADS;
    float inv1 = 1.0f / l1, inv2 = 1.0f / l2;
    int r1 = q0 + m0 + (lane >> 2), cc = (lane & 3) * 2;
    size_t row1 = (size_t)(b * NSEQ + r1) * DIMM + hh * DHEAD;
    size_t row2 = (size_t)(b * NSEQ + r1 + 8) * DIMM + hh * DHEAD;
#pragma unroll
    for (int nt = 0; nt < 8; nt++) {
        int col = nt * 8 + cc;
        __nv_bfloat16 h0, l0, h1, lo1;
        bsplit(of[nt][0] * inv1, h0, l0); bsplit(of[nt][1] * inv1, h1, lo1);
        *reinterpret_cast<uint32_t*>(Oh + row1 + col) = pack2(h0, h1);
        *reinterpret_cast<uint32_t*>(Ol + row1 + col) = pack2(l0, lo1);
        bsplit(of[nt][2] * inv2, h0, l0); bsplit(of[nt][3] * inv2, h1, lo1);
        *reinterpret_cast<uint32_t*>(Oh + row2 + col) = pack2(h0, h1);
        *reinterpret_cast<uint32_t*>(Ol + row2 + col) = pack2(l0, lo1);
    }
}

// ====== HMMA GEMM: C = A@B^T (+res, +split out), XOR-swizzled smem ============
// Rows of 32 bf16 (64 B); 16B-unit u swizzled as u ^ ((row>>1)&3) —
// conflict-free for both cp.async 16B stores and ldmatrix reads.
// BM=128: 3 stages; BM=64: 4 stages. Both 2 CTAs/SM (96 KB smem, 128-reg cap).
#define SWZ(row, u) ((uint32_t)((row) * 64 + ((((u) ^ (((row) >> 1) & 3))) << 4)))

template<int BM>
__global__ void __launch_bounds__(256, 2) gemm_mma(
    const __nv_bfloat16* __restrict__ Ah, const __nv_bfloat16* __restrict__ Al,
    const __nv_bfloat16* __restrict__ Bh, const __nv_bfloat16* __restrict__ Bl,
    const float* __restrict__ res, float* __restrict__ C,
    __nv_bfloat16* __restrict__ oh, __nv_bfloat16* __restrict__ ol,
    int N, int K)
{
    constexpr int MI     = BM / 32;
    constexpr int STAGES = (BM == 128 ? 3 : 4);
    constexpr int ASZB   = BM  * 64;
    constexpr int BSZB   = 128 * 64;
    constexpr int STGB   = 2 * ASZB + 2 * BSZB;

    extern __shared__ __align__(16) __nv_bfloat16 sm[];
    const int tid = threadIdx.x, lane = tid & 31, w = tid >> 5;
    const int wr = w & 1, wc = w >> 1;
    const int bm = blockIdx.y * BM, bn = blockIdx.x * 128;
    const int NK = K >> 5;
    const uint32_t sbase = smem_to_u32(sm);

    const __nv_bfloat16* gAh = Ah + (size_t)bm * K;
    const __nv_bfloat16* gAl = Al + (size_t)bm * K;
    const __nv_bfloat16* gBh = Bh + (size_t)bn * K;
    const __nv_bfloat16* gBl = Bl + (size_t)bn * K;

    float acc[MI][4][4];
#pragma unroll
    for (int a = 0; a < MI; a++)
#pragma unroll
        for (int b = 0; b < 4; b++)
#pragma unroll
            for (int c = 0; c < 4; c++) acc[a][b][c] = 0.f;

    auto issue = [&](int st, int kc) {
        uint32_t sb = sbase + st * STGB;
        int ko = kc * 32;
#pragma unroll
        for (int c = tid; c < BM * 4; c += 256) {
            int r = c >> 2, u = c & 3;
            uint32_t d = SWZ(r, u);
            CPASYNC(sb + d,        gAh + (size_t)r * K + ko + u * 8);
            CPASYNC(sb + ASZB + d, gAl + (size_t)r * K + ko + u * 8);
        }
#pragma unroll
        for (int c = tid; c < 512; c += 256) {
            int r = c >> 2, u = c & 3;
            uint32_t d = SWZ(r, u);
            CPASYNC(sb + 2 * ASZB + d,        gBh + (size_t)r * K + ko + u * 8);
            CPASYNC(sb + 2 * ASZB + BSZB + d, gBl + (size_t)r * K + ko + u * 8);
        }
    };

#pragma unroll
    for (int s = 0; s < STAGES - 1; s++) { issue(s, s); CPCOMMIT(); }

    const int lj = lane >> 3, lr = lane & 7;

    for (int kc = 0; kc < NK; kc++) {
        int rem = NK - 1 - kc;
        if (rem >= STAGES - 2) {
            if (STAGES == 4) CPWAIT2(); else CPWAIT1();
        } else if (rem == 1) CPWAIT1();
        else CPWAIT0();
        __syncthreads();
        if (kc + STAGES - 1 < NK) { issue((kc + STAGES - 1) % STAGES, kc + STAGES - 1); CPCOMMIT(); }

        uint32_t sb = sbase + (kc % STAGES) * STGB;
        uint32_t aH = sb, aL = sb + ASZB;
        uint32_t bH = sb + 2 * ASZB, bL = sb + 2 * ASZB + BSZB;

#pragma unroll
        for (int ks = 0; ks < 2; ks++) {
            uint32_t ahf[MI][4], alf[MI][4], bhf[2][4], blf[2][4];
#pragma unroll
            for (int mi = 0; mi < MI; mi++) {
                int mrow = wr * (BM / 2) + mi * 16 + (lj & 1) * 8 + lr;
                int u = ks * 2 + (lj >> 1);
                uint32_t off = SWZ(mrow, u);
                LDSM4(ahf[mi], aH + off);
                LDSM4(alf[mi], aL + off);
            }
#pragma unroll
            for (int bt = 0; bt < 2; bt++) {
                int nrow = wc * 32 + bt * 16 + (lj >> 1) * 8 + lr;
                int u = ks * 2 + (lj & 1);
                uint32_t off = SWZ(nrow, u);
                LDSM4(bhf[bt], bH + off);
                LDSM4(blf[bt], bL + off);
            }
#pragma unroll
            for (int mi = 0; mi < MI; mi++)
#pragma unroll
                for (int bt = 0; bt < 2; bt++)
#pragma unroll
                    for (int hf = 0; hf < 2; hf++)
                        MMA_BF16(acc[mi][bt * 2 + hf], ahf[mi],
                                 bhf[bt][hf * 2], bhf[bt][hf * 2 + 1]);
#pragma unroll
            for (int mi = 0; mi < MI; mi++)
#pragma unroll
                for (int bt = 0; bt < 2; bt++)
#pragma unroll
                    for (int hf = 0; hf < 2; hf++)
                        MMA_BF16(acc[mi][bt * 2 + hf], ahf[mi],
                                 blf[bt][hf * 2], blf[bt][hf * 2 + 1]);
#pragma unroll
            for (int mi = 0; mi < MI; mi++)
#pragma unroll
                for (int bt = 0; bt < 2; bt++)
#pragma unroll
                    for (int hf = 0; hf < 2; hf++)
                        MMA_BF16(acc[mi][bt * 2 + hf], alf[mi],
                                 bhf[bt][hf * 2], bhf[bt][hf * 2 + 1]);
        }
    }

#pragma unroll
    for (int mi = 0; mi < MI; mi++) {
        int row0 = bm + wr * (BM / 2) + mi * 16 + (lane >> 2);
#pragma unroll
        for (int nt = 0; nt < 4; nt++) {
            int col = bn + wc * 32 + nt * 8 + (lane & 3) * 2;
            size_t i0 = (size_t)row0 * N + col;
            size_t i1 = (size_t)(row0 + 8) * N + col;
            float2 v0 = make_float2(acc[mi][nt][0], acc[mi][nt][1]);
            float2 v1 = make_float2(acc[mi][nt][2], acc[mi][nt][3]);
            if (res) {
                float2 a0 = *reinterpret_cast<const float2*>(res + i0);
                float2 a1 = *reinterpret_cast<const float2*>(res + i1);
                v0.x += a0.x; v0.y += a0.y; v1.x += a1.x; v1.y += a1.y;
            }
            *reinterpret_cast<float2*>(C + i0) = v0;
            *reinterpret_cast<float2*>(C + i1) = v1;
            if (oh) {
                __nv_bfloat16 h0, l0, h1, l1;
                bsplit(v0.x, h0, l0); bsplit(v0.y, h1, l1);
                *reinterpret_cast<uint32_t*>(oh + i0) = pack2(h0, h1);
                *reinterpret_cast<uint32_t*>(ol + i0) = pack2(l0, l1);
                bsplit(v1.x, h0, l0); bsplit(v1.y, h1, l1);
                *reinterpret_cast<uint32_t*>(oh + i1) = pack2(h0, h1);
                *reinterpret_cast<uint32_t*>(ol + i1) = pack2(l0, l1);
            }
        }
    }
}

#define GSMEM128 (3 * (2 * 128 * 64 + 2 * 128 * 64))
#define GSMEM64  (4 * (2 * 64 * 64 + 2 * 128 * 64))

// ------------------------------ launch ----------------------------------------
extern "C" void kernel_launch(void* const* d_in, const int* in_sizes, int n_in,
                              void* d_out, int out_size)
{
    (void)in_sizes; (void)n_in; (void)out_size;
    const float* x          = (const float*)d_in[0];
    const float* attn_gamma = (const float*)d_in[1];
    const float* wq         = (const float*)d_in[2];
    const float* wkv        = (const float*)d_in[3];
    const float* q_scale    = (const float*)d_in[4];
    const float* k_scale    = (const float*)d_in[5];
    const float* wo         = (const float*)d_in[6];
    const float* ff_gamma   = (const float*)d_in[7];
    const float* ff_beta    = (const float*)d_in[8];
    const float* wff1       = (const float*)d_in[9];
    const float* wff2       = (const float*)d_in[10];
    float* xo = (float*)d_out;

    float *q, *kv, *u;
    __nv_bfloat16 *ah, *al, *xh, *xl, *wth, *wtl, *wth2, *wtl2;
    __nv_bfloat16 *qh, *ql, *kh, *kl, *vh, *vl;
    cudaGetSymbolAddress((void**)&q,    g_q);
    cudaGetSymbolAddress((void**)&kv,   g_kv);
    cudaGetSymbolAddress((void**)&u,    g_u);
    cudaGetSymbolAddress((void**)&ah,   g_ah);
    cudaGetSymbolAddress((void**)&al,   g_al);
    cudaGetSymbolAddress((void**)&xh,   g_xh);
    cudaGetSymbolAddress((void**)&xl,   g_xl);
    cudaGetSymbolAddress((void**)&wth,  g_wth);
    cudaGetSymbolAddress((void**)&wtl,  g_wtl);
    cudaGetSymbolAddress((void**)&wth2, g_wth2);
    cudaGetSymbolAddress((void**)&wtl2, g_wtl2);
    cudaGetSymbolAddress((void**)&qh,   g_qh);
    cudaGetSymbolAddress((void**)&ql,   g_ql);
    cudaGetSymbolAddress((void**)&kh,   g_kh);
    cudaGetSymbolAddress((void**)&kl,   g_kl);
    cudaGetSymbolAddress((void**)&vh,   g_vh);
    cudaGetSymbolAddress((void**)&vl,   g_vl);

    // stream + events created once, on the uncaptured correctness call
    static cudaStream_t s2 = nullptr;
    static cudaEvent_t evs[20];
    if (!s2) {
        cudaStreamCreate(&s2);
        for (int i = 0; i < 20; i++)
            cudaEventCreateWithFlags(&evs[i], cudaEventDisableTiming);
        cudaFuncSetAttribute(gemm_mma<128>,
            cudaFuncAttributeMaxDynamicSharedMemorySize, GSMEM128);
        cudaFuncSetAttribute(gemm_mma<64>,
            cudaFuncAttributeMaxDynamicSharedMemorySize, GSMEM64);
    }

    cudaMemcpyAsync(xo, x, (size_t)MTOK * DIMM * sizeof(float),
                    cudaMemcpyDeviceToDevice);
    split_kernel<<<(MTOK * DIMM) / 256, 256>>>(xo, xh, xl);

    for (int i = 0; i < 4; i++) {
        cudaEvent_t eA = evs[i * 5 + 0], eQ = evs[i * 5 + 1], eS = evs[i * 5 + 2];
        cudaEvent_t eO = evs[i * 5 + 3], eF = evs[i * 5 + 4];

        // d: LN for attention; fork point
        ln_kernel<<<MTOK, 256>>>(xo, attn_gamma + (size_t)i * DIMM, nullptr, ah, al);
        cudaEventRecord(eA, 0);

        // s2: kv chain (uses xh/xl from prev ff2 epilogue / initial split)
        cudaStreamWaitEvent(s2, eA, 0);
        wtrans_kernel<<<dim3(48, 24), 256, 0, s2>>>(
            wkv + (size_t)i * 768 * 1536, wth2, wtl2, 768, 1536);
        gemm_mma<128><<<dim3(12, 32), 256, GSMEM128, s2>>>(
            xh, xl, wth2, wtl2, nullptr, kv, nullptr, nullptr, 1536, 768);
        rope_split_kernel<<<dim3(MTOK, 3), 256, 0, s2>>>(
            kv, 2 * DIMM, k_scale + (size_t)i * DHEAD, 1.0f, kh, kl);
        vtrans_split_kernel<<<dim3(NSEQ / 32, BHTOT), 256, 0, s2>>>(kv, vh, vl);

        // d: q chain
        wtrans_kernel<<<dim3(24, 24), 256>>>(
            wq + (size_t)i * 768 * 768, wth, wtl, 768, 768);
        gemm_mma<64><<<dim3(6, 64), 256, GSMEM64>>>(
            ah, al, wth, wtl, nullptr, q, nullptr, nullptr, 768, 768);
        cudaEventRecord(eQ, 0);
        rope_split_kernel<<<dim3(MTOK, 3), 256>>>(
            q, DIMM, q_scale + (size_t)i * DHEAD, 8.0f, qh, ql);

        // s2: wo transpose (wth free after q GEMM)
        cudaStreamWaitEvent(s2, eQ, 0);
        wtrans_kernel<<<dim3(24, 24), 256, 0, s2>>>(
            wo + (size_t)i * 768 * 768, wth, wtl, 768, 768);
        cudaEventRecord(eS, s2);

        // d: attention + wo GEMM
        cudaStreamWaitEvent(0, eS, 0);
        attn_tc_kernel<<<dim3(NSEQ / 64, BHTOT), 128>>>(
            qh, ql, kh, kl, vh, vl, ah, al);
        gemm_mma<64><<<dim3(6, 64), 256, GSMEM64>>>(
            ah, al, wth, wtl, xo, xo, nullptr, nullptr, 768, 768);
        cudaEventRecord(eO, 0);

        // s2: ff weight transposes under attention/wo
        cudaStreamWaitEvent(s2, eO, 0);
        wtrans_kernel<<<dim3(128, 24), 256, 0, s2>>>(
            wff1 + (size_t)i * 768 * 4096, wth, wtl, 768, 4096);
        wtrans_kernel<<<dim3(24, 64), 256, 0, s2>>>(
            wff2 + (size_t)i * 2048 * 768, wth2, wtl2, 2048, 768);
        cudaEventRecord(eF, s2);

        // d: FF block; ff2 epilogue also emits next-layer xh/xl
        ln_kernel<<<MTOK, 256>>>(xo, ff_gamma + (size_t)i * DIMM,
                                 ff_beta + (size_t)i * DIMM, ah, al);
        cudaStreamWaitEvent(0, eF, 0);
        gemm_mma<128><<<dim3(32, 32), 256, GSMEM128>>>(
            ah, al, wth, wtl, nullptr, u, nullptr, nullptr, 4096, 768);
        gate_kernel<<<(MTOK * FFI) / 256, 256>>>(u, ah, al);
        gemm_mma<64><<<dim3(6, 64), 256, GSMEM64>>>(
            ah, al, wth2, wtl2, xo, xo, xh, xl, 768, 2048);
    }
}

// round 15
// speedup vs baseline: 3.2870x; 1.0222x over previous
#include <cuda_runtime.h>
#include <cuda_bf16.h>
#include <cstdint>
#include <cstddef>

#define DIMM    768
#define MTOK    4096
#define NSEQ    1024
#define NHEADS  12
#define DHEAD   64
#define FFI     2048
#define BHTOT   48

// ---------------- scratch (static device globals; no allocation) -------------
__device__ float g_q [MTOK * DIMM];
__device__ float g_kv[MTOK * 2 * DIMM];
__device__ __align__(16) float g_u [MTOK * 2 * FFI];   // reused as bf16 gh/gl
__device__ __align__(16) __nv_bfloat16 g_ah [MTOK * FFI];
__device__ __align__(16) __nv_bfloat16 g_al [MTOK * FFI];
__device__ __align__(16) __nv_bfloat16 g_xh [MTOK * DIMM];
__device__ __align__(16) __nv_bfloat16 g_xl [MTOK * DIMM];
__device__ __align__(16) __nv_bfloat16 g_wth [4096 * 768];
__device__ __align__(16) __nv_bfloat16 g_wtl [4096 * 768];
__device__ __align__(16) __nv_bfloat16 g_wth2[768 * 2048];
__device__ __align__(16) __nv_bfloat16 g_wtl2[768 * 2048];
__device__ __align__(16) __nv_bfloat16 g_qh [BHTOT * NSEQ * DHEAD];
__device__ __align__(16) __nv_bfloat16 g_ql [BHTOT * NSEQ * DHEAD];
__device__ __align__(16) __nv_bfloat16 g_kh [BHTOT * NSEQ * DHEAD];
__device__ __align__(16) __nv_bfloat16 g_kl [BHTOT * NSEQ * DHEAD];
__device__ __align__(16) __nv_bfloat16 g_vh [BHTOT * NSEQ * DHEAD]; // [bh][d][n]
__device__ __align__(16) __nv_bfloat16 g_vl [BHTOT * NSEQ * DHEAD];

// =========================== PTX helpers (sm_80-safe) =========================
__device__ __forceinline__ uint32_t smem_to_u32(const void* p) {
    uint32_t a;
    asm("{ .reg .u64 t; cvta.to.shared.u64 t, %1; cvt.u32.u64 %0, t; }"
        : "=r"(a) : "l"(p));
    return a;
}
#define CPASYNC(d, s) \
    asm volatile("cp.async.cg.shared.global [%0], [%1], 16;" :: "r"(d), "l"(s))
#define CPCOMMIT() asm volatile("cp.async.commit_group;" ::: "memory")
#define CPWAIT2()  asm volatile("cp.async.wait_group 2;" ::: "memory")
#define CPWAIT1()  asm volatile("cp.async.wait_group 1;" ::: "memory")
#define CPWAIT0()  asm volatile("cp.async.wait_group 0;" ::: "memory")
#define LDSM4(r, addr) \
    asm volatile("ldmatrix.sync.aligned.m8n8.x4.shared.b16 {%0,%1,%2,%3}, [%4];" \
        : "=r"((r)[0]), "=r"((r)[1]), "=r"((r)[2]), "=r"((r)[3]) : "r"(addr))
#define MMA_BF16(d, a, b0, b1) \
    asm volatile("mma.sync.aligned.m16n8k16.row.col.f32.bf16.bf16.f32 " \
        "{%0,%1,%2,%3}, {%4,%5,%6,%7}, {%8,%9}, {%0,%1,%2,%3};" \
        : "+f"((d)[0]), "+f"((d)[1]), "+f"((d)[2]), "+f"((d)[3]) \
        : "r"((a)[0]), "r"((a)[1]), "r"((a)[2]), "r"((a)[3]), "r"(b0), "r"(b1))

__device__ __forceinline__ void bsplit(float v, __nv_bfloat16& h, __nv_bfloat16& l) {
    h = __float2bfloat16(v);
    l = __float2bfloat16(v - __bfloat162float(h));
}
__device__ __forceinline__ uint32_t pack2(__nv_bfloat16 a, __nv_bfloat16 b) {
    return (uint32_t)__bfloat16_as_ushort(a) |
           ((uint32_t)__bfloat16_as_ushort(b) << 16);
}
// fast exp for y <= 0 (poly 2^f, magic-number split); rel err ~3e-6
__device__ __forceinline__ float fexp(float y) {
    float t = fmaxf(y * 1.4426950408889634f, -60.0f);
    float z = t + 12582912.0f;
    int   i = __float_as_int(z) - 0x4B400000;
    float f = t - (z - 12582912.0f);
    float p = 1.3333558146e-3f;
    p = fmaf(p, f, 9.6181291076e-3f);
    p = fmaf(p, f, 5.5504108664e-2f);
    p = fmaf(p, f, 2.4022650696e-1f);
    p = fmaf(p, f, 6.9314718056e-1f);
    p = fmaf(p, f, 1.0f);
    return __int_as_float(__float_as_int(p) + (i << 23));
}

// ------------------------- LayerNorm -> split bf16 ---------------------------
__global__ void __launch_bounds__(256) ln_kernel(
    const float* __restrict__ x, const float* __restrict__ gamma,
    const float* __restrict__ beta,
    __nv_bfloat16* __restrict__ oh, __nv_bfloat16* __restrict__ ol)
{
    int row = blockIdx.x, tid = threadIdx.x;
    const float* xr = x + (size_t)row * DIMM;
    float v0 = xr[tid], v1 = xr[tid + 256], v2 = xr[tid + 512];
    float s = v0 + v1 + v2, sq = v0 * v0 + v1 * v1 + v2 * v2;
#pragma unroll
    for (int o = 16; o > 0; o >>= 1) {
        s  += __shfl_xor_sync(0xffffffffu, s, o);
        sq += __shfl_xor_sync(0xffffffffu, sq, o);
    }
    __shared__ float red[16];
    if ((tid & 31) == 0) { red[tid >> 5] = s; red[(tid >> 5) + 8] = sq; }
    __syncthreads();
    float ts = 0.f, tq = 0.f;
#pragma unroll
    for (int i = 0; i < 8; i++) { ts += red[i]; tq += red[i + 8]; }
    float mu  = ts * (1.0f / 768.0f);
    float var = tq * (1.0f / 768.0f) - mu * mu;
    float inv = rsqrtf(var + 1e-5f);
    size_t base = (size_t)row * DIMM;
#pragma unroll
    for (int i = 0; i < 3; i++) {
        int c = tid + i * 256;
        float vv = (i == 0 ? v0 : (i == 1 ? v1 : v2));
        float b = beta ? beta[c] : 0.f;
        float y = (vv - mu) * inv * gamma[c] + b;
        __nv_bfloat16 h, l; bsplit(y, h, l);
        oh[base + c] = h; ol[base + c] = l;
    }
}

// ---------------- weight transpose + split: W[K,N] -> Wt[N,K] hi/lo ----------
// ilv=1: interleave output rows n' = (n < Nd/2) ? 2n : 2(n-Nd/2)+1  (a/g pairs)
__global__ void __launch_bounds__(256) wtrans_kernel(
    const float* __restrict__ W, __nv_bfloat16* __restrict__ th,
    __nv_bfloat16* __restrict__ tl, int Kd, int Nd, int ilv)
{
    __shared__ float t[32][33];
    int tx = threadIdx.x & 31, ty = threadIdx.x >> 5;
    int n0 = blockIdx.x * 32, k0 = blockIdx.y * 32;
#pragma unroll
    for (int i = 0; i < 4; i++)
        t[ty + i * 8][tx] = W[(size_t)(k0 + ty + i * 8) * Nd + n0 + tx];
    __syncthreads();
#pragma unroll
    for (int i = 0; i < 4; i++) {
        int n = n0 + ty + i * 8;
        int np = ilv ? ((n < (Nd >> 1)) ? (2 * n) : (2 * (n - (Nd >> 1)) + 1)) : n;
        float v = t[tx][ty + i * 8];
        __nv_bfloat16 h, l; bsplit(v, h, l);
        th[(size_t)np * Kd + k0 + tx] = h;
        tl[(size_t)np * Kd + k0 + tx] = l;
    }
}

// --------------------------- fp32 -> split bf16 ------------------------------
__global__ void __launch_bounds__(256) split_kernel(
    const float* __restrict__ x, __nv_bfloat16* __restrict__ oh,
    __nv_bfloat16* __restrict__ ol)
{
    int i = blockIdx.x * 256 + threadIdx.x;
    __nv_bfloat16 h, l; bsplit(x[i], h, l);
    oh[i] = h; ol[i] = l;
}

// ------------- RoPE + l2norm + scale (+8x for Q) -> split bf16 ---------------
__global__ void __launch_bounds__(256) rope_split_kernel(
    const float* __restrict__ src, int srcStride,
    const float* __restrict__ scale, float mult,
    __nv_bfloat16* __restrict__ dh, __nv_bfloat16* __restrict__ dl)
{
    int row = blockIdx.x, tid = threadIdx.x;
    int hh = tid >> 6, head = blockIdx.y * 4 + hh, d = tid & 63;
    int n = row & 1023, b = row >> 10;
    float v = src[(size_t)row * srcStride + head * DHEAD + d];
    int j = d >> 1, t = j >> 1;
    float p = (j & 1) ? (float)(n >> 5) : (float)(n & 31);
    float ang = p * exp2f(-0.830482024f * (float)t);
    float c = cosf(ang), s = sinf(ang);
    float other = __shfl_xor_sync(0xffffffffu, v, 1);
    float out = (d & 1) ? (other * s + v * c) : (v * c - other * s);
    float ss = out * out;
#pragma unroll
    for (int o = 16; o > 0; o >>= 1) ss += __shfl_xor_sync(0xffffffffu, ss, o);
    __shared__ float s8[8];
    if ((tid & 31) == 0) s8[tid >> 5] = ss;
    __syncthreads();
    float inv = 1.0f / fmaxf(sqrtf(s8[hh * 2] + s8[hh * 2 + 1]), 1e-12f);
    out = out * inv * scale[d] * mult;
    __nv_bfloat16 h, l; bsplit(out, h, l);
    size_t idx = (((size_t)(b * NHEADS + head)) * NSEQ + n) * DHEAD + d;
    dh[idx] = h; dl[idx] = l;
}

// --------- V transpose + split: kv[.,768+c] -> Vt[bh][d][n] hi/lo -------------
__global__ void __launch_bounds__(256) vtrans_split_kernel(
    const float* __restrict__ kv, __nv_bfloat16* __restrict__ vh,
    __nv_bfloat16* __restrict__ vl)
{
    __shared__ float t[32][65];
    int tid = threadIdx.x, bh = blockIdx.y, n0 = blockIdx.x * 32;
    int b = bh / NHEADS, h = bh % NHEADS;
#pragma unroll
    for (int i = 0; i < 8; i++) {
        int nl = (tid >> 6) + i * 4, d = tid & 63;
        t[nl][d] = kv[(size_t)(b * NSEQ + n0 + nl) * (2 * DIMM) + DIMM + h * DHEAD + d];
    }
    __syncthreads();
#pragma unroll
    for (int i = 0; i < 8; i++) {
        int dd = (tid >> 5) + i * 8, nl = tid & 31;
        float v = t[nl][dd];
        __nv_bfloat16 hi, lo; bsplit(v, hi, lo);
        size_t idx = ((size_t)bh * DHEAD + dd) * NSEQ + n0 + nl;
        vh[idx] = hi; vl[idx] = lo;
    }
}

// ================= tensor-core flash attention (split-3 bf16) =================
// K tiles via cp.async group 1, V via group 2: V latency hidden under S phase.
#define AROW 72
__global__ void __launch_bounds__(128) attn_tc_kernel(
    const __nv_bfloat16* __restrict__ Qh, const __nv_bfloat16* __restrict__ Ql,
    const __nv_bfloat16* __restrict__ Kh, const __nv_bfloat16* __restrict__ Kl,
    const __nv_bfloat16* __restrict__ Vh, const __nv_bfloat16* __restrict__ Vl,
    __nv_bfloat16* __restrict__ Oh, __nv_bfloat16* __restrict__ Ol)
{
    __shared__ __align__(16) __nv_bfloat16 sKh[64 * AROW], sKl[64 * AROW];
    __shared__ __align__(16) __nv_bfloat16 sVh[64 * AROW], sVl[64 * AROW];
    __shared__ __align__(16) __nv_bfloat16 sPh[64 * AROW], sPl[64 * AROW];

    int tid = threadIdx.x, lane = tid & 31, w = tid >> 5;
    int bh = blockIdx.y, q0 = blockIdx.x * 64;
    const __nv_bfloat16* qh = Qh + ((size_t)bh * NSEQ + q0) * DHEAD;
    const __nv_bfloat16* ql = Ql + ((size_t)bh * NSEQ + q0) * DHEAD;
    const __nv_bfloat16* kh = Kh + (size_t)bh * NSEQ * DHEAD;
    const __nv_bfloat16* kl = Kl + (size_t)bh * NSEQ * DHEAD;
    const __nv_bfloat16* vh = Vh + (size_t)bh * DHEAD * NSEQ;
    const __nv_bfloat16* vl = Vl + (size_t)bh * DHEAD * NSEQ;
    uint32_t aKh = smem_to_u32(sKh), aKl = smem_to_u32(sKl);
    uint32_t aVh = smem_to_u32(sVh), aVl = smem_to_u32(sVl);
    uint32_t aPh = smem_to_u32(sPh), aPl = smem_to_u32(sPl);

#pragma unroll
    for (int i = 0; i < 4; i++) {
        int id = tid + i * 128, r = id >> 3, c8 = (id & 7) * 8;
        *reinterpret_cast<uint4*>(&sPh[r * AROW + c8]) =
            *reinterpret_cast<const uint4*>(qh + r * 64 + c8);
        *reinterpret_cast<uint4*>(&sPl[r * AROW + c8]) =
            *reinterpret_cast<const uint4*>(ql + r * 64 + c8);
    }
    __syncthreads();
    const int lj = lane >> 3, lr = lane & 7, m0 = w * 16;
    uint32_t qhf[4][4], qlf[4][4];
#pragma unroll
    for (int ks = 0; ks < 4; ks++) {
        uint32_t off = (uint32_t)((m0 + (lj & 1) * 8 + lr) * AROW +
                                  ks * 16 + (lj >> 1) * 8) * 2;
        LDSM4(qhf[ks], aPh + off);
        LDSM4(qlf[ks], aPl + off);
    }

    float m1 = -1e30f, m2 = -1e30f, l1 = 0.f, l2 = 0.f;
    float of[8][4];
#pragma unroll
    for (int nt = 0; nt < 8; nt++)
#pragma unroll
        for (int j = 0; j < 4; j++) of[nt][j] = 0.f;

    for (int kt = 0; kt < 16; kt++) {
        __syncthreads();   // prior iter done reading sK/sV
        // issue K (group 1)
#pragma unroll
        for (int i = 0; i < 4; i++) {
            int c = tid + i * 128, r = c >> 3, u8 = (c & 7) * 8;
            uint32_t d = (uint32_t)(r * AROW + u8) * 2;
            CPASYNC(aKh + d, kh + (size_t)(kt * 64 + r) * 64 + u8);
            CPASYNC(aKl + d, kl + (size_t)(kt * 64 + r) * 64 + u8);
        }
        CPCOMMIT();
        // issue V (group 2)
#pragma unroll
        for (int i = 0; i < 4; i++) {
            int c = tid + i * 128, r = c >> 3, u8 = (c & 7) * 8;
            uint32_t d = (uint32_t)(r * AROW + u8) * 2;
            CPASYNC(aVh + d, vh + (size_t)r * NSEQ + kt * 64 + u8);
            CPASYNC(aVl + d, vl + (size_t)r * NSEQ + kt * 64 + u8);
        }
        CPCOMMIT();
        CPWAIT1();         // K arrived; V still in flight
        __syncthreads();

        // ---- S = Q K^T (split-3, term-major) ----
        float sf[8][4];
#pragma unroll
        for (int nt = 0; nt < 8; nt++)
#pragma unroll
            for (int j = 0; j < 4; j++) sf[nt][j] = 0.f;
#pragma unroll
        for (int ks = 0; ks < 4; ks++) {
            uint32_t khf[4][4], klf[4][4];
#pragma unroll
            for (int bt = 0; bt < 4; bt++) {
                uint32_t off = (uint32_t)((bt * 16 + (lj >> 1) * 8 + lr) * AROW +
                                          ks * 16 + (lj & 1) * 8) * 2;
                LDSM4(khf[bt], aKh + off);
                LDSM4(klf[bt], aKl + off);
            }
#pragma unroll
            for (int bt = 0; bt < 4; bt++)
#pragma unroll
                for (int hf = 0; hf < 2; hf++)
                    MMA_BF16(sf[bt * 2 + hf], qhf[ks], khf[bt][hf * 2], khf[bt][hf * 2 + 1]);
#pragma unroll
            for (int bt = 0; bt < 4; bt++)
#pragma unroll
                for (int hf = 0; hf < 2; hf++)
                    MMA_BF16(sf[bt * 2 + hf], qhf[ks], klf[bt][hf * 2], klf[bt][hf * 2 + 1]);
#pragma unroll
            for (int bt = 0; bt < 4; bt++)
#pragma unroll
                for (int hf = 0; hf < 2; hf++)
                    MMA_BF16(sf[bt * 2 + hf], qlf[ks], khf[bt][hf * 2], khf[bt][hf * 2 + 1]);
        }

        // ---- online softmax in fragments ----
        float mx1 = -1e30f, mx2 = -1e30f;
#pragma unroll
        for (int nt = 0; nt < 8; nt++) {
            mx1 = fmaxf(mx1, fmaxf(sf[nt][0], sf[nt][1]));
            mx2 = fmaxf(mx2, fmaxf(sf[nt][2], sf[nt][3]));
        }
        mx1 = fmaxf(mx1, __shfl_xor_sync(0xffffffffu, mx1, 1));
        mx1 = fmaxf(mx1, __shfl_xor_sync(0xffffffffu, mx1, 2));
        mx2 = fmaxf(mx2, __shfl_xor_sync(0xffffffffu, mx2, 1));
        mx2 = fmaxf(mx2, __shfl_xor_sync(0xffffffffu, mx2, 2));
        float mn1 = fmaxf(m1, mx1), mn2 = fmaxf(m2, mx2);
        float c1 = fexp(m1 - mn1), c2 = fexp(m2 - mn2);
        float rs1 = 0.f, rs2 = 0.f;
#pragma unroll
        for (int nt = 0; nt < 8; nt++) {
            sf[nt][0] = fexp(sf[nt][0] - mn1);
            sf[nt][1] = fexp(sf[nt][1] - mn1);
            sf[nt][2] = fexp(sf[nt][2] - mn2);
            sf[nt][3] = fexp(sf[nt][3] - mn2);
            rs1 += sf[nt][0] + sf[nt][1];
            rs2 += sf[nt][2] + sf[nt][3];
        }
        rs1 += __shfl_xor_sync(0xffffffffu, rs1, 1);
        rs1 += __shfl_xor_sync(0xffffffffu, rs1, 2);
        rs2 += __shfl_xor_sync(0xffffffffu, rs2, 1);
        rs2 += __shfl_xor_sync(0xffffffffu, rs2, 2);
        l1 = l1 * c1 + rs1; l2 = l2 * c2 + rs2;
        m1 = mn1; m2 = mn2;
#pragma unroll
        for (int nt = 0; nt < 8; nt++) {
            of[nt][0] *= c1; of[nt][1] *= c1;
            of[nt][2] *= c2; of[nt][3] *= c2;
        }

        int r1 = m0 + (lane >> 2), r2 = r1 + 8, cc = (lane & 3) * 2;
#pragma unroll
        for (int nt = 0; nt < 8; nt++) {
            int col = nt * 8 + cc;
            __nv_bfloat16 h0, l0, h1, lo1;
            bsplit(sf[nt][0], h0, l0); bsplit(sf[nt][1], h1, lo1);
            *reinterpret_cast<uint32_t*>(&sPh[r1 * AROW + col]) = pack2(h0, h1);
            *reinterpret_cast<uint32_t*>(&sPl[r1 * AROW + col]) = pack2(l0, lo1);
            bsplit(sf[nt][2], h0, l0); bsplit(sf[nt][3], h1, lo1);
            *reinterpret_cast<uint32_t*>(&sPh[r2 * AROW + col]) = pack2(h0, h1);
            *reinterpret_cast<uint32_t*>(&sPl[r2 * AROW + col]) = pack2(l0, lo1);
        }
        __syncwarp();
        CPWAIT0();         // V arrived
        __syncthreads();

        // ---- O += P V (split-3, term-major) ----
#pragma unroll
        for (int ks = 0; ks < 4; ks++) {
            uint32_t phf[4], plf[4], vhf[4][4], vlf[4][4];
            uint32_t offp = (uint32_t)((m0 + (lj & 1) * 8 + lr) * AROW +
                                       ks * 16 + (lj >> 1) * 8) * 2;
            LDSM4(phf, aPh + offp);
            LDSM4(plf, aPl + offp);
#pragma unroll
            for (int bt = 0; bt < 4; bt++) {
                uint32_t offv = (uint32_t)((bt * 16 + (lj >> 1) * 8 + lr) * AROW +
                                           ks * 16 + (lj & 1) * 8) * 2;
                LDSM4(vhf[bt], aVh + offv);
                LDSM4(vlf[bt], aVl + offv);
            }
#pragma unroll
            for (int bt = 0; bt < 4; bt++)
#pragma unroll
                for (int hf = 0; hf < 2; hf++)
                    MMA_BF16(of[bt * 2 + hf], phf, vhf[bt][hf * 2], vhf[bt][hf * 2 + 1]);
#pragma unroll
            for (int bt = 0; bt < 4; bt++)
#pragma unroll
                for (int hf = 0; hf < 2; hf++)
                    MMA_BF16(of[bt * 2 + hf], phf, vlf[bt][hf * 2], vlf[bt][hf * 2 + 1]);
#pragma unroll
            for (int bt = 0; bt < 4; bt++)
#pragma unroll
                for (int hf = 0; hf < 2; hf++)
                    MMA_BF16(of[bt * 2 + hf], plf, vhf[bt][hf * 2], vhf[bt][hf * 2 + 1]);
        }
    }

    int b = bh / NHEADS, hh = bh % NHEADS;
    float inv1 = 1.0f / l1, inv2 = 1.0f / l2;
    int r1 = q0 + m0 + (lane >> 2), cc = (lane & 3) * 2;
    size_t row1 = (size_t)(b * NSEQ + r1) * DIMM + hh * DHEAD;
    size_t row2 = (size_t)(b * NSEQ + r1 + 8) * DIMM + hh * DHEAD;
#pragma unroll
    for (int nt = 0; nt < 8; nt++) {
        int col = nt * 8 + cc;
        __nv_bfloat16 h0, l0, h1, lo1;
        bsplit(of[nt][0] * inv1, h0, l0); bsplit(of[nt][1] * inv1, h1, lo1);
        *reinterpret_cast<uint32_t*>(Oh + row1 + col) = pack2(h0, h1);
        *reinterpret_cast<uint32_t*>(Ol + row1 + col) = pack2(l0, lo1);
        bsplit(of[nt][2] * inv2, h0, l0); bsplit(of[nt][3] * inv2, h1, lo1);
        *reinterpret_cast<uint32_t*>(Oh + row2 + col) = pack2(h0, h1);
        *reinterpret_cast<uint32_t*>(Ol + row2 + col) = pack2(l0, lo1);
    }
}

// ====== HMMA GEMM: C = A@B^T (+res / split out / fused GELU-gate out) ========
// XOR-swizzled smem (64B rows); BM=128: 3 stages, BM=64: 4 stages; 2 CTAs/SM.
// gated=1: columns hold interleaved (a,g) pairs; epilogue writes
// a*gelu(g) as split bf16 into oh/ol with row stride N/2. C skipped if null.
#define SWZ(row, u) ((uint32_t)((row) * 64 + ((((u) ^ (((row) >> 1) & 3))) << 4)))

template<int BM>
__global__ void __launch_bounds__(256, 2) gemm_mma(
    const __nv_bfloat16* __restrict__ Ah, const __nv_bfloat16* __restrict__ Al,
    const __nv_bfloat16* __restrict__ Bh, const __nv_bfloat16* __restrict__ Bl,
    const float* __restrict__ res, float* __restrict__ C,
    __nv_bfloat16* __restrict__ oh, __nv_bfloat16* __restrict__ ol,
    int N, int K, int gated)
{
    constexpr int MI     = BM / 32;
    constexpr int STAGES = (BM == 128 ? 3 : 4);
    constexpr int ASZB   = BM  * 64;
    constexpr int BSZB   = 128 * 64;
    constexpr int STGB   = 2 * ASZB + 2 * BSZB;

    extern __shared__ __align__(16) __nv_bfloat16 sm[];
    const int tid = threadIdx.x, lane = tid & 31, w = tid >> 5;
    const int wr = w & 1, wc = w >> 1;
    const int bm = blockIdx.y * BM, bn = blockIdx.x * 128;
    const int NK = K >> 5;
    const uint32_t sbase = smem_to_u32(sm);

    const __nv_bfloat16* gAh = Ah + (size_t)bm * K;
    const __nv_bfloat16* gAl = Al + (size_t)bm * K;
    const __nv_bfloat16* gBh = Bh + (size_t)bn * K;
    const __nv_bfloat16* gBl = Bl + (size_t)bn * K;

    float acc[MI][4][4];
#pragma unroll
    for (int a = 0; a < MI; a++)
#pragma unroll
        for (int b = 0; b < 4; b++)
#pragma unroll
            for (int c = 0; c < 4; c++) acc[a][b][c] = 0.f;

    auto issue = [&](int st, int kc) {
        uint32_t sb = sbase + st * STGB;
        int ko = kc * 32;
#pragma unroll
        for (int c = tid; c < BM * 4; c += 256) {
            int r = c >> 2, u = c & 3;
            uint32_t d = SWZ(r, u);
            CPASYNC(sb + d,        gAh + (size_t)r * K + ko + u * 8);
            CPASYNC(sb + ASZB + d, gAl + (size_t)r * K + ko + u * 8);
        }
#pragma unroll
        for (int c = tid; c < 512; c += 256) {
            int r = c >> 2, u = c & 3;
            uint32_t d = SWZ(r, u);
            CPASYNC(sb + 2 * ASZB + d,        gBh + (size_t)r * K + ko + u * 8);
            CPASYNC(sb + 2 * ASZB + BSZB + d, gBl + (size_t)r * K + ko + u * 8);
        }
    };

#pragma unroll
    for (int s = 0; s < STAGES - 1; s++) { issue(s, s); CPCOMMIT(); }

    const int lj = lane >> 3, lr = lane & 7;

    for (int kc = 0; kc < NK; kc++) {
        int rem = NK - 1 - kc;
        if (rem >= STAGES - 2) {
            if (STAGES == 4) CPWAIT2(); else CPWAIT1();
        } else if (rem == 1) CPWAIT1();
        else CPWAIT0();
        __syncthreads();
        if (kc + STAGES - 1 < NK) { issue((kc + STAGES - 1) % STAGES, kc + STAGES - 1); CPCOMMIT(); }

        uint32_t sb = sbase + (kc % STAGES) * STGB;
        uint32_t aH = sb, aL = sb + ASZB;
        uint32_t bH = sb + 2 * ASZB, bL = sb + 2 * ASZB + BSZB;

#pragma unroll
        for (int ks = 0; ks < 2; ks++) {
            uint32_t ahf[MI][4], alf[MI][4], bhf[2][4], blf[2][4];
#pragma unroll
            for (int mi = 0; mi < MI; mi++) {
                int mrow = wr * (BM / 2) + mi * 16 + (lj & 1) * 8 + lr;
                int u = ks * 2 + (lj >> 1);
                uint32_t off = SWZ(mrow, u);
                LDSM4(ahf[mi], aH + off);
                LDSM4(alf[mi], aL + off);
            }
#pragma unroll
            for (int bt = 0; bt < 2; bt++) {
                int nrow = wc * 32 + bt * 16 + (lj >> 1) * 8 + lr;
                int u = ks * 2 + (lj & 1);
                uint32_t off = SWZ(nrow, u);
                LDSM4(bhf[bt], bH + off);
                LDSM4(blf[bt], bL + off);
            }
#pragma unroll
            for (int mi = 0; mi < MI; mi++)
#pragma unroll
                for (int bt = 0; bt < 2; bt++)
#pragma unroll
                    for (int hf = 0; hf < 2; hf++)
                        MMA_BF16(acc[mi][bt * 2 + hf], ahf[mi],
                                 bhf[bt][hf * 2], bhf[bt][hf * 2 + 1]);
#pragma unroll
            for (int mi = 0; mi < MI; mi++)
#pragma unroll
                for (int bt = 0; bt < 2; bt++)
#pragma unroll
                    for (int hf = 0; hf < 2; hf++)
                        MMA_BF16(acc[mi][bt * 2 + hf], ahf[mi],
                                 blf[bt][hf * 2], blf[bt][hf * 2 + 1]);
#pragma unroll
            for (int mi = 0; mi < MI; mi++)
#pragma unroll
                for (int bt = 0; bt < 2; bt++)
#pragma unroll
                    for (int hf = 0; hf < 2; hf++)
                        MMA_BF16(acc[mi][bt * 2 + hf], alf[mi],
                                 bhf[bt][hf * 2], bhf[bt][hf * 2 + 1]);
        }
    }

#pragma unroll
    for (int mi = 0; mi < MI; mi++) {
        int row0 = bm + wr * (BM / 2) + mi * 16 + (lane >> 2);
#pragma unroll
        for (int nt = 0; nt < 4; nt++) {
            int col = bn + wc * 32 + nt * 8 + (lane & 3) * 2;
            size_t i0 = (size_t)row0 * N + col;
            size_t i1 = (size_t)(row0 + 8) * N + col;
            float2 v0 = make_float2(acc[mi][nt][0], acc[mi][nt][1]);
            float2 v1 = make_float2(acc[mi][nt][2], acc[mi][nt][3]);
            if (res) {
                float2 a0 = *reinterpret_cast<const float2*>(res + i0);
                float2 a1 = *reinterpret_cast<const float2*>(res + i1);
                v0.x += a0.x; v0.y += a0.y; v1.x += a1.x; v1.y += a1.y;
            }
            if (C) {
                *reinterpret_cast<float2*>(C + i0) = v0;
                *reinterpret_cast<float2*>(C + i1) = v1;
            }
            if (gated) {
                int oc = col >> 1;
                int No = N >> 1;
                float g0 = 0.5f * v0.y * (1.0f + erff(v0.y * 0.7071067811865475f));
                float g1 = 0.5f * v1.y * (1.0f + erff(v1.y * 0.7071067811865475f));
                float r0v = v0.x * g0, r1v = v1.x * g1;
                __nv_bfloat16 h, l;
                bsplit(r0v, h, l);
                oh[(size_t)row0 * No + oc] = h; ol[(size_t)row0 * No + oc] = l;
                bsplit(r1v, h, l);
                oh[(size_t)(row0 + 8) * No + oc] = h; ol[(size_t)(row0 + 8) * No + oc] = l;
            } else if (oh) {
                __nv_bfloat16 h0, l0, h1, l1;
                bsplit(v0.x, h0, l0); bsplit(v0.y, h1, l1);
                *reinterpret_cast<uint32_t*>(oh + i0) = pack2(h0, h1);
                *reinterpret_cast<uint32_t*>(ol + i0) = pack2(l0, l1);
                bsplit(v1.x, h0, l0); bsplit(v1.y, h1, l1);
                *reinterpret_cast<uint32_t*>(oh + i1) = pack2(h0, h1);
                *reinterpret_cast<uint32_t*>(ol + i1) = pack2(l0, l1);
            }
        }
    }
}

#define GSMEM128 (3 * (2 * 128 * 64 + 2 * 128 * 64))
#define GSMEM64  (4 * (2 * 64 * 64 + 2 * 128 * 64))

// ------------------------------ launch ----------------------------------------
extern "C" void kernel_launch(void* const* d_in, const int* in_sizes, int n_in,
                              void* d_out, int out_size)
{
    (void)in_sizes; (void)n_in; (void)out_size;
    const float* x          = (const float*)d_in[0];
    const float* attn_gamma = (const float*)d_in[1];
    const float* wq         = (const float*)d_in[2];
    const float* wkv        = (const float*)d_in[3];
    const float* q_scale    = (const float*)d_in[4];
    const float* k_scale    = (const float*)d_in[5];
    const float* wo         = (const float*)d_in[6];
    const float* ff_gamma   = (const float*)d_in[7];
    const float* ff_beta    = (const float*)d_in[8];
    const float* wff1       = (const float*)d_in[9];
    const float* wff2       = (const float*)d_in[10];
    float* xo = (float*)d_out;

    float *q, *kv, *u;
    __nv_bfloat16 *ah, *al, *xh, *xl, *wth, *wtl, *wth2, *wtl2;
    __nv_bfloat16 *qh, *ql, *kh, *kl, *vh, *vl;
    cudaGetSymbolAddress((void**)&q,    g_q);
    cudaGetSymbolAddress((void**)&kv,   g_kv);
    cudaGetSymbolAddress((void**)&u,    g_u);
    cudaGetSymbolAddress((void**)&ah,   g_ah);
    cudaGetSymbolAddress((void**)&al,   g_al);
    cudaGetSymbolAddress((void**)&xh,   g_xh);
    cudaGetSymbolAddress((void**)&xl,   g_xl);
    cudaGetSymbolAddress((void**)&wth,  g_wth);
    cudaGetSymbolAddress((void**)&wtl,  g_wtl);
    cudaGetSymbolAddress((void**)&wth2, g_wth2);
    cudaGetSymbolAddress((void**)&wtl2, g_wtl2);
    cudaGetSymbolAddress((void**)&qh,   g_qh);
    cudaGetSymbolAddress((void**)&ql,   g_ql);
    cudaGetSymbolAddress((void**)&kh,   g_kh);
    cudaGetSymbolAddress((void**)&kl,   g_kl);
    cudaGetSymbolAddress((void**)&vh,   g_vh);
    cudaGetSymbolAddress((void**)&vl,   g_vl);
    // reuse g_u storage for the fused-gate bf16 outputs [4096 x 2048] hi/lo
    __nv_bfloat16* gh = (__nv_bfloat16*)u;
    __nv_bfloat16* gl = gh + (size_t)MTOK * FFI;

    // stream + events created once, on the uncaptured correctness call
    static cudaStream_t s2 = nullptr;
    static cudaEvent_t evs[20];
    if (!s2) {
        cudaStreamCreate(&s2);
        for (int i = 0; i < 20; i++)
            cudaEventCreateWithFlags(&evs[i], cudaEventDisableTiming);
        cudaFuncSetAttribute(gemm_mma<128>,
            cudaFuncAttributeMaxDynamicSharedMemorySize, GSMEM128);
        cudaFuncSetAttribute(gemm_mma<64>,
            cudaFuncAttributeMaxDynamicSharedMemorySize, GSMEM64);
    }

    cudaMemcpyAsync(xo, x, (size_t)MTOK * DIMM * sizeof(float),
                    cudaMemcpyDeviceToDevice);
    split_kernel<<<(MTOK * DIMM) / 256, 256>>>(xo, xh, xl);

    for (int i = 0; i < 4; i++) {
        cudaEvent_t eA = evs[i * 5 + 0], eQ = evs[i * 5 + 1], eS = evs[i * 5 + 2];
        cudaEvent_t eO = evs[i * 5 + 3], eF = evs[i * 5 + 4];

        // d: LN for attention; fork point
        ln_kernel<<<MTOK, 256>>>(xo, attn_gamma + (size_t)i * DIMM, nullptr, ah, al);
        cudaEventRecord(eA, 0);

        // s2: kv chain (uses xh/xl from prev ff2 epilogue / initial split)
        cudaStreamWaitEvent(s2, eA, 0);
        wtrans_kernel<<<dim3(48, 24), 256, 0, s2>>>(
            wkv + (size_t)i * 768 * 1536, wth2, wtl2, 768, 1536, 0);
        gemm_mma<128><<<dim3(12, 32), 256, GSMEM128, s2>>>(
            xh, xl, wth2, wtl2, nullptr, kv, nullptr, nullptr, 1536, 768, 0);
        rope_split_kernel<<<dim3(MTOK, 3), 256, 0, s2>>>(
            kv, 2 * DIMM, k_scale + (size_t)i * DHEAD, 1.0f, kh, kl);
        vtrans_split_kernel<<<dim3(NSEQ / 32, BHTOT), 256, 0, s2>>>(kv, vh, vl);

        // d: q chain
        wtrans_kernel<<<dim3(24, 24), 256>>>(
            wq + (size_t)i * 768 * 768, wth, wtl, 768, 768, 0);
        gemm_mma<64><<<dim3(6, 64), 256, GSMEM64>>>(
            ah, al, wth, wtl, nullptr, q, nullptr, nullptr, 768, 768, 0);
        cudaEventRecord(eQ, 0);
        rope_split_kernel<<<dim3(MTOK, 3), 256>>>(
            q, DIMM, q_scale + (size_t)i * DHEAD, 8.0f, qh, ql);

        // s2: wo transpose (wth free after q GEMM)
        cudaStreamWaitEvent(s2, eQ, 0);
        wtrans_kernel<<<dim3(24, 24), 256, 0, s2>>>(
            wo + (size_t)i * 768 * 768, wth, wtl, 768, 768, 0);
        cudaEventRecord(eS, s2);

        // d: attention + wo GEMM
        cudaStreamWaitEvent(0, eS, 0);
        attn_tc_kernel<<<dim3(NSEQ / 64, BHTOT), 128>>>(
            qh, ql, kh, kl, vh, vl, ah, al);
        gemm_mma<64><<<dim3(6, 64), 256, GSMEM64>>>(
            ah, al, wth, wtl, xo, xo, nullptr, nullptr, 768, 768, 0);
        cudaEventRecord(eO, 0);

        // s2: ff weight transposes under attention/wo (ff1 interleaved a/g)
        cudaStreamWaitEvent(s2, eO, 0);
        wtrans_kernel<<<dim3(128, 24), 256, 0, s2>>>(
            wff1 + (size_t)i * 768 * 4096, wth, wtl, 768, 4096, 1);
        wtrans_kernel<<<dim3(24, 64), 256, 0, s2>>>(
            wff2 + (size_t)i * 2048 * 768, wth2, wtl2, 2048, 768, 0);
        cudaEventRecord(eF, s2);

        // d: FF block; ff1 epilogue fuses GELU-gate -> gh/gl; ff2 emits xh/xl
        ln_kernel<<<MTOK, 256>>>(xo, ff_gamma + (size_t)i * DIMM,
                                 ff_beta + (size_t)i * DIMM, ah, al);
        cudaStreamWaitEvent(0, eF, 0);
        gemm_mma<128><<<dim3(32, 32), 256, GSMEM128>>>(
            ah, al, wth, wtl, nullptr, nullptr, gh, gl, 4096, 768, 1);
        gemm_mma<64><<<dim3(6, 64), 256, GSMEM64>>>(
            gh, gl, wth2, wtl2, xo, xo, xh, xl, 768, 2048, 0);
    }
}